// round 5
// baseline (speedup 1.0000x reference)
#include <cuda_runtime.h>
#include <cuda_bf16.h>
#include <cstdint>

#define ME   4096   // B*T rows
#define EMB  512
#define TT   2048
#define BB   2
#define HH   8
#define DD   64
#define WSZ  (EMB * EMB)

typedef __nv_bfloat16 bf16;

// ---- scratch (device globals; no cudaMalloc allowed) -----------------------
__device__ float g_q[ME * EMB];
__device__ float g_k[ME * EMB];
__device__ __align__(16) bf16 g_xh[ME * EMB];
__device__ __align__(16) bf16 g_xl[ME * EMB];
__device__ __align__(16) bf16 g_qh[ME * EMB];
__device__ __align__(16) bf16 g_ql[ME * EMB];
__device__ __align__(16) bf16 g_kh[ME * EMB];
__device__ __align__(16) bf16 g_kl[ME * EMB];
__device__ __align__(16) bf16 g_vh[ME * EMB];
__device__ __align__(16) bf16 g_vl[ME * EMB];
__device__ __align__(16) bf16 g_oh[ME * EMB];
__device__ __align__(16) bf16 g_ol[ME * EMB];
__device__ __align__(16) bf16 g_wh[4 * WSZ];
__device__ __align__(16) bf16 g_wl[4 * WSZ];

// ---- helpers ----------------------------------------------------------------
__device__ __forceinline__ unsigned sa(const void* p) {
    return (unsigned)__cvta_generic_to_shared(p);
}
__device__ __forceinline__ void ldsm4(unsigned r[4], unsigned addr) {
    asm volatile("ldmatrix.sync.aligned.m8n8.x4.shared.b16 {%0,%1,%2,%3}, [%4];"
                 : "=r"(r[0]), "=r"(r[1]), "=r"(r[2]), "=r"(r[3]) : "r"(addr));
}
__device__ __forceinline__ void ldsm4t(unsigned r[4], unsigned addr) {
    asm volatile("ldmatrix.sync.aligned.m8n8.x4.trans.shared.b16 {%0,%1,%2,%3}, [%4];"
                 : "=r"(r[0]), "=r"(r[1]), "=r"(r[2]), "=r"(r[3]) : "r"(addr));
}
__device__ __forceinline__ void mma16816(float d[4], const unsigned a[4],
                                         unsigned b0, unsigned b1) {
    asm volatile(
        "mma.sync.aligned.m16n8k16.row.col.f32.bf16.bf16.f32 "
        "{%0,%1,%2,%3}, {%4,%5,%6,%7}, {%8,%9}, {%0,%1,%2,%3};"
        : "+f"(d[0]), "+f"(d[1]), "+f"(d[2]), "+f"(d[3])
        : "r"(a[0]), "r"(a[1]), "r"(a[2]), "r"(a[3]), "r"(b0), "r"(b1));
}
__device__ __forceinline__ unsigned pk2(float lo, float hi) {
    unsigned r;
    asm("cvt.rn.bf16x2.f32 %0, %1, %2;" : "=r"(r) : "f"(hi), "f"(lo));
    return r;
}
__device__ __forceinline__ void unpk2(unsigned u, float& lo, float& hi) {
    __nv_bfloat162 t = *reinterpret_cast<__nv_bfloat162*>(&u);
    lo = __bfloat162float(t.x);
    hi = __bfloat162float(t.y);
}

#define CP_ASYNC16(dst, src) \
    asm volatile("cp.async.cg.shared.global [%0], [%1], 16;" :: "r"(dst), "l"(src))
#define CP_COMMIT() asm volatile("cp.async.commit_group;" ::: "memory")
#define CP_WAIT(n)  asm volatile("cp.async.wait_group %0;" :: "n"(n) : "memory")

// ---- split fp32 -> (hi, lo) bf16 ---------------------------------------------
__device__ __forceinline__ void split4(const float* __restrict__ in,
                                       bf16* __restrict__ h, bf16* __restrict__ l,
                                       int i)
{
    float4 v = *(const float4*)&in[i];
    bf16 h0 = __float2bfloat16_rn(v.x), h1 = __float2bfloat16_rn(v.y);
    bf16 h2 = __float2bfloat16_rn(v.z), h3 = __float2bfloat16_rn(v.w);
    __nv_bfloat162 hh0; hh0.x = h0; hh0.y = h1;
    __nv_bfloat162 hh1; hh1.x = h2; hh1.y = h3;
    *(__nv_bfloat162*)&h[i]     = hh0;
    *(__nv_bfloat162*)&h[i + 2] = hh1;
    __nv_bfloat162 ll0, ll1;
    ll0.x = __float2bfloat16_rn(v.x - __bfloat162float(h0));
    ll0.y = __float2bfloat16_rn(v.y - __bfloat162float(h1));
    ll1.x = __float2bfloat16_rn(v.z - __bfloat162float(h2));
    ll1.y = __float2bfloat16_rn(v.w - __bfloat162float(h3));
    *(__nv_bfloat162*)&l[i]     = ll0;
    *(__nv_bfloat162*)&l[i + 2] = ll1;
}

__global__ void split_x(const float* __restrict__ in, int n)
{
    int i = (blockIdx.x * blockDim.x + threadIdx.x) * 4;
    if (i < n) split4(in, g_xh, g_xl, i);
}

__global__ void split_w(const float* __restrict__ w0, const float* __restrict__ w1,
                        const float* __restrict__ w2, const float* __restrict__ w3)
{
    const int z = blockIdx.y;
    const float* src = (z == 0) ? w0 : (z == 1) ? w1 : (z == 2) ? w2 : w3;
    int i = (blockIdx.x * blockDim.x + threadIdx.x) * 4;
    if (i < WSZ) split4(src, g_wh + z * WSZ, g_wl + z * WSZ, i);
}

// ---- per-head LayerNorm + scale -> bf16 split (q & k in one launch) ----------
__global__ __launch_bounds__(256) void ln_head2(
    const float* __restrict__ gamK, const float* __restrict__ betK,
    const float* __restrict__ gamQ, const float* __restrict__ betQ)
{
    const int which = blockIdx.y;   // 0 = k, 1 = q
    const float* buf = which ? g_q : g_k;
    bf16* oh = which ? g_qh : g_kh;
    bf16* ol = which ? g_ql : g_kl;
    const float* gam = which ? gamQ : gamK;
    const float* bet = which ? betQ : betK;

    const int r    = blockIdx.x * 8 + (threadIdx.x >> 5);
    const int lane = threadIdx.x & 31;
    const int t = r >> 3;
    const int h = r & 7;
    const size_t base = (size_t)t * EMB + h * DD;
    const float* p = buf + base;

    float e0 = p[lane], e1 = p[lane + 32];
    float s  = e0 + e1;
    float ss = e0 * e0 + e1 * e1;
#pragma unroll
    for (int off = 16; off; off >>= 1) {
        s  += __shfl_xor_sync(0xffffffffu, s, off);
        ss += __shfl_xor_sync(0xffffffffu, ss, off);
    }
    const float mean = s * (1.f / 64.f);
    const float var  = ss * (1.f / 64.f) - mean * mean;
    const float rs   = rsqrtf(var + 1e-5f);
    const float SC   = 0.21022410381342865f;  // 512^-0.25
    float v0 = ((e0 - mean) * rs * gam[lane]      + bet[lane])      * SC;
    float v1 = ((e1 - mean) * rs * gam[lane + 32] + bet[lane + 32]) * SC;
    bf16 h0 = __float2bfloat16_rn(v0);
    bf16 h1 = __float2bfloat16_rn(v1);
    oh[base + lane]      = h0;
    oh[base + lane + 32] = h1;
    ol[base + lane]      = __float2bfloat16_rn(v0 - __bfloat162float(h0));
    ol[base + lane + 32] = __float2bfloat16_rn(v1 - __bfloat162float(h1));
}

// ---------------------------------------------------------------------------
// bf16-split GEMM body (HMMA): C[.,N=512] tile 128x64, 256 thr, 8 warps (4x2),
// warp tile 32x32. Per k-tile (64): load {Ah,Al,Wh,Wl} via cp.async 2-stage,
// compute 3 split terms. Dyn smem: 2 stages x 55296 B = 110592 B.
// ---------------------------------------------------------------------------
__device__ __forceinline__ void proj_body(
    const bf16* __restrict__ Ah, const bf16* __restrict__ Al,
    const bf16* __restrict__ Wh, const bf16* __restrict__ Wl,
    const float* __restrict__ bias, float* __restrict__ C,
    bf16* __restrict__ Ch, bf16* __restrict__ Cl)
{
    extern __shared__ __align__(16) char smp[];
    const unsigned smb = sa(smp);

    const int tid  = threadIdx.x;
    const int lane = tid & 31;
    const int w    = tid >> 5;
    const int wr   = w & 3;
    const int wc   = w >> 2;
    const int row0 = blockIdx.x * 128;
    const int col0 = blockIdx.y * 64;

    const int lr  = tid >> 3;        // 0..31
    const int lcb = (tid & 7) * 16;  // byte col of 16B chunk
    const int lce = (tid & 7) * 8;   // element col

    float acc[2][4][4];
#pragma unroll
    for (int m = 0; m < 2; m++)
#pragma unroll
        for (int j = 0; j < 4; j++)
#pragma unroll
            for (int e = 0; e < 4; e++) acc[m][j][e] = 0.f;

    auto load_stage = [&](int s, int kt) {
        const unsigned st = smb + (unsigned)s * 55296u;
#pragma unroll
        for (int i = 0; i < 4; i++) {
            int r = lr + i * 32;
            unsigned dst = st + r * 144 + lcb;
            CP_ASYNC16(dst, Ah + (size_t)(row0 + r) * EMB + kt * 64 + lce);
            CP_ASYNC16(dst + 18432u, Al + (size_t)(row0 + r) * EMB + kt * 64 + lce);
        }
#pragma unroll
        for (int i = 0; i < 2; i++) {
            int r = lr + i * 32;
            unsigned dst = st + 36864u + r * 144 + lcb;
            CP_ASYNC16(dst, Wh + (size_t)(col0 + r) * EMB + kt * 64 + lce);
            CP_ASYNC16(dst + 9216u, Wl + (size_t)(col0 + r) * EMB + kt * 64 + lce);
        }
    };

    const unsigned aoff = (wr * 32 + (lane & 15)) * 144 + (lane >> 4) * 16;
    const unsigned boff = 36864u +
        (wc * 32 + ((lane >> 4) << 3) + (lane & 7)) * 144 + (((lane >> 3) & 1) * 16);

    load_stage(0, 0); CP_COMMIT();
    load_stage(1, 1); CP_COMMIT();

    for (int kt = 0; kt < 8; kt++) {
        const int s = kt & 1;
        if (kt < 7) { CP_WAIT(1); } else { CP_WAIT(0); }
        __syncthreads();
        const unsigned st = smb + (unsigned)s * 55296u;
        const unsigned aAh = st + aoff;
        const unsigned aWh = st + boff;
#pragma unroll
        for (int kc = 0; kc < 4; kc++) {
            unsigned a0h[4], a1h[4], a0l[4], a1l[4];
            ldsm4(a0h, aAh + kc * 32);
            ldsm4(a1h, aAh + kc * 32 + 16 * 144);
            ldsm4(a0l, aAh + 18432u + kc * 32);
            ldsm4(a1l, aAh + 18432u + kc * 32 + 16 * 144);
#pragma unroll
            for (int jp = 0; jp < 2; jp++) {
                unsigned bh[4], bl[4];
                ldsm4(bh, aWh + kc * 32 + jp * 16 * 144);
                ldsm4(bl, aWh + 9216u + kc * 32 + jp * 16 * 144);
                // hh
                mma16816(acc[0][2 * jp],     a0h, bh[0], bh[1]);
                mma16816(acc[0][2 * jp + 1], a0h, bh[2], bh[3]);
                mma16816(acc[1][2 * jp],     a1h, bh[0], bh[1]);
                mma16816(acc[1][2 * jp + 1], a1h, bh[2], bh[3]);
                // hl
                mma16816(acc[0][2 * jp],     a0h, bl[0], bl[1]);
                mma16816(acc[0][2 * jp + 1], a0h, bl[2], bl[3]);
                mma16816(acc[1][2 * jp],     a1h, bl[0], bl[1]);
                mma16816(acc[1][2 * jp + 1], a1h, bl[2], bl[3]);
                // lh
                mma16816(acc[0][2 * jp],     a0l, bh[0], bh[1]);
                mma16816(acc[0][2 * jp + 1], a0l, bh[2], bh[3]);
                mma16816(acc[1][2 * jp],     a1l, bh[0], bh[1]);
                mma16816(acc[1][2 * jp + 1], a1l, bh[2], bh[3]);
            }
        }
        __syncthreads();
        if (kt + 2 < 8) { load_stage(s, kt + 2); CP_COMMIT(); }
    }

    // epilogue
#pragma unroll
    for (int m = 0; m < 2; m++) {
#pragma unroll
        for (int j = 0; j < 4; j++) {
            const int gr = row0 + wr * 32 + m * 16 + (lane >> 2);
            const int gc = col0 + wc * 32 + j * 8 + (lane & 3) * 2;
            float b0 = 0.f, b1 = 0.f;
            if (bias) { b0 = bias[gc]; b1 = bias[gc + 1]; }
            float v00 = acc[m][j][0] + b0, v01 = acc[m][j][1] + b1;
            float v10 = acc[m][j][2] + b0, v11 = acc[m][j][3] + b1;
            if (C) {
                *(float2*)&C[(size_t)gr * EMB + gc]       = make_float2(v00, v01);
                *(float2*)&C[(size_t)(gr + 8) * EMB + gc] = make_float2(v10, v11);
            }
            if (Ch) {
                unsigned h0 = pk2(v00, v01);
                unsigned h1 = pk2(v10, v11);
                *(unsigned*)&Ch[(size_t)gr * EMB + gc]       = h0;
                *(unsigned*)&Ch[(size_t)(gr + 8) * EMB + gc] = h1;
                float a_, b_;
                unpk2(h0, a_, b_);
                *(unsigned*)&Cl[(size_t)gr * EMB + gc] = pk2(v00 - a_, v01 - b_);
                unpk2(h1, a_, b_);
                *(unsigned*)&Cl[(size_t)(gr + 8) * EMB + gc] = pk2(v10 - a_, v11 - b_);
            }
        }
    }
}

__global__ __launch_bounds__(256, 2) void proj_qkv()
{
    const int z = blockIdx.z;
    const bf16* Wh = g_wh + (size_t)z * WSZ;
    const bf16* Wl = g_wl + (size_t)z * WSZ;
    if (z == 0)
        proj_body(g_xh, g_xl, Wh, Wl, nullptr, g_k, nullptr, nullptr);
    else if (z == 1)
        proj_body(g_xh, g_xl, Wh, Wl, nullptr, g_q, nullptr, nullptr);
    else
        proj_body(g_xh, g_xl, Wh, Wl, nullptr, nullptr, g_vh, g_vl);
}

__global__ __launch_bounds__(256, 2) void proj_out(const float* __restrict__ bias,
                                                   float* __restrict__ out)
{
    proj_body(g_oh, g_ol, g_wh + 3 * (size_t)WSZ, g_wl + 3 * (size_t)WSZ,
              bias, out, nullptr, nullptr);
}

// ---- flash attention on mma.sync bf16 (split), occ-4 register diet -----------
__global__ __launch_bounds__(128, 4) void attn_mma(const float* __restrict__ mask)
{
    extern __shared__ char smraw[];
    bf16* Qh_s = (bf16*)smraw;                 // [64][72]
    bf16* Ql_s = Qh_s + 64 * 72;
    bf16* Kh_s = Ql_s + 64 * 72;
    bf16* Kl_s = Kh_s + 64 * 72;
    bf16* Vh_s = Kl_s + 64 * 72;
    bf16* Vl_s = Vh_s + 64 * 72;
    float* mk  = (float*)(Vl_s + 64 * 72);     // [64]

    const int b   = blockIdx.z;
    const int h   = blockIdx.y;
    const int t0  = blockIdx.x * 64;
    const int tid = threadIdx.x;
    const int lane = tid & 31;
    const int w    = tid >> 5;

    const int lr = tid >> 3;          // 0..15
    const int lc = (tid & 7) * 8;

#pragma unroll
    for (int i = 0; i < 4; i++) {
        int r = lr + i * 16;
        size_t gi = (size_t)(b * TT + t0 + r) * EMB + h * DD + lc;
        *(uint4*)&Qh_s[r * 72 + lc] = *(const uint4*)&g_qh[gi];
        *(uint4*)&Ql_s[r * 72 + lc] = *(const uint4*)&g_ql[gi];
    }

    const unsigned qh_a = sa(&Qh_s[(w * 16 + (lane & 15)) * 72 + (lane >> 4) * 8]);
    const unsigned ql_a = sa(&Ql_s[(w * 16 + (lane & 15)) * 72 + (lane >> 4) * 8]);
    const int krow = ((lane >> 4) << 3) + (lane & 7);
    const unsigned kh_a = sa(&Kh_s[krow * 72 + ((lane >> 3) & 1) * 8]);
    const unsigned kl_a = sa(&Kl_s[krow * 72 + ((lane >> 3) & 1) * 8]);
    const int vrow = ((lane >> 3) & 1) * 8 + (lane & 7);
    const int vcol = ((lane >> 4) << 3);
    const unsigned vh_a = sa(&Vh_s[vrow * 72 + vcol]);
    const unsigned vl_a = sa(&Vl_s[vrow * 72 + vcol]);

    float oa[8][4];
#pragma unroll
    for (int j = 0; j < 8; j++)
#pragma unroll
        for (int e = 0; e < 4; e++) oa[j][e] = 0.f;
    float m_i[2] = {-1e30f, -1e30f};
    float l_i[2] = {0.f, 0.f};

    const float mq0 = mask[b * TT + t0 + w * 16 + (lane >> 2)];
    const float mq1 = mask[b * TT + t0 + w * 16 + (lane >> 2) + 8];

    for (int s0 = 0; s0 < TT; s0 += 64) {
        __syncthreads();
#pragma unroll
        for (int i = 0; i < 4; i++) {
            int r = lr + i * 16;
            size_t gi = (size_t)(b * TT + s0 + r) * EMB + h * DD + lc;
            *(uint4*)&Kh_s[r * 72 + lc] = *(const uint4*)&g_kh[gi];
            *(uint4*)&Kl_s[r * 72 + lc] = *(const uint4*)&g_kl[gi];
            *(uint4*)&Vh_s[r * 72 + lc] = *(const uint4*)&g_vh[gi];
            *(uint4*)&Vl_s[r * 72 + lc] = *(const uint4*)&g_vl[gi];
        }
        if (tid < 64) mk[tid] = mask[b * TT + s0 + tid];
        __syncthreads();

        // ---- S = Q K^T (3 split terms) ----
        float sc[8][4];
#pragma unroll
        for (int j = 0; j < 8; j++)
#pragma unroll
            for (int e = 0; e < 4; e++) sc[j][e] = 0.f;

#pragma unroll
        for (int term = 0; term < 3; term++) {
            const unsigned qa = (term < 2) ? qh_a : ql_a;
            const unsigned ka = (term == 1) ? kl_a : kh_a;
#pragma unroll
            for (int kc = 0; kc < 4; kc++) {
                unsigned a[4];
                ldsm4(a, qa + kc * 32);
#pragma unroll
                for (int jp = 0; jp < 4; jp++) {
                    unsigned bb[4];
                    ldsm4(bb, ka + kc * 32 + jp * 16 * 144);
                    mma16816(sc[2 * jp],     a, bb[0], bb[1]);
                    mma16816(sc[2 * jp + 1], a, bb[2], bb[3]);
                }
            }
        }

        // ---- mask + online softmax ----
        float mx0 = -1e30f, mx1 = -1e30f;
#pragma unroll
        for (int j = 0; j < 8; j++) {
            int col = j * 8 + (lane & 3) * 2;
            float mk0 = mk[col], mk1 = mk[col + 1];
            sc[j][0] = (mq0 > 0.f && mk0 > 0.f) ? sc[j][0] : -1e30f;
            sc[j][1] = (mq0 > 0.f && mk1 > 0.f) ? sc[j][1] : -1e30f;
            sc[j][2] = (mq1 > 0.f && mk0 > 0.f) ? sc[j][2] : -1e30f;
            sc[j][3] = (mq1 > 0.f && mk1 > 0.f) ? sc[j][3] : -1e30f;
            mx0 = fmaxf(mx0, fmaxf(sc[j][0], sc[j][1]));
            mx1 = fmaxf(mx1, fmaxf(sc[j][2], sc[j][3]));
        }
        mx0 = fmaxf(mx0, __shfl_xor_sync(0xffffffffu, mx0, 1));
        mx0 = fmaxf(mx0, __shfl_xor_sync(0xffffffffu, mx0, 2));
        mx1 = fmaxf(mx1, __shfl_xor_sync(0xffffffffu, mx1, 1));
        mx1 = fmaxf(mx1, __shfl_xor_sync(0xffffffffu, mx1, 2));

        const float mn0 = fmaxf(m_i[0], mx0);
        const float mn1 = fmaxf(m_i[1], mx1);
        const float c0 = __expf(m_i[0] - mn0);
        const float c1 = __expf(m_i[1] - mn1);
        float rs0 = 0.f, rs1 = 0.f;
#pragma unroll
        for (int j = 0; j < 8; j++) {
            sc[j][0] = __expf(sc[j][0] - mn0);
            sc[j][1] = __expf(sc[j][1] - mn0);
            sc[j][2] = __expf(sc[j][2] - mn1);
            sc[j][3] = __expf(sc[j][3] - mn1);
            rs0 += sc[j][0] + sc[j][1];
            rs1 += sc[j][2] + sc[j][3];
        }
        rs0 += __shfl_xor_sync(0xffffffffu, rs0, 1);
        rs0 += __shfl_xor_sync(0xffffffffu, rs0, 2);
        rs1 += __shfl_xor_sync(0xffffffffu, rs1, 1);
        rs1 += __shfl_xor_sync(0xffffffffu, rs1, 2);
        l_i[0] = l_i[0] * c0 + rs0;
        l_i[1] = l_i[1] * c1 + rs1;
        m_i[0] = mn0; m_i[1] = mn1;
#pragma unroll
        for (int j = 0; j < 8; j++) {
            oa[j][0] *= c0; oa[j][1] *= c0;
            oa[j][2] *= c1; oa[j][3] *= c1;
        }

        // ---- O += P V : hh + hl terms (pack per kc, no persistent ph regs) ----
#pragma unroll
        for (int kc = 0; kc < 4; kc++) {
            unsigned a[4];
            a[0] = pk2(sc[2 * kc][0],     sc[2 * kc][1]);
            a[1] = pk2(sc[2 * kc][2],     sc[2 * kc][3]);
            a[2] = pk2(sc[2 * kc + 1][0], sc[2 * kc + 1][1]);
            a[3] = pk2(sc[2 * kc + 1][2], sc[2 * kc + 1][3]);
#pragma unroll
            for (int jp = 0; jp < 4; jp++) {
                unsigned bb[4];
                ldsm4t(bb, vh_a + kc * 16 * 144 + jp * 32);
                mma16816(oa[2 * jp],     a, bb[0], bb[1]);
                mma16816(oa[2 * jp + 1], a, bb[2], bb[3]);
            }
#pragma unroll
            for (int jp = 0; jp < 4; jp++) {
                unsigned bb[4];
                ldsm4t(bb, vl_a + kc * 16 * 144 + jp * 32);
                mma16816(oa[2 * jp],     a, bb[0], bb[1]);
                mma16816(oa[2 * jp + 1], a, bb[2], bb[3]);
            }
        }
        // ---- residual P-lo term ----
#pragma unroll
        for (int kc = 0; kc < 4; kc++) {
            unsigned a[4];
            float x, y;
            unsigned t;
            t = pk2(sc[2 * kc][0], sc[2 * kc][1]); unpk2(t, x, y);
            a[0] = pk2(sc[2 * kc][0] - x, sc[2 * kc][1] - y);
            t = pk2(sc[2 * kc][2], sc[2 * kc][3]); unpk2(t, x, y);
            a[1] = pk2(sc[2 * kc][2] - x, sc[2 * kc][3] - y);
            t = pk2(sc[2 * kc + 1][0], sc[2 * kc + 1][1]); unpk2(t, x, y);
            a[2] = pk2(sc[2 * kc + 1][0] - x, sc[2 * kc + 1][1] - y);
            t = pk2(sc[2 * kc + 1][2], sc[2 * kc + 1][3]); unpk2(t, x, y);
            a[3] = pk2(sc[2 * kc + 1][2] - x, sc[2 * kc + 1][3] - y);
#pragma unroll
            for (int jp = 0; jp < 4; jp++) {
                unsigned bb[4];
                ldsm4t(bb, vh_a + kc * 16 * 144 + jp * 32);
                mma16816(oa[2 * jp],     a, bb[0], bb[1]);
                mma16816(oa[2 * jp + 1], a, bb[2], bb[3]);
            }
        }
    }

    const float inv0 = 1.f / l_i[0];
    const float inv1 = 1.f / l_i[1];
    const int gr0 = b * TT + t0 + w * 16 + (lane >> 2);
#pragma unroll
    for (int j = 0; j < 8; j++) {
        const int col = h * DD + j * 8 + (lane & 3) * 2;
        float v00 = oa[j][0] * inv0, v01 = oa[j][1] * inv0;
        float v10 = oa[j][2] * inv1, v11 = oa[j][3] * inv1;
        unsigned h0 = pk2(v00, v01);
        unsigned h1 = pk2(v10, v11);
        *(unsigned*)&g_oh[(size_t)gr0 * EMB + col]       = h0;
        *(unsigned*)&g_oh[(size_t)(gr0 + 8) * EMB + col] = h1;
        float x, y;
        unpk2(h0, x, y);
        *(unsigned*)&g_ol[(size_t)gr0 * EMB + col] = pk2(v00 - x, v01 - y);
        unpk2(h1, x, y);
        *(unsigned*)&g_ol[(size_t)(gr0 + 8) * EMB + col] = pk2(v10 - x, v11 - y);
    }
}

// ---------------------------------------------------------------------------
extern "C" void kernel_launch(void* const* d_in, const int* in_sizes, int n_in,
                              void* d_out, int out_size)
{
    const float* x    = (const float*)d_in[0];
    const float* mask = (const float*)d_in[1];
    const float* Wk   = (const float*)d_in[2];
    const float* Wq   = (const float*)d_in[3];
    const float* Wv   = (const float*)d_in[4];
    const float* Wu   = (const float*)d_in[5];
    const float* bu   = (const float*)d_in[6];
    const float* klng = (const float*)d_in[7];
    const float* klnb = (const float*)d_in[8];
    const float* qlng = (const float*)d_in[9];
    const float* qlnb = (const float*)d_in[10];
    float* out = (float*)d_out;

    // splits (2 launches)
    split_x<<<(ME * EMB / 4 + 255) / 256, 256>>>(x, ME * EMB);
    split_w<<<dim3((WSZ / 4 + 255) / 256, 4), 256>>>(Wk, Wq, Wv, Wu);

    // fused QKV projections (cp.async pipelined HMMA)
    const int PSMEM = 2 * 55296;  // 110592
    cudaFuncSetAttribute(proj_qkv,
                         cudaFuncAttributeMaxDynamicSharedMemorySize, PSMEM);
    cudaFuncSetAttribute(proj_out,
                         cudaFuncAttributeMaxDynamicSharedMemorySize, PSMEM);
    proj_qkv<<<dim3(ME / 128, EMB / 64, 3), 256, PSMEM>>>();

    // per-head LN -> bf16 split (q & k fused)
    ln_head2<<<dim3(ME * HH / 8, 2), 256>>>(klng, klnb, qlng, qlnb);

    // attention, occupancy 4 -> single wave
    const int ASMEM = 6 * 64 * 72 * (int)sizeof(bf16) + 64 * (int)sizeof(float);
    cudaFuncSetAttribute(attn_mma,
                         cudaFuncAttributeMaxDynamicSharedMemorySize, ASMEM);
    attn_mma<<<dim3(TT / 64, HH, BB), 128, ASMEM>>>(mask);

    // output projection
    proj_out<<<dim3(ME / 128, EMB / 64, 1), 256, PSMEM>>>(bu, out);
}

// round 6
// speedup vs baseline: 1.0317x; 1.0317x over previous
#include <cuda_runtime.h>
#include <cuda_bf16.h>
#include <cstdint>

#define ME   4096   // B*T rows
#define EMB  512
#define TT   2048
#define BB   2
#define HH   8
#define DD   64
#define WSZ  (EMB * EMB)

typedef __nv_bfloat16 bf16;

// ---- scratch (device globals; no cudaMalloc allowed) -----------------------
__device__ __align__(16) bf16 g_xh[ME * EMB];
__device__ __align__(16) bf16 g_xl[ME * EMB];
__device__ __align__(16) bf16 g_qh[ME * EMB];
__device__ __align__(16) bf16 g_ql[ME * EMB];
__device__ __align__(16) bf16 g_kh[ME * EMB];
__device__ __align__(16) bf16 g_kl[ME * EMB];
__device__ __align__(16) bf16 g_vh[ME * EMB];
__device__ __align__(16) bf16 g_vl[ME * EMB];
__device__ __align__(16) bf16 g_oh[ME * EMB];
__device__ __align__(16) bf16 g_ol[ME * EMB];
__device__ __align__(16) bf16 g_wh[4 * WSZ];
__device__ __align__(16) bf16 g_wl[4 * WSZ];

// ---- helpers ----------------------------------------------------------------
__device__ __forceinline__ unsigned sa(const void* p) {
    return (unsigned)__cvta_generic_to_shared(p);
}
__device__ __forceinline__ void ldsm4(unsigned r[4], unsigned addr) {
    asm volatile("ldmatrix.sync.aligned.m8n8.x4.shared.b16 {%0,%1,%2,%3}, [%4];"
                 : "=r"(r[0]), "=r"(r[1]), "=r"(r[2]), "=r"(r[3]) : "r"(addr));
}
__device__ __forceinline__ void ldsm4t(unsigned r[4], unsigned addr) {
    asm volatile("ldmatrix.sync.aligned.m8n8.x4.trans.shared.b16 {%0,%1,%2,%3}, [%4];"
                 : "=r"(r[0]), "=r"(r[1]), "=r"(r[2]), "=r"(r[3]) : "r"(addr));
}
__device__ __forceinline__ void mma16816(float d[4], const unsigned a[4],
                                         unsigned b0, unsigned b1) {
    asm volatile(
        "mma.sync.aligned.m16n8k16.row.col.f32.bf16.bf16.f32 "
        "{%0,%1,%2,%3}, {%4,%5,%6,%7}, {%8,%9}, {%0,%1,%2,%3};"
        : "+f"(d[0]), "+f"(d[1]), "+f"(d[2]), "+f"(d[3])
        : "r"(a[0]), "r"(a[1]), "r"(a[2]), "r"(a[3]), "r"(b0), "r"(b1));
}
__device__ __forceinline__ unsigned pk2(float lo, float hi) {
    unsigned r;
    asm("cvt.rn.bf16x2.f32 %0, %1, %2;" : "=r"(r) : "f"(hi), "f"(lo));
    return r;
}
__device__ __forceinline__ void unpk2(unsigned u, float& lo, float& hi) {
    __nv_bfloat162 t = *reinterpret_cast<__nv_bfloat162*>(&u);
    lo = __bfloat162float(t.x);
    hi = __bfloat162float(t.y);
}

#define CP_ASYNC16(dst, src) \
    asm volatile("cp.async.cg.shared.global [%0], [%1], 16;" :: "r"(dst), "l"(src))
#define CP_COMMIT() asm volatile("cp.async.commit_group;" ::: "memory")
#define CP_WAIT(n)  asm volatile("cp.async.wait_group %0;" :: "n"(n) : "memory")

// ---- split fp32 -> (hi, lo) bf16 ---------------------------------------------
__device__ __forceinline__ void split4(const float* __restrict__ in,
                                       bf16* __restrict__ h, bf16* __restrict__ l,
                                       int i)
{
    float4 v = *(const float4*)&in[i];
    bf16 h0 = __float2bfloat16_rn(v.x), h1 = __float2bfloat16_rn(v.y);
    bf16 h2 = __float2bfloat16_rn(v.z), h3 = __float2bfloat16_rn(v.w);
    __nv_bfloat162 hh0; hh0.x = h0; hh0.y = h1;
    __nv_bfloat162 hh1; hh1.x = h2; hh1.y = h3;
    *(__nv_bfloat162*)&h[i]     = hh0;
    *(__nv_bfloat162*)&h[i + 2] = hh1;
    __nv_bfloat162 ll0, ll1;
    ll0.x = __float2bfloat16_rn(v.x - __bfloat162float(h0));
    ll0.y = __float2bfloat16_rn(v.y - __bfloat162float(h1));
    ll1.x = __float2bfloat16_rn(v.z - __bfloat162float(h2));
    ll1.y = __float2bfloat16_rn(v.w - __bfloat162float(h3));
    *(__nv_bfloat162*)&l[i]     = ll0;
    *(__nv_bfloat162*)&l[i + 2] = ll1;
}

__global__ void split_x(const float* __restrict__ in, int n)
{
    int i = (blockIdx.x * blockDim.x + threadIdx.x) * 4;
    if (i < n) split4(in, g_xh, g_xl, i);
}

__global__ void split_w(const float* __restrict__ w0, const float* __restrict__ w1,
                        const float* __restrict__ w2, const float* __restrict__ w3)
{
    const int z = blockIdx.y;
    const float* src = (z == 0) ? w0 : (z == 1) ? w1 : (z == 2) ? w2 : w3;
    int i = (blockIdx.x * blockDim.x + threadIdx.x) * 4;
    if (i < WSZ) split4(src, g_wh + z * WSZ, g_wl + z * WSZ, i);
}

// ---------------------------------------------------------------------------
// bf16-split GEMM body (HMMA): tile 128x64, 256 thr, 8 warps (4 Mrow x 2 Ncol),
// cp.async 2-stage pipeline. Epilogue modes:
//   C   != 0 : fp32 out (+bias)
//   Ch  != 0, gam == 0 : plain bf16 hi/lo split out
//   Ch  != 0, gam != 0 : per-(token,head) LayerNorm (tile == one head) + *SC,
//                        then bf16 hi/lo split out
// ---------------------------------------------------------------------------
__device__ __forceinline__ void proj_body(
    const bf16* __restrict__ Ah, const bf16* __restrict__ Al,
    const bf16* __restrict__ Wh, const bf16* __restrict__ Wl,
    const float* __restrict__ bias, float* __restrict__ C,
    bf16* __restrict__ Ch, bf16* __restrict__ Cl,
    const float* __restrict__ gam, const float* __restrict__ bet)
{
    extern __shared__ __align__(16) char smp[];
    const unsigned smb = sa(smp);

    const int tid  = threadIdx.x;
    const int lane = tid & 31;
    const int w    = tid >> 5;
    const int wr   = w & 3;
    const int wc   = w >> 2;
    const int row0 = blockIdx.x * 128;
    const int col0 = blockIdx.y * 64;

    const int lr  = tid >> 3;        // 0..31
    const int lcb = (tid & 7) * 16;  // byte col of 16B chunk
    const int lce = (tid & 7) * 8;   // element col

    float acc[2][4][4];
#pragma unroll
    for (int m = 0; m < 2; m++)
#pragma unroll
        for (int j = 0; j < 4; j++)
#pragma unroll
            for (int e = 0; e < 4; e++) acc[m][j][e] = 0.f;

    auto load_stage = [&](int s, int kt) {
        const unsigned st = smb + (unsigned)s * 55296u;
#pragma unroll
        for (int i = 0; i < 4; i++) {
            int r = lr + i * 32;
            unsigned dst = st + r * 144 + lcb;
            CP_ASYNC16(dst, Ah + (size_t)(row0 + r) * EMB + kt * 64 + lce);
            CP_ASYNC16(dst + 18432u, Al + (size_t)(row0 + r) * EMB + kt * 64 + lce);
        }
#pragma unroll
        for (int i = 0; i < 2; i++) {
            int r = lr + i * 32;
            unsigned dst = st + 36864u + r * 144 + lcb;
            CP_ASYNC16(dst, Wh + (size_t)(col0 + r) * EMB + kt * 64 + lce);
            CP_ASYNC16(dst + 9216u, Wl + (size_t)(col0 + r) * EMB + kt * 64 + lce);
        }
    };

    const unsigned aoff = (wr * 32 + (lane & 15)) * 144 + (lane >> 4) * 16;
    const unsigned boff = 36864u +
        (wc * 32 + ((lane >> 4) << 3) + (lane & 7)) * 144 + (((lane >> 3) & 1) * 16);

    load_stage(0, 0); CP_COMMIT();
    load_stage(1, 1); CP_COMMIT();

    for (int kt = 0; kt < 8; kt++) {
        const int s = kt & 1;
        if (kt < 7) { CP_WAIT(1); } else { CP_WAIT(0); }
        __syncthreads();
        const unsigned st = smb + (unsigned)s * 55296u;
        const unsigned aAh = st + aoff;
        const unsigned aWh = st + boff;
#pragma unroll
        for (int kc = 0; kc < 4; kc++) {
            unsigned a0h[4], a1h[4], a0l[4], a1l[4];
            ldsm4(a0h, aAh + kc * 32);
            ldsm4(a1h, aAh + kc * 32 + 16 * 144);
            ldsm4(a0l, aAh + 18432u + kc * 32);
            ldsm4(a1l, aAh + 18432u + kc * 32 + 16 * 144);
#pragma unroll
            for (int jp = 0; jp < 2; jp++) {
                unsigned bh[4], bl[4];
                ldsm4(bh, aWh + kc * 32 + jp * 16 * 144);
                ldsm4(bl, aWh + 9216u + kc * 32 + jp * 16 * 144);
                mma16816(acc[0][2 * jp],     a0h, bh[0], bh[1]);
                mma16816(acc[0][2 * jp + 1], a0h, bh[2], bh[3]);
                mma16816(acc[1][2 * jp],     a1h, bh[0], bh[1]);
                mma16816(acc[1][2 * jp + 1], a1h, bh[2], bh[3]);
                mma16816(acc[0][2 * jp],     a0h, bl[0], bl[1]);
                mma16816(acc[0][2 * jp + 1], a0h, bl[2], bl[3]);
                mma16816(acc[1][2 * jp],     a1h, bl[0], bl[1]);
                mma16816(acc[1][2 * jp + 1], a1h, bl[2], bl[3]);
                mma16816(acc[0][2 * jp],     a0l, bh[0], bh[1]);
                mma16816(acc[0][2 * jp + 1], a0l, bh[2], bh[3]);
                mma16816(acc[1][2 * jp],     a1l, bh[0], bh[1]);
                mma16816(acc[1][2 * jp + 1], a1l, bh[2], bh[3]);
            }
        }
        __syncthreads();
        if (kt + 2 < 8) { load_stage(s, kt + 2); CP_COMMIT(); }
    }

    if (gam) {
        // ---- per-row (token,head) LayerNorm over the 64-col tile + *SC ------
        float* redS = (float*)smp;          // [2][128]
        float* redQ = redS + 256;           // [2][128]
        float sum[2][2], ssq[2][2];
#pragma unroll
        for (int m = 0; m < 2; m++)
#pragma unroll
            for (int i = 0; i < 2; i++) {
                float s_ = 0.f, q_ = 0.f;
#pragma unroll
                for (int j = 0; j < 4; j++) {
                    float a0 = acc[m][j][2 * i], a1 = acc[m][j][2 * i + 1];
                    s_ += a0 + a1;
                    q_ += a0 * a0 + a1 * a1;
                }
                sum[m][i] = s_; ssq[m][i] = q_;
            }
#pragma unroll
        for (int off = 1; off <= 2; off <<= 1)
#pragma unroll
            for (int m = 0; m < 2; m++)
#pragma unroll
                for (int i = 0; i < 2; i++) {
                    sum[m][i] += __shfl_xor_sync(0xffffffffu, sum[m][i], off);
                    ssq[m][i] += __shfl_xor_sync(0xffffffffu, ssq[m][i], off);
                }
        if ((lane & 3) == 0) {
#pragma unroll
            for (int m = 0; m < 2; m++)
#pragma unroll
                for (int i = 0; i < 2; i++) {
                    int row = wr * 32 + m * 16 + i * 8 + (lane >> 2);
                    redS[wc * 128 + row] = sum[m][i];
                    redQ[wc * 128 + row] = ssq[m][i];
                }
        }
        __syncthreads();
        const float SC = 0.21022410381342865f;  // 512^-0.25
#pragma unroll
        for (int m = 0; m < 2; m++)
#pragma unroll
            for (int i = 0; i < 2; i++) {
                const int row = wr * 32 + m * 16 + i * 8 + (lane >> 2);
                const float s_ = redS[row] + redS[128 + row];
                const float q_ = redQ[row] + redQ[128 + row];
                const float mean = s_ * (1.f / 64.f);
                const float var  = q_ * (1.f / 64.f) - mean * mean;
                const float rs   = rsqrtf(var + 1e-5f);
                const int gr = row0 + row;
#pragma unroll
                for (int j = 0; j < 4; j++) {
                    const int cl = wc * 32 + j * 8 + (lane & 3) * 2;
                    float v0 = ((acc[m][j][2 * i]     - mean) * rs * gam[cl]     + bet[cl])     * SC;
                    float v1 = ((acc[m][j][2 * i + 1] - mean) * rs * gam[cl + 1] + bet[cl + 1]) * SC;
                    unsigned hp = pk2(v0, v1);
                    *(unsigned*)&Ch[(size_t)gr * EMB + col0 + cl] = hp;
                    float x, y;
                    unpk2(hp, x, y);
                    *(unsigned*)&Cl[(size_t)gr * EMB + col0 + cl] = pk2(v0 - x, v1 - y);
                }
            }
        return;
    }

    // ---- plain epilogue ------------------------------------------------------
#pragma unroll
    for (int m = 0; m < 2; m++) {
#pragma unroll
        for (int j = 0; j < 4; j++) {
            const int gr = row0 + wr * 32 + m * 16 + (lane >> 2);
            const int gc = col0 + wc * 32 + j * 8 + (lane & 3) * 2;
            float b0 = 0.f, b1 = 0.f;
            if (bias) { b0 = bias[gc]; b1 = bias[gc + 1]; }
            float v00 = acc[m][j][0] + b0, v01 = acc[m][j][1] + b1;
            float v10 = acc[m][j][2] + b0, v11 = acc[m][j][3] + b1;
            if (C) {
                *(float2*)&C[(size_t)gr * EMB + gc]       = make_float2(v00, v01);
                *(float2*)&C[(size_t)(gr + 8) * EMB + gc] = make_float2(v10, v11);
            }
            if (Ch) {
                unsigned h0 = pk2(v00, v01);
                unsigned h1 = pk2(v10, v11);
                *(unsigned*)&Ch[(size_t)gr * EMB + gc]       = h0;
                *(unsigned*)&Ch[(size_t)(gr + 8) * EMB + gc] = h1;
                float a_, b_;
                unpk2(h0, a_, b_);
                *(unsigned*)&Cl[(size_t)gr * EMB + gc] = pk2(v00 - a_, v01 - b_);
                unpk2(h1, a_, b_);
                *(unsigned*)&Cl[(size_t)(gr + 8) * EMB + gc] = pk2(v10 - a_, v11 - b_);
            }
        }
    }
}

__global__ __launch_bounds__(256, 2) void proj_qkv(
    const float* __restrict__ klng, const float* __restrict__ klnb,
    const float* __restrict__ qlng, const float* __restrict__ qlnb)
{
    const int z = blockIdx.z;
    const bf16* Wh = g_wh + (size_t)z * WSZ;
    const bf16* Wl = g_wl + (size_t)z * WSZ;
    if (z == 0)
        proj_body(g_xh, g_xl, Wh, Wl, nullptr, nullptr, g_kh, g_kl, klng, klnb);
    else if (z == 1)
        proj_body(g_xh, g_xl, Wh, Wl, nullptr, nullptr, g_qh, g_ql, qlng, qlnb);
    else
        proj_body(g_xh, g_xl, Wh, Wl, nullptr, nullptr, g_vh, g_vl, nullptr, nullptr);
}

__global__ __launch_bounds__(256, 2) void proj_out(const float* __restrict__ bias,
                                                   float* __restrict__ out)
{
    proj_body(g_oh, g_ol, g_wh + 3 * (size_t)WSZ, g_wl + 3 * (size_t)WSZ,
              bias, out, nullptr, nullptr, nullptr, nullptr);
}

// ---------------------------------------------------------------------------
// Flash attention, 128-query tiles, 256 thr (8 warps x 16 rows),
// cp.async double-buffered K/V (hi/lo). smem = Q 36864 + KV 2x36864 = 110592 B.
// ---------------------------------------------------------------------------
__global__ __launch_bounds__(256, 2) void attn_mma(const float* __restrict__ mask)
{
    extern __shared__ __align__(16) char smraw[];
    bf16* Qh_s = (bf16*)smraw;                  // [128][72]
    bf16* Ql_s = Qh_s + 128 * 72;
    bf16* KVs  = Ql_s + 128 * 72;               // [2 stages][4 arrays][64*72]

    const int b   = blockIdx.z;
    const int h   = blockIdx.y;
    const int t0  = blockIdx.x * 128;
    const int tid = threadIdx.x;
    const int lane = tid & 31;
    const int w    = tid >> 5;

    // ---- Q load (with stage 0 in cp.async group 1) ----
#pragma unroll
    for (int i = 0; i < 4; i++) {
        int idx = tid + i * 256;           // 0..1023
        int r = idx >> 3, c = idx & 7;
        size_t gi = (size_t)(b * TT + t0 + r) * EMB + h * DD + c * 8;
        unsigned d = sa(Qh_s) + r * 144 + c * 16;
        CP_ASYNC16(d, g_qh + gi);
        CP_ASYNC16(d + 18432u, g_ql + gi);  // Ql_s right after Qh_s
    }

    auto load_kv = [&](int s, int kt) {
        const unsigned base = sa(KVs) + (unsigned)s * 36864u;
        const int s0 = kt * 64;
#pragma unroll
        for (int i = 0; i < 2; i++) {
            int idx = tid + i * 256;       // 0..511
            int r = idx >> 3, c = idx & 7;
            size_t gi = (size_t)(b * TT + s0 + r) * EMB + h * DD + c * 8;
            unsigned d = base + r * 144 + c * 16;
            CP_ASYNC16(d,          g_kh + gi);
            CP_ASYNC16(d + 9216u,  g_kl + gi);
            CP_ASYNC16(d + 18432u, g_vh + gi);
            CP_ASYNC16(d + 27648u, g_vl + gi);
        }
    };

    load_kv(0, 0); CP_COMMIT();
    load_kv(1, 1); CP_COMMIT();

    const unsigned qh_a = sa(Qh_s) + (w * 16 + (lane & 15)) * 144 + (lane >> 4) * 16;
    const unsigned ql_a = qh_a + 18432u;
    const unsigned koff = (((lane >> 4) << 3) + (lane & 7)) * 144 + ((lane >> 3) & 1) * 16;
    const unsigned voff = ((((lane >> 3) & 1) * 8 + (lane & 7)) * 72 + ((lane >> 4) << 3)) * 2;

    float oa[8][4];
#pragma unroll
    for (int j = 0; j < 8; j++)
#pragma unroll
        for (int e = 0; e < 4; e++) oa[j][e] = 0.f;
    float m_i[2] = {-1e30f, -1e30f};
    float l_i[2] = {0.f, 0.f};

    const float mq0 = mask[b * TT + t0 + w * 16 + (lane >> 2)];
    const float mq1 = mask[b * TT + t0 + w * 16 + (lane >> 2) + 8];

    for (int kt = 0; kt < TT / 64; kt++) {
        const int s = kt & 1;
        if (kt < TT / 64 - 1) { CP_WAIT(1); } else { CP_WAIT(0); }
        __syncthreads();

        const unsigned stb  = sa(KVs) + (unsigned)s * 36864u;
        const unsigned kh_a = stb + koff;
        const unsigned kl_a = kh_a + 9216u;
        const unsigned vh_a = stb + 18432u + voff;
        const unsigned vl_a = vh_a + 9216u;

        // ---- S = Q K^T (3 split terms) ----
        float sc[8][4];
#pragma unroll
        for (int j = 0; j < 8; j++)
#pragma unroll
            for (int e = 0; e < 4; e++) sc[j][e] = 0.f;

#pragma unroll
        for (int term = 0; term < 3; term++) {
            const unsigned qa = (term < 2) ? qh_a : ql_a;
            const unsigned ka = (term == 1) ? kl_a : kh_a;
#pragma unroll
            for (int kc = 0; kc < 4; kc++) {
                unsigned a[4];
                ldsm4(a, qa + kc * 32);
#pragma unroll
                for (int jp = 0; jp < 4; jp++) {
                    unsigned bb[4];
                    ldsm4(bb, ka + kc * 32 + jp * 16 * 144);
                    mma16816(sc[2 * jp],     a, bb[0], bb[1]);
                    mma16816(sc[2 * jp + 1], a, bb[2], bb[3]);
                }
            }
        }

        // ---- mask + online softmax (mask read via L1) ----
        const int s0 = kt * 64;
        float mx0 = -1e30f, mx1 = -1e30f;
#pragma unroll
        for (int j = 0; j < 8; j++) {
            float2 mv = __ldg((const float2*)&mask[b * TT + s0 + j * 8 + (lane & 3) * 2]);
            sc[j][0] = (mq0 > 0.f && mv.x > 0.f) ? sc[j][0] : -1e30f;
            sc[j][1] = (mq0 > 0.f && mv.y > 0.f) ? sc[j][1] : -1e30f;
            sc[j][2] = (mq1 > 0.f && mv.x > 0.f) ? sc[j][2] : -1e30f;
            sc[j][3] = (mq1 > 0.f && mv.y > 0.f) ? sc[j][3] : -1e30f;
            mx0 = fmaxf(mx0, fmaxf(sc[j][0], sc[j][1]));
            mx1 = fmaxf(mx1, fmaxf(sc[j][2], sc[j][3]));
        }
        mx0 = fmaxf(mx0, __shfl_xor_sync(0xffffffffu, mx0, 1));
        mx0 = fmaxf(mx0, __shfl_xor_sync(0xffffffffu, mx0, 2));
        mx1 = fmaxf(mx1, __shfl_xor_sync(0xffffffffu, mx1, 1));
        mx1 = fmaxf(mx1, __shfl_xor_sync(0xffffffffu, mx1, 2));

        const float mn0 = fmaxf(m_i[0], mx0);
        const float mn1 = fmaxf(m_i[1], mx1);
        const float c0 = __expf(m_i[0] - mn0);
        const float c1 = __expf(m_i[1] - mn1);
        float rs0 = 0.f, rs1 = 0.f;
#pragma unroll
        for (int j = 0; j < 8; j++) {
            sc[j][0] = __expf(sc[j][0] - mn0);
            sc[j][1] = __expf(sc[j][1] - mn0);
            sc[j][2] = __expf(sc[j][2] - mn1);
            sc[j][3] = __expf(sc[j][3] - mn1);
            rs0 += sc[j][0] + sc[j][1];
            rs1 += sc[j][2] + sc[j][3];
        }
        rs0 += __shfl_xor_sync(0xffffffffu, rs0, 1);
        rs0 += __shfl_xor_sync(0xffffffffu, rs0, 2);
        rs1 += __shfl_xor_sync(0xffffffffu, rs1, 1);
        rs1 += __shfl_xor_sync(0xffffffffu, rs1, 2);
        l_i[0] = l_i[0] * c0 + rs0;
        l_i[1] = l_i[1] * c1 + rs1;
        m_i[0] = mn0; m_i[1] = mn1;
#pragma unroll
        for (int j = 0; j < 8; j++) {
            oa[j][0] *= c0; oa[j][1] *= c0;
            oa[j][2] *= c1; oa[j][3] *= c1;
        }

        // ---- O += P V : P_hi*(V_hi+V_lo) ----
#pragma unroll
        for (int kc = 0; kc < 4; kc++) {
            unsigned a[4];
            a[0] = pk2(sc[2 * kc][0],     sc[2 * kc][1]);
            a[1] = pk2(sc[2 * kc][2],     sc[2 * kc][3]);
            a[2] = pk2(sc[2 * kc + 1][0], sc[2 * kc + 1][1]);
            a[3] = pk2(sc[2 * kc + 1][2], sc[2 * kc + 1][3]);
#pragma unroll
            for (int jp = 0; jp < 4; jp++) {
                unsigned bb[4];
                ldsm4t(bb, vh_a + kc * 16 * 144 + jp * 32);
                mma16816(oa[2 * jp],     a, bb[0], bb[1]);
                mma16816(oa[2 * jp + 1], a, bb[2], bb[3]);
            }
#pragma unroll
            for (int jp = 0; jp < 4; jp++) {
                unsigned bb[4];
                ldsm4t(bb, vl_a + kc * 16 * 144 + jp * 32);
                mma16816(oa[2 * jp],     a, bb[0], bb[1]);
                mma16816(oa[2 * jp + 1], a, bb[2], bb[3]);
            }
        }
        // ---- residual P_lo * V_hi ----
#pragma unroll
        for (int kc = 0; kc < 4; kc++) {
            unsigned a[4];
            float x, y;
            unsigned t;
            t = pk2(sc[2 * kc][0], sc[2 * kc][1]); unpk2(t, x, y);
            a[0] = pk2(sc[2 * kc][0] - x, sc[2 * kc][1] - y);
            t = pk2(sc[2 * kc][2], sc[2 * kc][3]); unpk2(t, x, y);
            a[1] = pk2(sc[2 * kc][2] - x, sc[2 * kc][3] - y);
            t = pk2(sc[2 * kc + 1][0], sc[2 * kc + 1][1]); unpk2(t, x, y);
            a[2] = pk2(sc[2 * kc + 1][0] - x, sc[2 * kc + 1][1] - y);
            t = pk2(sc[2 * kc + 1][2], sc[2 * kc + 1][3]); unpk2(t, x, y);
            a[3] = pk2(sc[2 * kc + 1][2] - x, sc[2 * kc + 1][3] - y);
#pragma unroll
            for (int jp = 0; jp < 4; jp++) {
                unsigned bb[4];
                ldsm4t(bb, vh_a + kc * 16 * 144 + jp * 32);
                mma16816(oa[2 * jp],     a, bb[0], bb[1]);
                mma16816(oa[2 * jp + 1], a, bb[2], bb[3]);
            }
        }

        __syncthreads();
        if (kt + 2 < TT / 64) { load_kv(s, kt + 2); CP_COMMIT(); }
    }

    // ---- epilogue: O / l -> bf16 split ----
    const float inv0 = 1.f / l_i[0];
    const float inv1 = 1.f / l_i[1];
    const int gr0 = b * TT + t0 + w * 16 + (lane >> 2);
#pragma unroll
    for (int j = 0; j < 8; j++) {
        const int col = h * DD + j * 8 + (lane & 3) * 2;
        float v00 = oa[j][0] * inv0, v01 = oa[j][1] * inv0;
        float v10 = oa[j][2] * inv1, v11 = oa[j][3] * inv1;
        unsigned h0 = pk2(v00, v01);
        unsigned h1 = pk2(v10, v11);
        *(unsigned*)&g_oh[(size_t)gr0 * EMB + col]       = h0;
        *(unsigned*)&g_oh[(size_t)(gr0 + 8) * EMB + col] = h1;
        float x, y;
        unpk2(h0, x, y);
        *(unsigned*)&g_ol[(size_t)gr0 * EMB + col] = pk2(v00 - x, v01 - y);
        unpk2(h1, x, y);
        *(unsigned*)&g_ol[(size_t)(gr0 + 8) * EMB + col] = pk2(v10 - x, v11 - y);
    }
}

// ---------------------------------------------------------------------------
extern "C" void kernel_launch(void* const* d_in, const int* in_sizes, int n_in,
                              void* d_out, int out_size)
{
    const float* x    = (const float*)d_in[0];
    const float* mask = (const float*)d_in[1];
    const float* Wk   = (const float*)d_in[2];
    const float* Wq   = (const float*)d_in[3];
    const float* Wv   = (const float*)d_in[4];
    const float* Wu   = (const float*)d_in[5];
    const float* bu   = (const float*)d_in[6];
    const float* klng = (const float*)d_in[7];
    const float* klnb = (const float*)d_in[8];
    const float* qlng = (const float*)d_in[9];
    const float* qlnb = (const float*)d_in[10];
    float* out = (float*)d_out;

    split_x<<<(ME * EMB / 4 + 255) / 256, 256>>>(x, ME * EMB);
    split_w<<<dim3((WSZ / 4 + 255) / 256, 4), 256>>>(Wk, Wq, Wv, Wu);

    const int PSMEM = 2 * 55296;  // 110592
    cudaFuncSetAttribute(proj_qkv,
                         cudaFuncAttributeMaxDynamicSharedMemorySize, PSMEM);
    cudaFuncSetAttribute(proj_out,
                         cudaFuncAttributeMaxDynamicSharedMemorySize, PSMEM);
    proj_qkv<<<dim3(ME / 128, EMB / 64, 3), 256, PSMEM>>>(klng, klnb, qlng, qlnb);

    const int ASMEM = (2 * 128 * 72 + 2 * 4 * 64 * 72) * (int)sizeof(bf16);  // 110592
    cudaFuncSetAttribute(attn_mma,
                         cudaFuncAttributeMaxDynamicSharedMemorySize, ASMEM);
    attn_mma<<<dim3(TT / 128, HH, BB), 256, ASMEM>>>(mask);

    proj_out<<<dim3(ME / 128, EMB / 64, 1), 256, PSMEM>>>(bu, out);
}

// round 7
// speedup vs baseline: 1.4718x; 1.4266x over previous
#include <cuda_runtime.h>
#include <cuda_bf16.h>
#include <cstdint>

#define ME   4096   // B*T rows
#define EMB  512
#define TT   2048
#define BB   2
#define HH   8
#define DD   64
#define WSZ  (EMB * EMB)

typedef __nv_bfloat16 bf16;

// ---- scratch (device globals; no cudaMalloc allowed) -----------------------
__device__ __align__(16) bf16 g_xh[ME * EMB];
__device__ __align__(16) bf16 g_xl[ME * EMB];
__device__ __align__(16) bf16 g_qh[ME * EMB];
__device__ __align__(16) bf16 g_ql[ME * EMB];
__device__ __align__(16) bf16 g_kh[ME * EMB];
__device__ __align__(16) bf16 g_kl[ME * EMB];
__device__ __align__(16) bf16 g_vh[ME * EMB];
__device__ __align__(16) bf16 g_vl[ME * EMB];
__device__ __align__(16) bf16 g_oh[ME * EMB];
__device__ __align__(16) bf16 g_ol[ME * EMB];
__device__ __align__(16) bf16 g_wh[4 * WSZ];
__device__ __align__(16) bf16 g_wl[4 * WSZ];

// ---- helpers ----------------------------------------------------------------
__device__ __forceinline__ unsigned sa(const void* p) {
    return (unsigned)__cvta_generic_to_shared(p);
}
__device__ __forceinline__ void ldsm4(unsigned r[4], unsigned addr) {
    asm volatile("ldmatrix.sync.aligned.m8n8.x4.shared.b16 {%0,%1,%2,%3}, [%4];"
                 : "=r"(r[0]), "=r"(r[1]), "=r"(r[2]), "=r"(r[3]) : "r"(addr));
}
__device__ __forceinline__ void ldsm4t(unsigned r[4], unsigned addr) {
    asm volatile("ldmatrix.sync.aligned.m8n8.x4.trans.shared.b16 {%0,%1,%2,%3}, [%4];"
                 : "=r"(r[0]), "=r"(r[1]), "=r"(r[2]), "=r"(r[3]) : "r"(addr));
}
__device__ __forceinline__ void mma16816(float d[4], const unsigned a[4],
                                         unsigned b0, unsigned b1) {
    asm volatile(
        "mma.sync.aligned.m16n8k16.row.col.f32.bf16.bf16.f32 "
        "{%0,%1,%2,%3}, {%4,%5,%6,%7}, {%8,%9}, {%0,%1,%2,%3};"
        : "+f"(d[0]), "+f"(d[1]), "+f"(d[2]), "+f"(d[3])
        : "r"(a[0]), "r"(a[1]), "r"(a[2]), "r"(a[3]), "r"(b0), "r"(b1));
}
__device__ __forceinline__ unsigned pk2(float lo, float hi) {
    unsigned r;
    asm("cvt.rn.bf16x2.f32 %0, %1, %2;" : "=r"(r) : "f"(hi), "f"(lo));
    return r;
}
__device__ __forceinline__ void unpk2(unsigned u, float& lo, float& hi) {
    __nv_bfloat162 t = *reinterpret_cast<__nv_bfloat162*>(&u);
    lo = __bfloat162float(t.x);
    hi = __bfloat162float(t.y);
}

#define CP_ASYNC16(dst, src) \
    asm volatile("cp.async.cg.shared.global [%0], [%1], 16;" :: "r"(dst), "l"(src))
#define CP_COMMIT() asm volatile("cp.async.commit_group;" ::: "memory")
#define CP_WAIT(n)  asm volatile("cp.async.wait_group %0;" :: "n"(n) : "memory")

// ---- split fp32 -> (hi, lo) bf16 ---------------------------------------------
__device__ __forceinline__ void split4(const float* __restrict__ in,
                                       bf16* __restrict__ h, bf16* __restrict__ l,
                                       int i)
{
    float4 v = *(const float4*)&in[i];
    bf16 h0 = __float2bfloat16_rn(v.x), h1 = __float2bfloat16_rn(v.y);
    bf16 h2 = __float2bfloat16_rn(v.z), h3 = __float2bfloat16_rn(v.w);
    __nv_bfloat162 hh0; hh0.x = h0; hh0.y = h1;
    __nv_bfloat162 hh1; hh1.x = h2; hh1.y = h3;
    *(__nv_bfloat162*)&h[i]     = hh0;
    *(__nv_bfloat162*)&h[i + 2] = hh1;
    __nv_bfloat162 ll0, ll1;
    ll0.x = __float2bfloat16_rn(v.x - __bfloat162float(h0));
    ll0.y = __float2bfloat16_rn(v.y - __bfloat162float(h1));
    ll1.x = __float2bfloat16_rn(v.z - __bfloat162float(h2));
    ll1.y = __float2bfloat16_rn(v.w - __bfloat162float(h3));
    *(__nv_bfloat162*)&l[i]     = ll0;
    *(__nv_bfloat162*)&l[i + 2] = ll1;
}

__global__ void split_x(const float* __restrict__ in, int n)
{
    int i = (blockIdx.x * blockDim.x + threadIdx.x) * 4;
    if (i < n) split4(in, g_xh, g_xl, i);
}

__global__ void split_w(const float* __restrict__ w0, const float* __restrict__ w1,
                        const float* __restrict__ w2, const float* __restrict__ w3)
{
    const int z = blockIdx.y;
    const float* src = (z == 0) ? w0 : (z == 1) ? w1 : (z == 2) ? w2 : w3;
    int i = (blockIdx.x * blockDim.x + threadIdx.x) * 4;
    if (i < WSZ) split4(src, g_wh + z * WSZ, g_wl + z * WSZ, i);
}

// ---------------------------------------------------------------------------
// bf16-split GEMM body (HMMA): tile 128x64, 256 thr, 8 warps (4 Mrow x 2 Ncol),
// cp.async 2-stage pipeline. Epilogue: fp32 (+bias), or bf16 split, optionally
// with fused per-(token,head) LayerNorm (tile == one head) + *512^-0.25.
// ---------------------------------------------------------------------------
__device__ __forceinline__ void proj_body(
    const bf16* __restrict__ Ah, const bf16* __restrict__ Al,
    const bf16* __restrict__ Wh, const bf16* __restrict__ Wl,
    const float* __restrict__ bias, float* __restrict__ C,
    bf16* __restrict__ Ch, bf16* __restrict__ Cl,
    const float* __restrict__ gam, const float* __restrict__ bet)
{
    extern __shared__ __align__(16) char smp[];
    const unsigned smb = sa(smp);

    const int tid  = threadIdx.x;
    const int lane = tid & 31;
    const int w    = tid >> 5;
    const int wr   = w & 3;
    const int wc   = w >> 2;
    const int row0 = blockIdx.x * 128;
    const int col0 = blockIdx.y * 64;

    const int lr  = tid >> 3;        // 0..31
    const int lcb = (tid & 7) * 16;  // byte col of 16B chunk
    const int lce = (tid & 7) * 8;   // element col

    float acc[2][4][4];
#pragma unroll
    for (int m = 0; m < 2; m++)
#pragma unroll
        for (int j = 0; j < 4; j++)
#pragma unroll
            for (int e = 0; e < 4; e++) acc[m][j][e] = 0.f;

    auto load_stage = [&](int s, int kt) {
        const unsigned st = smb + (unsigned)s * 55296u;
#pragma unroll
        for (int i = 0; i < 4; i++) {
            int r = lr + i * 32;
            unsigned dst = st + r * 144 + lcb;
            CP_ASYNC16(dst, Ah + (size_t)(row0 + r) * EMB + kt * 64 + lce);
            CP_ASYNC16(dst + 18432u, Al + (size_t)(row0 + r) * EMB + kt * 64 + lce);
        }
#pragma unroll
        for (int i = 0; i < 2; i++) {
            int r = lr + i * 32;
            unsigned dst = st + 36864u + r * 144 + lcb;
            CP_ASYNC16(dst, Wh + (size_t)(col0 + r) * EMB + kt * 64 + lce);
            CP_ASYNC16(dst + 9216u, Wl + (size_t)(col0 + r) * EMB + kt * 64 + lce);
        }
    };

    const unsigned aoff = (wr * 32 + (lane & 15)) * 144 + (lane >> 4) * 16;
    const unsigned boff = 36864u +
        (wc * 32 + ((lane >> 4) << 3) + (lane & 7)) * 144 + (((lane >> 3) & 1) * 16);

    load_stage(0, 0); CP_COMMIT();
    load_stage(1, 1); CP_COMMIT();

    for (int kt = 0; kt < 8; kt++) {
        const int s = kt & 1;
        if (kt < 7) { CP_WAIT(1); } else { CP_WAIT(0); }
        __syncthreads();
        const unsigned st = smb + (unsigned)s * 55296u;
        const unsigned aAh = st + aoff;
        const unsigned aWh = st + boff;
#pragma unroll
        for (int kc = 0; kc < 4; kc++) {
            unsigned a0h[4], a1h[4], a0l[4], a1l[4];
            ldsm4(a0h, aAh + kc * 32);
            ldsm4(a1h, aAh + kc * 32 + 16 * 144);
            ldsm4(a0l, aAh + 18432u + kc * 32);
            ldsm4(a1l, aAh + 18432u + kc * 32 + 16 * 144);
#pragma unroll
            for (int jp = 0; jp < 2; jp++) {
                unsigned bh[4], bl[4];
                ldsm4(bh, aWh + kc * 32 + jp * 16 * 144);
                ldsm4(bl, aWh + 9216u + kc * 32 + jp * 16 * 144);
                mma16816(acc[0][2 * jp],     a0h, bh[0], bh[1]);
                mma16816(acc[0][2 * jp + 1], a0h, bh[2], bh[3]);
                mma16816(acc[1][2 * jp],     a1h, bh[0], bh[1]);
                mma16816(acc[1][2 * jp + 1], a1h, bh[2], bh[3]);
                mma16816(acc[0][2 * jp],     a0h, bl[0], bl[1]);
                mma16816(acc[0][2 * jp + 1], a0h, bl[2], bl[3]);
                mma16816(acc[1][2 * jp],     a1h, bl[0], bl[1]);
                mma16816(acc[1][2 * jp + 1], a1h, bl[2], bl[3]);
                mma16816(acc[0][2 * jp],     a0l, bh[0], bh[1]);
                mma16816(acc[0][2 * jp + 1], a0l, bh[2], bh[3]);
                mma16816(acc[1][2 * jp],     a1l, bh[0], bh[1]);
                mma16816(acc[1][2 * jp + 1], a1l, bh[2], bh[3]);
            }
        }
        __syncthreads();
        if (kt + 2 < 8) { load_stage(s, kt + 2); CP_COMMIT(); }
    }

    if (gam) {
        // ---- per-row (token,head) LayerNorm over the 64-col tile + *SC ------
        float* redS = (float*)smp;          // [2][128]
        float* redQ = redS + 256;           // [2][128]
        float sum[2][2], ssq[2][2];
#pragma unroll
        for (int m = 0; m < 2; m++)
#pragma unroll
            for (int i = 0; i < 2; i++) {
                float s_ = 0.f, q_ = 0.f;
#pragma unroll
                for (int j = 0; j < 4; j++) {
                    float a0 = acc[m][j][2 * i], a1 = acc[m][j][2 * i + 1];
                    s_ += a0 + a1;
                    q_ += a0 * a0 + a1 * a1;
                }
                sum[m][i] = s_; ssq[m][i] = q_;
            }
#pragma unroll
        for (int off = 1; off <= 2; off <<= 1)
#pragma unroll
            for (int m = 0; m < 2; m++)
#pragma unroll
                for (int i = 0; i < 2; i++) {
                    sum[m][i] += __shfl_xor_sync(0xffffffffu, sum[m][i], off);
                    ssq[m][i] += __shfl_xor_sync(0xffffffffu, ssq[m][i], off);
                }
        if ((lane & 3) == 0) {
#pragma unroll
            for (int m = 0; m < 2; m++)
#pragma unroll
                for (int i = 0; i < 2; i++) {
                    int row = wr * 32 + m * 16 + i * 8 + (lane >> 2);
                    redS[wc * 128 + row] = sum[m][i];
                    redQ[wc * 128 + row] = ssq[m][i];
                }
        }
        __syncthreads();
        const float SC = 0.21022410381342865f;  // 512^-0.25
#pragma unroll
        for (int m = 0; m < 2; m++)
#pragma unroll
            for (int i = 0; i < 2; i++) {
                const int row = wr * 32 + m * 16 + i * 8 + (lane >> 2);
                const float s_ = redS[row] + redS[128 + row];
                const float q_ = redQ[row] + redQ[128 + row];
                const float mean = s_ * (1.f / 64.f);
                const float var  = q_ * (1.f / 64.f) - mean * mean;
                const float rs   = rsqrtf(var + 1e-5f);
                const int gr = row0 + row;
#pragma unroll
                for (int j = 0; j < 4; j++) {
                    const int cl = wc * 32 + j * 8 + (lane & 3) * 2;
                    float v0 = ((acc[m][j][2 * i]     - mean) * rs * gam[cl]     + bet[cl])     * SC;
                    float v1 = ((acc[m][j][2 * i + 1] - mean) * rs * gam[cl + 1] + bet[cl + 1]) * SC;
                    unsigned hp = pk2(v0, v1);
                    *(unsigned*)&Ch[(size_t)gr * EMB + col0 + cl] = hp;
                    float x, y;
                    unpk2(hp, x, y);
                    *(unsigned*)&Cl[(size_t)gr * EMB + col0 + cl] = pk2(v0 - x, v1 - y);
                }
            }
        return;
    }

    // ---- plain epilogue ------------------------------------------------------
#pragma unroll
    for (int m = 0; m < 2; m++) {
#pragma unroll
        for (int j = 0; j < 4; j++) {
            const int gr = row0 + wr * 32 + m * 16 + (lane >> 2);
            const int gc = col0 + wc * 32 + j * 8 + (lane & 3) * 2;
            float b0 = 0.f, b1 = 0.f;
            if (bias) { b0 = bias[gc]; b1 = bias[gc + 1]; }
            float v00 = acc[m][j][0] + b0, v01 = acc[m][j][1] + b1;
            float v10 = acc[m][j][2] + b0, v11 = acc[m][j][3] + b1;
            if (C) {
                *(float2*)&C[(size_t)gr * EMB + gc]       = make_float2(v00, v01);
                *(float2*)&C[(size_t)(gr + 8) * EMB + gc] = make_float2(v10, v11);
            }
            if (Ch) {
                unsigned h0 = pk2(v00, v01);
                unsigned h1 = pk2(v10, v11);
                *(unsigned*)&Ch[(size_t)gr * EMB + gc]       = h0;
                *(unsigned*)&Ch[(size_t)(gr + 8) * EMB + gc] = h1;
                float a_, b_;
                unpk2(h0, a_, b_);
                *(unsigned*)&Cl[(size_t)gr * EMB + gc] = pk2(v00 - a_, v01 - b_);
                unpk2(h1, a_, b_);
                *(unsigned*)&Cl[(size_t)(gr + 8) * EMB + gc] = pk2(v10 - a_, v11 - b_);
            }
        }
    }
}

__global__ __launch_bounds__(256, 2) void proj_qkv(
    const float* __restrict__ klng, const float* __restrict__ klnb,
    const float* __restrict__ qlng, const float* __restrict__ qlnb)
{
    const int z = blockIdx.z;
    const bf16* Wh = g_wh + (size_t)z * WSZ;
    const bf16* Wl = g_wl + (size_t)z * WSZ;
    if (z == 0)
        proj_body(g_xh, g_xl, Wh, Wl, nullptr, nullptr, g_kh, g_kl, klng, klnb);
    else if (z == 1)
        proj_body(g_xh, g_xl, Wh, Wl, nullptr, nullptr, g_qh, g_ql, qlng, qlnb);
    else
        proj_body(g_xh, g_xl, Wh, Wl, nullptr, nullptr, g_vh, g_vl, nullptr, nullptr);
}

__global__ __launch_bounds__(256, 2) void proj_out(const float* __restrict__ bias,
                                                   float* __restrict__ out)
{
    proj_body(g_oh, g_ol, g_wh + 3 * (size_t)WSZ, g_wl + 3 * (size_t)WSZ,
              bias, out, nullptr, nullptr, nullptr, nullptr);
}

// ---------------------------------------------------------------------------
// Flash attention, 128-query tiles, 256 thr. No-max softmax (LN bounds scores:
// |s| <= ||q||*||k|| = 2.83, exp can't overflow). cp.async double-buffered K/V.
// smem: Q 36864 + KV 2x36864 + mask 2x256 = 111104 B.
// ---------------------------------------------------------------------------
__global__ __launch_bounds__(256, 2) void attn_mma(const float* __restrict__ mask)
{
    extern __shared__ __align__(16) char smraw[];
    const unsigned smb = sa(smraw);
    const unsigned QH = 0, QL = 18432u, KV = 36864u, MK = 110592u;

    const int b   = blockIdx.z;
    const int h   = blockIdx.y;
    const int t0  = blockIdx.x * 128;
    const int tid = threadIdx.x;
    const int lane = tid & 31;
    const int w    = tid >> 5;

    // ---- Q load ----
#pragma unroll
    for (int i = 0; i < 4; i++) {
        int idx = tid + i * 256;           // 0..1023
        int r = idx >> 3, c = idx & 7;
        size_t gi = (size_t)(b * TT + t0 + r) * EMB + h * DD + c * 8;
        unsigned d = smb + QH + r * 144 + c * 16;
        CP_ASYNC16(d, g_qh + gi);
        CP_ASYNC16(d + QL, g_ql + gi);
    }

    auto load_kv = [&](int s, int kt) {
        const unsigned base = smb + KV + (unsigned)s * 36864u;
        const int s0 = kt * 64;
#pragma unroll
        for (int i = 0; i < 2; i++) {
            int idx = tid + i * 256;       // 0..511
            int r = idx >> 3, c = idx & 7;
            size_t gi = (size_t)(b * TT + s0 + r) * EMB + h * DD + c * 8;
            unsigned d = base + r * 144 + c * 16;
            CP_ASYNC16(d,          g_kh + gi);
            CP_ASYNC16(d + 9216u,  g_kl + gi);
            CP_ASYNC16(d + 18432u, g_vh + gi);
            CP_ASYNC16(d + 27648u, g_vl + gi);
        }
        if (tid < 16)
            CP_ASYNC16(smb + MK + (unsigned)s * 256u + tid * 16,
                       mask + b * TT + s0 + tid * 4);
    };

    load_kv(0, 0); CP_COMMIT();
    load_kv(1, 1); CP_COMMIT();

    const unsigned qh_a = smb + QH + (w * 16 + (lane & 15)) * 144 + (lane >> 4) * 16;
    const unsigned ql_a = qh_a + QL;
    const unsigned koff = (((lane >> 4) << 3) + (lane & 7)) * 144 + ((lane >> 3) & 1) * 16;
    const unsigned voff = ((((lane >> 3) & 1) * 8 + (lane & 7)) * 72 + ((lane >> 4) << 3)) * 2;

    float oa[8][4];
#pragma unroll
    for (int j = 0; j < 8; j++)
#pragma unroll
        for (int e = 0; e < 4; e++) oa[j][e] = 0.f;
    float l0 = 0.f, l1 = 0.f;

    const float mq0 = mask[b * TT + t0 + w * 16 + (lane >> 2)];
    const float mq1 = mask[b * TT + t0 + w * 16 + (lane >> 2) + 8];

    for (int kt = 0; kt < TT / 64; kt++) {
        const int s = kt & 1;
        if (kt < TT / 64 - 1) { CP_WAIT(1); } else { CP_WAIT(0); }
        __syncthreads();

        const unsigned stb  = smb + KV + (unsigned)s * 36864u;
        const unsigned kh_a = stb + koff;
        const unsigned kl_a = kh_a + 9216u;
        const unsigned vh_a = stb + 18432u + voff;
        const unsigned vl_a = vh_a + 9216u;
        const float* mkbuf = (const float*)(smraw + MK + (unsigned)s * 256u);

        // ---- S = Q K^T (restructured: Qh/Ql loaded once per kc) ----
        float sc[8][4];
#pragma unroll
        for (int j = 0; j < 8; j++)
#pragma unroll
            for (int e = 0; e < 4; e++) sc[j][e] = 0.f;

#pragma unroll
        for (int kc = 0; kc < 4; kc++) {
            unsigned ah[4], al[4];
            ldsm4(ah, qh_a + kc * 32);
            ldsm4(al, ql_a + kc * 32);
#pragma unroll
            for (int jp = 0; jp < 4; jp++) {
                unsigned bh[4], bl[4];
                ldsm4(bh, kh_a + kc * 32 + jp * 16 * 144);
                mma16816(sc[2 * jp],     ah, bh[0], bh[1]);
                mma16816(sc[2 * jp + 1], ah, bh[2], bh[3]);
                mma16816(sc[2 * jp],     al, bh[0], bh[1]);
                mma16816(sc[2 * jp + 1], al, bh[2], bh[3]);
                ldsm4(bl, kl_a + kc * 32 + jp * 16 * 144);
                mma16816(sc[2 * jp],     ah, bl[0], bl[1]);
                mma16816(sc[2 * jp + 1], ah, bl[2], bl[3]);
            }
        }

        // ---- mask + exp (no max subtraction: |s| <= 2.83 guaranteed) ----
#pragma unroll
        for (int j = 0; j < 8; j++) {
            int col = j * 8 + (lane & 3) * 2;
            float mk0 = mkbuf[col], mk1 = mkbuf[col + 1];
            sc[j][0] = (mq0 > 0.f && mk0 > 0.f) ? sc[j][0] : -30.f;
            sc[j][1] = (mq0 > 0.f && mk1 > 0.f) ? sc[j][1] : -30.f;
            sc[j][2] = (mq1 > 0.f && mk0 > 0.f) ? sc[j][2] : -30.f;
            sc[j][3] = (mq1 > 0.f && mk1 > 0.f) ? sc[j][3] : -30.f;
            sc[j][0] = __expf(sc[j][0]);
            sc[j][1] = __expf(sc[j][1]);
            sc[j][2] = __expf(sc[j][2]);
            sc[j][3] = __expf(sc[j][3]);
            l0 += sc[j][0] + sc[j][1];
            l1 += sc[j][2] + sc[j][3];
        }

        // ---- O += P V (restructured: Vh loaded once per kc*jp) ----
#pragma unroll
        for (int kc = 0; kc < 4; kc++) {
            unsigned ahp[4], alp[4];
            ahp[0] = pk2(sc[2 * kc][0],     sc[2 * kc][1]);
            ahp[1] = pk2(sc[2 * kc][2],     sc[2 * kc][3]);
            ahp[2] = pk2(sc[2 * kc + 1][0], sc[2 * kc + 1][1]);
            ahp[3] = pk2(sc[2 * kc + 1][2], sc[2 * kc + 1][3]);
            {
                float x, y;
                unpk2(ahp[0], x, y);
                alp[0] = pk2(sc[2 * kc][0] - x, sc[2 * kc][1] - y);
                unpk2(ahp[1], x, y);
                alp[1] = pk2(sc[2 * kc][2] - x, sc[2 * kc][3] - y);
                unpk2(ahp[2], x, y);
                alp[2] = pk2(sc[2 * kc + 1][0] - x, sc[2 * kc + 1][1] - y);
                unpk2(ahp[3], x, y);
                alp[3] = pk2(sc[2 * kc + 1][2] - x, sc[2 * kc + 1][3] - y);
            }
#pragma unroll
            for (int jp = 0; jp < 4; jp++) {
                unsigned bvh[4], bvl[4];
                ldsm4t(bvh, vh_a + kc * 16 * 144 + jp * 32);
                mma16816(oa[2 * jp],     ahp, bvh[0], bvh[1]);
                mma16816(oa[2 * jp + 1], ahp, bvh[2], bvh[3]);
                mma16816(oa[2 * jp],     alp, bvh[0], bvh[1]);
                mma16816(oa[2 * jp + 1], alp, bvh[2], bvh[3]);
                ldsm4t(bvl, vl_a + kc * 16 * 144 + jp * 32);
                mma16816(oa[2 * jp],     ahp, bvl[0], bvl[1]);
                mma16816(oa[2 * jp + 1], ahp, bvl[2], bvl[3]);
            }
        }

        __syncthreads();
        if (kt + 2 < TT / 64) { load_kv(s, kt + 2); CP_COMMIT(); }
    }

    // ---- epilogue: reduce l across quad, O / l -> bf16 split ----
    l0 += __shfl_xor_sync(0xffffffffu, l0, 1);
    l0 += __shfl_xor_sync(0xffffffffu, l0, 2);
    l1 += __shfl_xor_sync(0xffffffffu, l1, 1);
    l1 += __shfl_xor_sync(0xffffffffu, l1, 2);
    const float inv0 = 1.f / l0;
    const float inv1 = 1.f / l1;
    const int gr0 = b * TT + t0 + w * 16 + (lane >> 2);
#pragma unroll
    for (int j = 0; j < 8; j++) {
        const int col = h * DD + j * 8 + (lane & 3) * 2;
        float v00 = oa[j][0] * inv0, v01 = oa[j][1] * inv0;
        float v10 = oa[j][2] * inv1, v11 = oa[j][3] * inv1;
        unsigned h0 = pk2(v00, v01);
        unsigned h1 = pk2(v10, v11);
        *(unsigned*)&g_oh[(size_t)gr0 * EMB + col]       = h0;
        *(unsigned*)&g_oh[(size_t)(gr0 + 8) * EMB + col] = h1;
        float x, y;
        unpk2(h0, x, y);
        *(unsigned*)&g_ol[(size_t)gr0 * EMB + col] = pk2(v00 - x, v01 - y);
        unpk2(h1, x, y);
        *(unsigned*)&g_ol[(size_t)(gr0 + 8) * EMB + col] = pk2(v10 - x, v11 - y);
    }
}

// ---------------------------------------------------------------------------
extern "C" void kernel_launch(void* const* d_in, const int* in_sizes, int n_in,
                              void* d_out, int out_size)
{
    const float* x    = (const float*)d_in[0];
    const float* mask = (const float*)d_in[1];
    const float* Wk   = (const float*)d_in[2];
    const float* Wq   = (const float*)d_in[3];
    const float* Wv   = (const float*)d_in[4];
    const float* Wu   = (const float*)d_in[5];
    const float* bu   = (const float*)d_in[6];
    const float* klng = (const float*)d_in[7];
    const float* klnb = (const float*)d_in[8];
    const float* qlng = (const float*)d_in[9];
    const float* qlnb = (const float*)d_in[10];
    float* out = (float*)d_out;

    split_x<<<(ME * EMB / 4 + 255) / 256, 256>>>(x, ME * EMB);
    split_w<<<dim3((WSZ / 4 + 255) / 256, 4), 256>>>(Wk, Wq, Wv, Wu);

    const int PSMEM = 2 * 55296;  // 110592
    cudaFuncSetAttribute(proj_qkv,
                         cudaFuncAttributeMaxDynamicSharedMemorySize, PSMEM);
    cudaFuncSetAttribute(proj_out,
                         cudaFuncAttributeMaxDynamicSharedMemorySize, PSMEM);
    proj_qkv<<<dim3(ME / 128, EMB / 64, 3), 256, PSMEM>>>(klng, klnb, qlng, qlnb);

    const int ASMEM = 110592 + 512;  // 111104
    cudaFuncSetAttribute(attn_mma,
                         cudaFuncAttributeMaxDynamicSharedMemorySize, ASMEM);
    attn_mma<<<dim3(TT / 128, HH, BB), 256, ASMEM>>>(mask);

    proj_out<<<dim3(ME / 128, EMB / 64, 1), 256, PSMEM>>>(bu, out);
}

// round 8
// speedup vs baseline: 1.7522x; 1.1905x over previous
#include <cuda_runtime.h>
#include <cuda_bf16.h>
#include <cuda_fp16.h>
#include <cstdint>

#define ME   4096   // B*T rows
#define EMB  512
#define TT   2048
#define BB   2
#define HH   8
#define DD   64
#define WSZ  (EMB * EMB)

typedef __nv_bfloat16 bf16;

// ---- scratch (device globals; no cudaMalloc allowed) -----------------------
__device__ __align__(16) bf16   g_xh[ME * EMB];
__device__ __align__(16) bf16   g_xl[ME * EMB];
__device__ __align__(16) bf16   g_oh[ME * EMB];
__device__ __align__(16) bf16   g_ol[ME * EMB];
__device__ __align__(16) bf16   g_wh[4 * WSZ];
__device__ __align__(16) bf16   g_wl[4 * WSZ];
__device__ __align__(16) __half g_qh16[ME * EMB];
__device__ __align__(16) __half g_ql16[ME * EMB];
__device__ __align__(16) __half g_kh16[ME * EMB];
__device__ __align__(16) __half g_vh16[ME * EMB];

// ---- helpers ----------------------------------------------------------------
__device__ __forceinline__ unsigned sa(const void* p) {
    return (unsigned)__cvta_generic_to_shared(p);
}
__device__ __forceinline__ void ldsm4(unsigned r[4], unsigned addr) {
    asm volatile("ldmatrix.sync.aligned.m8n8.x4.shared.b16 {%0,%1,%2,%3}, [%4];"
                 : "=r"(r[0]), "=r"(r[1]), "=r"(r[2]), "=r"(r[3]) : "r"(addr));
}
__device__ __forceinline__ void ldsm4t(unsigned r[4], unsigned addr) {
    asm volatile("ldmatrix.sync.aligned.m8n8.x4.trans.shared.b16 {%0,%1,%2,%3}, [%4];"
                 : "=r"(r[0]), "=r"(r[1]), "=r"(r[2]), "=r"(r[3]) : "r"(addr));
}
// bf16 mma
__device__ __forceinline__ void mma16816(float d[4], const unsigned a[4],
                                         unsigned b0, unsigned b1) {
    asm volatile(
        "mma.sync.aligned.m16n8k16.row.col.f32.bf16.bf16.f32 "
        "{%0,%1,%2,%3}, {%4,%5,%6,%7}, {%8,%9}, {%0,%1,%2,%3};"
        : "+f"(d[0]), "+f"(d[1]), "+f"(d[2]), "+f"(d[3])
        : "r"(a[0]), "r"(a[1]), "r"(a[2]), "r"(a[3]), "r"(b0), "r"(b1));
}
// fp16 mma
__device__ __forceinline__ void mma16816h(float d[4], const unsigned a[4],
                                          unsigned b0, unsigned b1) {
    asm volatile(
        "mma.sync.aligned.m16n8k16.row.col.f32.f16.f16.f32 "
        "{%0,%1,%2,%3}, {%4,%5,%6,%7}, {%8,%9}, {%0,%1,%2,%3};"
        : "+f"(d[0]), "+f"(d[1]), "+f"(d[2]), "+f"(d[3])
        : "r"(a[0]), "r"(a[1]), "r"(a[2]), "r"(a[3]), "r"(b0), "r"(b1));
}
__device__ __forceinline__ unsigned pk2(float lo, float hi) {     // bf16x2
    unsigned r;
    asm("cvt.rn.bf16x2.f32 %0, %1, %2;" : "=r"(r) : "f"(hi), "f"(lo));
    return r;
}
__device__ __forceinline__ void unpk2(unsigned u, float& lo, float& hi) {
    __nv_bfloat162 t = *reinterpret_cast<__nv_bfloat162*>(&u);
    lo = __bfloat162float(t.x);
    hi = __bfloat162float(t.y);
}
__device__ __forceinline__ unsigned pk2h(float lo, float hi) {    // f16x2
    __half2 t = __floats2half2_rn(lo, hi);
    return *reinterpret_cast<unsigned*>(&t);
}
__device__ __forceinline__ void unpk2h(unsigned u, float& lo, float& hi) {
    __half2 t = *reinterpret_cast<__half2*>(&u);
    float2 f = __half22float2(t);
    lo = f.x; hi = f.y;
}

#define CP_ASYNC16(dst, src) \
    asm volatile("cp.async.cg.shared.global [%0], [%1], 16;" :: "r"(dst), "l"(src))
#define CP_COMMIT() asm volatile("cp.async.commit_group;" ::: "memory")
#define CP_WAIT(n)  asm volatile("cp.async.wait_group %0;" :: "n"(n) : "memory")

// ---- split fp32 -> (hi, lo) bf16 ---------------------------------------------
__device__ __forceinline__ void split4(const float* __restrict__ in,
                                       bf16* __restrict__ h, bf16* __restrict__ l,
                                       int i)
{
    float4 v = *(const float4*)&in[i];
    bf16 h0 = __float2bfloat16_rn(v.x), h1 = __float2bfloat16_rn(v.y);
    bf16 h2 = __float2bfloat16_rn(v.z), h3 = __float2bfloat16_rn(v.w);
    __nv_bfloat162 hh0; hh0.x = h0; hh0.y = h1;
    __nv_bfloat162 hh1; hh1.x = h2; hh1.y = h3;
    *(__nv_bfloat162*)&h[i]     = hh0;
    *(__nv_bfloat162*)&h[i + 2] = hh1;
    __nv_bfloat162 ll0, ll1;
    ll0.x = __float2bfloat16_rn(v.x - __bfloat162float(h0));
    ll0.y = __float2bfloat16_rn(v.y - __bfloat162float(h1));
    ll1.x = __float2bfloat16_rn(v.z - __bfloat162float(h2));
    ll1.y = __float2bfloat16_rn(v.w - __bfloat162float(h3));
    *(__nv_bfloat162*)&l[i]     = ll0;
    *(__nv_bfloat162*)&l[i + 2] = ll1;
}

__global__ void split_x(const float* __restrict__ in, int n)
{
    int i = (blockIdx.x * blockDim.x + threadIdx.x) * 4;
    if (i < n) split4(in, g_xh, g_xl, i);
}

__global__ void split_w(const float* __restrict__ w0, const float* __restrict__ w1,
                        const float* __restrict__ w2, const float* __restrict__ w3)
{
    const int z = blockIdx.y;
    const float* src = (z == 0) ? w0 : (z == 1) ? w1 : (z == 2) ? w2 : w3;
    int i = (blockIdx.x * blockDim.x + threadIdx.x) * 4;
    if (i < WSZ) split4(src, g_wh + z * WSZ, g_wl + z * WSZ, i);
}

// ---------------------------------------------------------------------------
// bf16-split GEMM body (HMMA, 3 terms): tile 128x64, 256 thr, cp.async 2-stage.
// Epilogues: fp32 (+bias); or fp16 out (hi, optional lo residual), optionally
// with fused per-(token,head) LayerNorm (tile == one head) + *512^-0.25.
// ---------------------------------------------------------------------------
__device__ __forceinline__ void proj_body(
    const bf16* __restrict__ Ah, const bf16* __restrict__ Al,
    const bf16* __restrict__ Wh, const bf16* __restrict__ Wl,
    const float* __restrict__ bias, float* __restrict__ C,
    __half* __restrict__ Hh, __half* __restrict__ Hl,
    const float* __restrict__ gam, const float* __restrict__ bet)
{
    extern __shared__ __align__(16) char smp[];
    const unsigned smb = sa(smp);

    const int tid  = threadIdx.x;
    const int lane = tid & 31;
    const int w    = tid >> 5;
    const int wr   = w & 3;
    const int wc   = w >> 2;
    const int row0 = blockIdx.x * 128;
    const int col0 = blockIdx.y * 64;

    const int lr  = tid >> 3;
    const int lcb = (tid & 7) * 16;
    const int lce = (tid & 7) * 8;

    float acc[2][4][4];
#pragma unroll
    for (int m = 0; m < 2; m++)
#pragma unroll
        for (int j = 0; j < 4; j++)
#pragma unroll
            for (int e = 0; e < 4; e++) acc[m][j][e] = 0.f;

    auto load_stage = [&](int s, int kt) {
        const unsigned st = smb + (unsigned)s * 55296u;
#pragma unroll
        for (int i = 0; i < 4; i++) {
            int r = lr + i * 32;
            unsigned dst = st + r * 144 + lcb;
            CP_ASYNC16(dst, Ah + (size_t)(row0 + r) * EMB + kt * 64 + lce);
            CP_ASYNC16(dst + 18432u, Al + (size_t)(row0 + r) * EMB + kt * 64 + lce);
        }
#pragma unroll
        for (int i = 0; i < 2; i++) {
            int r = lr + i * 32;
            unsigned dst = st + 36864u + r * 144 + lcb;
            CP_ASYNC16(dst, Wh + (size_t)(col0 + r) * EMB + kt * 64 + lce);
            CP_ASYNC16(dst + 9216u, Wl + (size_t)(col0 + r) * EMB + kt * 64 + lce);
        }
    };

    const unsigned aoff = (wr * 32 + (lane & 15)) * 144 + (lane >> 4) * 16;
    const unsigned boff = 36864u +
        (wc * 32 + ((lane >> 4) << 3) + (lane & 7)) * 144 + (((lane >> 3) & 1) * 16);

    load_stage(0, 0); CP_COMMIT();
    load_stage(1, 1); CP_COMMIT();

    for (int kt = 0; kt < 8; kt++) {
        const int s = kt & 1;
        if (kt < 7) { CP_WAIT(1); } else { CP_WAIT(0); }
        __syncthreads();
        const unsigned st = smb + (unsigned)s * 55296u;
        const unsigned aAh = st + aoff;
        const unsigned aWh = st + boff;
#pragma unroll
        for (int kc = 0; kc < 4; kc++) {
            unsigned a0h[4], a1h[4], a0l[4], a1l[4];
            ldsm4(a0h, aAh + kc * 32);
            ldsm4(a1h, aAh + kc * 32 + 16 * 144);
            ldsm4(a0l, aAh + 18432u + kc * 32);
            ldsm4(a1l, aAh + 18432u + kc * 32 + 16 * 144);
#pragma unroll
            for (int jp = 0; jp < 2; jp++) {
                unsigned bh[4], bl[4];
                ldsm4(bh, aWh + kc * 32 + jp * 16 * 144);
                ldsm4(bl, aWh + 9216u + kc * 32 + jp * 16 * 144);
                mma16816(acc[0][2 * jp],     a0h, bh[0], bh[1]);
                mma16816(acc[0][2 * jp + 1], a0h, bh[2], bh[3]);
                mma16816(acc[1][2 * jp],     a1h, bh[0], bh[1]);
                mma16816(acc[1][2 * jp + 1], a1h, bh[2], bh[3]);
                mma16816(acc[0][2 * jp],     a0h, bl[0], bl[1]);
                mma16816(acc[0][2 * jp + 1], a0h, bl[2], bl[3]);
                mma16816(acc[1][2 * jp],     a1h, bl[0], bl[1]);
                mma16816(acc[1][2 * jp + 1], a1h, bl[2], bl[3]);
                mma16816(acc[0][2 * jp],     a0l, bh[0], bh[1]);
                mma16816(acc[0][2 * jp + 1], a0l, bh[2], bh[3]);
                mma16816(acc[1][2 * jp],     a1l, bh[0], bh[1]);
                mma16816(acc[1][2 * jp + 1], a1l, bh[2], bh[3]);
            }
        }
        __syncthreads();
        if (kt + 2 < 8) { load_stage(s, kt + 2); CP_COMMIT(); }
    }

    if (gam) {
        // ---- fused per-row LayerNorm + *SC -> fp16 (hi, optional lo) --------
        float* redS = (float*)smp;          // [2][128]
        float* redQ = redS + 256;           // [2][128]
        float sum[2][2], ssq[2][2];
#pragma unroll
        for (int m = 0; m < 2; m++)
#pragma unroll
            for (int i = 0; i < 2; i++) {
                float s_ = 0.f, q_ = 0.f;
#pragma unroll
                for (int j = 0; j < 4; j++) {
                    float a0 = acc[m][j][2 * i], a1 = acc[m][j][2 * i + 1];
                    s_ += a0 + a1;
                    q_ += a0 * a0 + a1 * a1;
                }
                sum[m][i] = s_; ssq[m][i] = q_;
            }
#pragma unroll
        for (int off = 1; off <= 2; off <<= 1)
#pragma unroll
            for (int m = 0; m < 2; m++)
#pragma unroll
                for (int i = 0; i < 2; i++) {
                    sum[m][i] += __shfl_xor_sync(0xffffffffu, sum[m][i], off);
                    ssq[m][i] += __shfl_xor_sync(0xffffffffu, ssq[m][i], off);
                }
        if ((lane & 3) == 0) {
#pragma unroll
            for (int m = 0; m < 2; m++)
#pragma unroll
                for (int i = 0; i < 2; i++) {
                    int row = wr * 32 + m * 16 + i * 8 + (lane >> 2);
                    redS[wc * 128 + row] = sum[m][i];
                    redQ[wc * 128 + row] = ssq[m][i];
                }
        }
        __syncthreads();
        const float SC = 0.21022410381342865f;  // 512^-0.25
#pragma unroll
        for (int m = 0; m < 2; m++)
#pragma unroll
            for (int i = 0; i < 2; i++) {
                const int row = wr * 32 + m * 16 + i * 8 + (lane >> 2);
                const float s_ = redS[row] + redS[128 + row];
                const float q_ = redQ[row] + redQ[128 + row];
                const float mean = s_ * (1.f / 64.f);
                const float var  = q_ * (1.f / 64.f) - mean * mean;
                const float rs   = rsqrtf(var + 1e-5f);
                const int gr = row0 + row;
#pragma unroll
                for (int j = 0; j < 4; j++) {
                    const int cl = wc * 32 + j * 8 + (lane & 3) * 2;
                    float v0 = ((acc[m][j][2 * i]     - mean) * rs * gam[cl]     + bet[cl])     * SC;
                    float v1 = ((acc[m][j][2 * i + 1] - mean) * rs * gam[cl + 1] + bet[cl + 1]) * SC;
                    unsigned hp = pk2h(v0, v1);
                    *(unsigned*)&Hh[(size_t)gr * EMB + col0 + cl] = hp;
                    if (Hl) {
                        float x, y;
                        unpk2h(hp, x, y);
                        *(unsigned*)&Hl[(size_t)gr * EMB + col0 + cl] = pk2h(v0 - x, v1 - y);
                    }
                }
            }
        return;
    }

    // ---- plain epilogue ------------------------------------------------------
#pragma unroll
    for (int m = 0; m < 2; m++) {
#pragma unroll
        for (int j = 0; j < 4; j++) {
            const int gr = row0 + wr * 32 + m * 16 + (lane >> 2);
            const int gc = col0 + wc * 32 + j * 8 + (lane & 3) * 2;
            float b0 = 0.f, b1 = 0.f;
            if (bias) { b0 = bias[gc]; b1 = bias[gc + 1]; }
            float v00 = acc[m][j][0] + b0, v01 = acc[m][j][1] + b1;
            float v10 = acc[m][j][2] + b0, v11 = acc[m][j][3] + b1;
            if (C) {
                *(float2*)&C[(size_t)gr * EMB + gc]       = make_float2(v00, v01);
                *(float2*)&C[(size_t)(gr + 8) * EMB + gc] = make_float2(v10, v11);
            }
            if (Hh) {
                *(unsigned*)&Hh[(size_t)gr * EMB + gc]       = pk2h(v00, v01);
                *(unsigned*)&Hh[(size_t)(gr + 8) * EMB + gc] = pk2h(v10, v11);
            }
        }
    }
}

__global__ __launch_bounds__(256, 2) void proj_qkv(
    const float* __restrict__ klng, const float* __restrict__ klnb,
    const float* __restrict__ qlng, const float* __restrict__ qlnb)
{
    const int z = blockIdx.z;
    const bf16* Wh = g_wh + (size_t)z * WSZ;
    const bf16* Wl = g_wl + (size_t)z * WSZ;
    if (z == 0)       // K: LN, fp16 hi only
        proj_body(g_xh, g_xl, Wh, Wl, nullptr, nullptr, g_kh16, nullptr, klng, klnb);
    else if (z == 1)  // Q: LN, fp16 hi + lo
        proj_body(g_xh, g_xl, Wh, Wl, nullptr, nullptr, g_qh16, g_ql16, qlng, qlnb);
    else              // V: plain, fp16 hi only
        proj_body(g_xh, g_xl, Wh, Wl, nullptr, nullptr, g_vh16, nullptr, nullptr, nullptr);
}

__global__ __launch_bounds__(256, 2) void proj_out(const float* __restrict__ bias,
                                                   float* __restrict__ out)
{
    proj_body(g_oh, g_ol, g_wh + 3 * (size_t)WSZ, g_wl + 3 * (size_t)WSZ,
              bias, out, nullptr, nullptr, nullptr, nullptr);
}

// ---------------------------------------------------------------------------
// Flash attention (fp16, 2-term): 128-query tiles, 256 thr. No-max softmax
// (LN bounds |s| <= 2.83). S = (Qh+Ql)*K, O = (Ph+Pl)*V with K,V single fp16.
// Q fragments hoisted to registers. cp.async double-buffered K/V.
// smem: Qh/Ql 2x18432 + 2 stages x {K,V} 18432 + mask 512 = 74240 B.
// ---------------------------------------------------------------------------
__global__ __launch_bounds__(256, 2) void attn_mma(const float* __restrict__ mask)
{
    extern __shared__ __align__(16) char smraw[];
    const unsigned smb = sa(smraw);
    const unsigned QH = 0, QL = 18432u, KV = 36864u, MK = 73728u;

    const int b   = blockIdx.z;
    const int h   = blockIdx.y;
    const int t0  = blockIdx.x * 128;
    const int tid = threadIdx.x;
    const int lane = tid & 31;
    const int w    = tid >> 5;

    // ---- Q load (fp16 hi + lo) ----
#pragma unroll
    for (int i = 0; i < 4; i++) {
        int idx = tid + i * 256;           // 0..1023
        int r = idx >> 3, c = idx & 7;
        size_t gi = (size_t)(b * TT + t0 + r) * EMB + h * DD + c * 8;
        unsigned d = smb + QH + r * 144 + c * 16;
        CP_ASYNC16(d, g_qh16 + gi);
        CP_ASYNC16(d + QL, g_ql16 + gi);
    }

    auto load_kv = [&](int s, int kt) {
        const unsigned base = smb + KV + (unsigned)s * 18432u;
        const int s0 = kt * 64;
#pragma unroll
        for (int i = 0; i < 2; i++) {
            int idx = tid + i * 256;       // 0..511
            int r = idx >> 3, c = idx & 7;
            size_t gi = (size_t)(b * TT + s0 + r) * EMB + h * DD + c * 8;
            unsigned d = base + r * 144 + c * 16;
            CP_ASYNC16(d,         g_kh16 + gi);
            CP_ASYNC16(d + 9216u, g_vh16 + gi);
        }
        if (tid < 16)
            CP_ASYNC16(smb + MK + (unsigned)s * 256u + tid * 16,
                       mask + b * TT + s0 + tid * 4);
    };

    load_kv(0, 0); CP_COMMIT();
    load_kv(1, 1); CP_COMMIT();

    const unsigned qh_a = smb + QH + (w * 16 + (lane & 15)) * 144 + (lane >> 4) * 16;
    const unsigned ql_a = qh_a + QL;
    const unsigned koff = (((lane >> 4) << 3) + (lane & 7)) * 144 + ((lane >> 3) & 1) * 16;
    const unsigned voff = ((((lane >> 3) & 1) * 8 + (lane & 7)) * 72 + ((lane >> 4) << 3)) * 2;

    // ---- wait Q (+stage0), hoist Q fragments into registers ----
    CP_WAIT(1);
    __syncthreads();
    unsigned qhf[4][4], qlf[4][4];
#pragma unroll
    for (int kc = 0; kc < 4; kc++) {
        ldsm4(qhf[kc], qh_a + kc * 32);
        ldsm4(qlf[kc], ql_a + kc * 32);
    }

    float oa[8][4];
#pragma unroll
    for (int j = 0; j < 8; j++)
#pragma unroll
        for (int e = 0; e < 4; e++) oa[j][e] = 0.f;
    float l0 = 0.f, l1 = 0.f;

    const float mq0 = mask[b * TT + t0 + w * 16 + (lane >> 2)];
    const float mq1 = mask[b * TT + t0 + w * 16 + (lane >> 2) + 8];

    for (int kt = 0; kt < TT / 64; kt++) {
        const int s = kt & 1;
        if (kt < TT / 64 - 1) { CP_WAIT(1); } else { CP_WAIT(0); }
        __syncthreads();

        const unsigned stb  = smb + KV + (unsigned)s * 18432u;
        const unsigned kh_a = stb + koff;
        const unsigned vh_a = stb + 9216u + voff;
        const float* mkbuf = (const float*)(smraw + MK + (unsigned)s * 256u);

        // ---- S = (Qh + Ql) * K ----
        float sc[8][4];
#pragma unroll
        for (int j = 0; j < 8; j++)
#pragma unroll
            for (int e = 0; e < 4; e++) sc[j][e] = 0.f;

#pragma unroll
        for (int kc = 0; kc < 4; kc++) {
#pragma unroll
            for (int jp = 0; jp < 4; jp++) {
                unsigned bh[4];
                ldsm4(bh, kh_a + kc * 32 + jp * 16 * 144);
                mma16816h(sc[2 * jp],     qhf[kc], bh[0], bh[1]);
                mma16816h(sc[2 * jp + 1], qhf[kc], bh[2], bh[3]);
                mma16816h(sc[2 * jp],     qlf[kc], bh[0], bh[1]);
                mma16816h(sc[2 * jp + 1], qlf[kc], bh[2], bh[3]);
            }
        }

        // ---- mask + exp (no max subtraction) ----
#pragma unroll
        for (int j = 0; j < 8; j++) {
            int col = j * 8 + (lane & 3) * 2;
            float mk0 = mkbuf[col], mk1 = mkbuf[col + 1];
            sc[j][0] = (mq0 > 0.f && mk0 > 0.f) ? sc[j][0] : -30.f;
            sc[j][1] = (mq0 > 0.f && mk1 > 0.f) ? sc[j][1] : -30.f;
            sc[j][2] = (mq1 > 0.f && mk0 > 0.f) ? sc[j][2] : -30.f;
            sc[j][3] = (mq1 > 0.f && mk1 > 0.f) ? sc[j][3] : -30.f;
            sc[j][0] = __expf(sc[j][0]);
            sc[j][1] = __expf(sc[j][1]);
            sc[j][2] = __expf(sc[j][2]);
            sc[j][3] = __expf(sc[j][3]);
            l0 += sc[j][0] + sc[j][1];
            l1 += sc[j][2] + sc[j][3];
        }

        // ---- O += (Ph + Pl) * V ----
#pragma unroll
        for (int kc = 0; kc < 4; kc++) {
            unsigned ahp[4], alp[4];
            ahp[0] = pk2h(sc[2 * kc][0],     sc[2 * kc][1]);
            ahp[1] = pk2h(sc[2 * kc][2],     sc[2 * kc][3]);
            ahp[2] = pk2h(sc[2 * kc + 1][0], sc[2 * kc + 1][1]);
            ahp[3] = pk2h(sc[2 * kc + 1][2], sc[2 * kc + 1][3]);
            {
                float x, y;
                unpk2h(ahp[0], x, y);
                alp[0] = pk2h(sc[2 * kc][0] - x, sc[2 * kc][1] - y);
                unpk2h(ahp[1], x, y);
                alp[1] = pk2h(sc[2 * kc][2] - x, sc[2 * kc][3] - y);
                unpk2h(ahp[2], x, y);
                alp[2] = pk2h(sc[2 * kc + 1][0] - x, sc[2 * kc + 1][1] - y);
                unpk2h(ahp[3], x, y);
                alp[3] = pk2h(sc[2 * kc + 1][2] - x, sc[2 * kc + 1][3] - y);
            }
#pragma unroll
            for (int jp = 0; jp < 4; jp++) {
                unsigned bv[4];
                ldsm4t(bv, vh_a + kc * 16 * 144 + jp * 32);
                mma16816h(oa[2 * jp],     ahp, bv[0], bv[1]);
                mma16816h(oa[2 * jp + 1], ahp, bv[2], bv[3]);
                mma16816h(oa[2 * jp],     alp, bv[0], bv[1]);
                mma16816h(oa[2 * jp + 1], alp, bv[2], bv[3]);
            }
        }

        __syncthreads();
        if (kt + 2 < TT / 64) { load_kv(s, kt + 2); CP_COMMIT(); }
    }

    // ---- epilogue: reduce l across quad, O / l -> bf16 split ----
    l0 += __shfl_xor_sync(0xffffffffu, l0, 1);
    l0 += __shfl_xor_sync(0xffffffffu, l0, 2);
    l1 += __shfl_xor_sync(0xffffffffu, l1, 1);
    l1 += __shfl_xor_sync(0xffffffffu, l1, 2);
    const float inv0 = 1.f / l0;
    const float inv1 = 1.f / l1;
    const int gr0 = b * TT + t0 + w * 16 + (lane >> 2);
#pragma unroll
    for (int j = 0; j < 8; j++) {
        const int col = h * DD + j * 8 + (lane & 3) * 2;
        float v00 = oa[j][0] * inv0, v01 = oa[j][1] * inv0;
        float v10 = oa[j][2] * inv1, v11 = oa[j][3] * inv1;
        unsigned h0 = pk2(v00, v01);
        unsigned h1 = pk2(v10, v11);
        *(unsigned*)&g_oh[(size_t)gr0 * EMB + col]       = h0;
        *(unsigned*)&g_oh[(size_t)(gr0 + 8) * EMB + col] = h1;
        float x, y;
        unpk2(h0, x, y);
        *(unsigned*)&g_ol[(size_t)gr0 * EMB + col] = pk2(v00 - x, v01 - y);
        unpk2(h1, x, y);
        *(unsigned*)&g_ol[(size_t)(gr0 + 8) * EMB + col] = pk2(v10 - x, v11 - y);
    }
}

// ---------------------------------------------------------------------------
extern "C" void kernel_launch(void* const* d_in, const int* in_sizes, int n_in,
                              void* d_out, int out_size)
{
    const float* x    = (const float*)d_in[0];
    const float* mask = (const float*)d_in[1];
    const float* Wk   = (const float*)d_in[2];
    const float* Wq   = (const float*)d_in[3];
    const float* Wv   = (const float*)d_in[4];
    const float* Wu   = (const float*)d_in[5];
    const float* bu   = (const float*)d_in[6];
    const float* klng = (const float*)d_in[7];
    const float* klnb = (const float*)d_in[8];
    const float* qlng = (const float*)d_in[9];
    const float* qlnb = (const float*)d_in[10];
    float* out = (float*)d_out;

    split_x<<<(ME * EMB / 4 + 255) / 256, 256>>>(x, ME * EMB);
    split_w<<<dim3((WSZ / 4 + 255) / 256, 4), 256>>>(Wk, Wq, Wv, Wu);

    const int PSMEM = 2 * 55296;  // 110592
    cudaFuncSetAttribute(proj_qkv,
                         cudaFuncAttributeMaxDynamicSharedMemorySize, PSMEM);
    cudaFuncSetAttribute(proj_out,
                         cudaFuncAttributeMaxDynamicSharedMemorySize, PSMEM);
    proj_qkv<<<dim3(ME / 128, EMB / 64, 3), 256, PSMEM>>>(klng, klnb, qlng, qlnb);

    const int ASMEM = 73728 + 512;  // 74240
    cudaFuncSetAttribute(attn_mma,
                         cudaFuncAttributeMaxDynamicSharedMemorySize, ASMEM);
    attn_mma<<<dim3(TT / 128, HH, BB), 256, ASMEM>>>(mask);

    proj_out<<<dim3(ME / 128, EMB / 64, 1), 256, PSMEM>>>(bu, out);
}

// round 9
// speedup vs baseline: 2.2076x; 1.2599x over previous
#include <cuda_runtime.h>
#include <cuda_bf16.h>
#include <cuda_fp16.h>
#include <cstdint>

#define ME   4096   // B*T rows
#define EMB  512
#define TT   2048
#define BB   2
#define HH   8
#define DD   64
#define WSZ  (EMB * EMB)

typedef __nv_bfloat16 bf16;

// ---- scratch (device globals; no cudaMalloc allowed) -----------------------
__device__ __align__(16) bf16   g_xh[ME * EMB];
__device__ __align__(16) bf16   g_xl[ME * EMB];
__device__ __align__(16) bf16   g_oh[ME * EMB];
__device__ __align__(16) bf16   g_ol[ME * EMB];
__device__ __align__(16) bf16   g_wh[4 * WSZ];
__device__ __align__(16) bf16   g_wl[4 * WSZ];
__device__ __align__(16) __half g_qh16[ME * EMB];   // carries SC*log2e
__device__ __align__(16) __half g_kh16[ME * EMB];   // carries SC
__device__ __align__(16) __half g_vh16[ME * EMB];

// ---- helpers ----------------------------------------------------------------
__device__ __forceinline__ unsigned sa(const void* p) {
    return (unsigned)__cvta_generic_to_shared(p);
}
__device__ __forceinline__ void ldsm4(unsigned r[4], unsigned addr) {
    asm volatile("ldmatrix.sync.aligned.m8n8.x4.shared.b16 {%0,%1,%2,%3}, [%4];"
                 : "=r"(r[0]), "=r"(r[1]), "=r"(r[2]), "=r"(r[3]) : "r"(addr));
}
__device__ __forceinline__ void ldsm4t(unsigned r[4], unsigned addr) {
    asm volatile("ldmatrix.sync.aligned.m8n8.x4.trans.shared.b16 {%0,%1,%2,%3}, [%4];"
                 : "=r"(r[0]), "=r"(r[1]), "=r"(r[2]), "=r"(r[3]) : "r"(addr));
}
__device__ __forceinline__ void mma16816(float d[4], const unsigned a[4],
                                         unsigned b0, unsigned b1) {
    asm volatile(
        "mma.sync.aligned.m16n8k16.row.col.f32.bf16.bf16.f32 "
        "{%0,%1,%2,%3}, {%4,%5,%6,%7}, {%8,%9}, {%0,%1,%2,%3};"
        : "+f"(d[0]), "+f"(d[1]), "+f"(d[2]), "+f"(d[3])
        : "r"(a[0]), "r"(a[1]), "r"(a[2]), "r"(a[3]), "r"(b0), "r"(b1));
}
__device__ __forceinline__ void mma16816h(float d[4], const unsigned a[4],
                                          unsigned b0, unsigned b1) {
    asm volatile(
        "mma.sync.aligned.m16n8k16.row.col.f32.f16.f16.f32 "
        "{%0,%1,%2,%3}, {%4,%5,%6,%7}, {%8,%9}, {%0,%1,%2,%3};"
        : "+f"(d[0]), "+f"(d[1]), "+f"(d[2]), "+f"(d[3])
        : "r"(a[0]), "r"(a[1]), "r"(a[2]), "r"(a[3]), "r"(b0), "r"(b1));
}
__device__ __forceinline__ unsigned pk2(float lo, float hi) {     // bf16x2
    unsigned r;
    asm("cvt.rn.bf16x2.f32 %0, %1, %2;" : "=r"(r) : "f"(hi), "f"(lo));
    return r;
}
__device__ __forceinline__ void unpk2(unsigned u, float& lo, float& hi) {
    __nv_bfloat162 t = *reinterpret_cast<__nv_bfloat162*>(&u);
    lo = __bfloat162float(t.x);
    hi = __bfloat162float(t.y);
}
__device__ __forceinline__ unsigned pk2h(float lo, float hi) {    // f16x2
    __half2 t = __floats2half2_rn(lo, hi);
    return *reinterpret_cast<unsigned*>(&t);
}
__device__ __forceinline__ unsigned ex2h2(unsigned a) {           // 2^x on f16x2
    unsigned r;
    asm("ex2.approx.f16x2 %0, %1;" : "=r"(r) : "r"(a));
    return r;
}
__device__ __forceinline__ float2 h22f2(unsigned u) {
    __half2 t = *reinterpret_cast<__half2*>(&u);
    return __half22float2(t);
}

#define CP_ASYNC16(dst, src) \
    asm volatile("cp.async.cg.shared.global [%0], [%1], 16;" :: "r"(dst), "l"(src))
#define CP_COMMIT() asm volatile("cp.async.commit_group;" ::: "memory")
#define CP_WAIT(n)  asm volatile("cp.async.wait_group %0;" :: "n"(n) : "memory")

// ---- split fp32 -> (hi, lo) bf16 ---------------------------------------------
__device__ __forceinline__ void split4(const float* __restrict__ in,
                                       bf16* __restrict__ h, bf16* __restrict__ l,
                                       int i)
{
    float4 v = *(const float4*)&in[i];
    bf16 h0 = __float2bfloat16_rn(v.x), h1 = __float2bfloat16_rn(v.y);
    bf16 h2 = __float2bfloat16_rn(v.z), h3 = __float2bfloat16_rn(v.w);
    __nv_bfloat162 hh0; hh0.x = h0; hh0.y = h1;
    __nv_bfloat162 hh1; hh1.x = h2; hh1.y = h3;
    *(__nv_bfloat162*)&h[i]     = hh0;
    *(__nv_bfloat162*)&h[i + 2] = hh1;
    __nv_bfloat162 ll0, ll1;
    ll0.x = __float2bfloat16_rn(v.x - __bfloat162float(h0));
    ll0.y = __float2bfloat16_rn(v.y - __bfloat162float(h1));
    ll1.x = __float2bfloat16_rn(v.z - __bfloat162float(h2));
    ll1.y = __float2bfloat16_rn(v.w - __bfloat162float(h3));
    *(__nv_bfloat162*)&l[i]     = ll0;
    *(__nv_bfloat162*)&l[i + 2] = ll1;
}

__global__ void split_x(const float* __restrict__ in, int n)
{
    int i = (blockIdx.x * blockDim.x + threadIdx.x) * 4;
    if (i < n) split4(in, g_xh, g_xl, i);
}

__global__ void split_w(const float* __restrict__ w0, const float* __restrict__ w1,
                        const float* __restrict__ w2, const float* __restrict__ w3)
{
    const int z = blockIdx.y;
    const float* src = (z == 0) ? w0 : (z == 1) ? w1 : (z == 2) ? w2 : w3;
    int i = (blockIdx.x * blockDim.x + threadIdx.x) * 4;
    if (i < WSZ) split4(src, g_wh + z * WSZ, g_wl + z * WSZ, i);
}

// ---------------------------------------------------------------------------
// bf16-split GEMM body (HMMA, 3 terms): tile 128x64, 256 thr, cp.async 2-stage.
// Epilogues: fp32 (+bias); or fp16 hi out, optionally with fused per-(token,
// head) LayerNorm (tile == one head) scaled by `lnsc`.
// ---------------------------------------------------------------------------
__device__ __forceinline__ void proj_body(
    const bf16* __restrict__ Ah, const bf16* __restrict__ Al,
    const bf16* __restrict__ Wh, const bf16* __restrict__ Wl,
    const float* __restrict__ bias, float* __restrict__ C,
    __half* __restrict__ Hh,
    const float* __restrict__ gam, const float* __restrict__ bet, float lnsc)
{
    extern __shared__ __align__(16) char smp[];
    const unsigned smb = sa(smp);

    const int tid  = threadIdx.x;
    const int lane = tid & 31;
    const int w    = tid >> 5;
    const int wr   = w & 3;
    const int wc   = w >> 2;
    const int row0 = blockIdx.x * 128;
    const int col0 = blockIdx.y * 64;

    const int lr  = tid >> 3;
    const int lcb = (tid & 7) * 16;
    const int lce = (tid & 7) * 8;

    float acc[2][4][4];
#pragma unroll
    for (int m = 0; m < 2; m++)
#pragma unroll
        for (int j = 0; j < 4; j++)
#pragma unroll
            for (int e = 0; e < 4; e++) acc[m][j][e] = 0.f;

    auto load_stage = [&](int s, int kt) {
        const unsigned st = smb + (unsigned)s * 55296u;
#pragma unroll
        for (int i = 0; i < 4; i++) {
            int r = lr + i * 32;
            unsigned dst = st + r * 144 + lcb;
            CP_ASYNC16(dst, Ah + (size_t)(row0 + r) * EMB + kt * 64 + lce);
            CP_ASYNC16(dst + 18432u, Al + (size_t)(row0 + r) * EMB + kt * 64 + lce);
        }
#pragma unroll
        for (int i = 0; i < 2; i++) {
            int r = lr + i * 32;
            unsigned dst = st + 36864u + r * 144 + lcb;
            CP_ASYNC16(dst, Wh + (size_t)(col0 + r) * EMB + kt * 64 + lce);
            CP_ASYNC16(dst + 9216u, Wl + (size_t)(col0 + r) * EMB + kt * 64 + lce);
        }
    };

    const unsigned aoff = (wr * 32 + (lane & 15)) * 144 + (lane >> 4) * 16;
    const unsigned boff = 36864u +
        (wc * 32 + ((lane >> 4) << 3) + (lane & 7)) * 144 + (((lane >> 3) & 1) * 16);

    load_stage(0, 0); CP_COMMIT();
    load_stage(1, 1); CP_COMMIT();

    for (int kt = 0; kt < 8; kt++) {
        const int s = kt & 1;
        if (kt < 7) { CP_WAIT(1); } else { CP_WAIT(0); }
        __syncthreads();
        const unsigned st = smb + (unsigned)s * 55296u;
        const unsigned aAh = st + aoff;
        const unsigned aWh = st + boff;
#pragma unroll
        for (int kc = 0; kc < 4; kc++) {
            unsigned a0h[4], a1h[4], a0l[4], a1l[4];
            ldsm4(a0h, aAh + kc * 32);
            ldsm4(a1h, aAh + kc * 32 + 16 * 144);
            ldsm4(a0l, aAh + 18432u + kc * 32);
            ldsm4(a1l, aAh + 18432u + kc * 32 + 16 * 144);
#pragma unroll
            for (int jp = 0; jp < 2; jp++) {
                unsigned bh[4], bl[4];
                ldsm4(bh, aWh + kc * 32 + jp * 16 * 144);
                ldsm4(bl, aWh + 9216u + kc * 32 + jp * 16 * 144);
                mma16816(acc[0][2 * jp],     a0h, bh[0], bh[1]);
                mma16816(acc[0][2 * jp + 1], a0h, bh[2], bh[3]);
                mma16816(acc[1][2 * jp],     a1h, bh[0], bh[1]);
                mma16816(acc[1][2 * jp + 1], a1h, bh[2], bh[3]);
                mma16816(acc[0][2 * jp],     a0h, bl[0], bl[1]);
                mma16816(acc[0][2 * jp + 1], a0h, bl[2], bl[3]);
                mma16816(acc[1][2 * jp],     a1h, bl[0], bl[1]);
                mma16816(acc[1][2 * jp + 1], a1h, bl[2], bl[3]);
                mma16816(acc[0][2 * jp],     a0l, bh[0], bh[1]);
                mma16816(acc[0][2 * jp + 1], a0l, bh[2], bh[3]);
                mma16816(acc[1][2 * jp],     a1l, bh[0], bh[1]);
                mma16816(acc[1][2 * jp + 1], a1l, bh[2], bh[3]);
            }
        }
        __syncthreads();
        if (kt + 2 < 8) { load_stage(s, kt + 2); CP_COMMIT(); }
    }

    if (gam) {
        // ---- fused per-row LayerNorm + *lnsc -> fp16 hi ----------------------
        float* redS = (float*)smp;          // [2][128]
        float* redQ = redS + 256;           // [2][128]
        float sum[2][2], ssq[2][2];
#pragma unroll
        for (int m = 0; m < 2; m++)
#pragma unroll
            for (int i = 0; i < 2; i++) {
                float s_ = 0.f, q_ = 0.f;
#pragma unroll
                for (int j = 0; j < 4; j++) {
                    float a0 = acc[m][j][2 * i], a1 = acc[m][j][2 * i + 1];
                    s_ += a0 + a1;
                    q_ += a0 * a0 + a1 * a1;
                }
                sum[m][i] = s_; ssq[m][i] = q_;
            }
#pragma unroll
        for (int off = 1; off <= 2; off <<= 1)
#pragma unroll
            for (int m = 0; m < 2; m++)
#pragma unroll
                for (int i = 0; i < 2; i++) {
                    sum[m][i] += __shfl_xor_sync(0xffffffffu, sum[m][i], off);
                    ssq[m][i] += __shfl_xor_sync(0xffffffffu, ssq[m][i], off);
                }
        if ((lane & 3) == 0) {
#pragma unroll
            for (int m = 0; m < 2; m++)
#pragma unroll
                for (int i = 0; i < 2; i++) {
                    int row = wr * 32 + m * 16 + i * 8 + (lane >> 2);
                    redS[wc * 128 + row] = sum[m][i];
                    redQ[wc * 128 + row] = ssq[m][i];
                }
        }
        __syncthreads();
#pragma unroll
        for (int m = 0; m < 2; m++)
#pragma unroll
            for (int i = 0; i < 2; i++) {
                const int row = wr * 32 + m * 16 + i * 8 + (lane >> 2);
                const float s_ = redS[row] + redS[128 + row];
                const float q_ = redQ[row] + redQ[128 + row];
                const float mean = s_ * (1.f / 64.f);
                const float var  = q_ * (1.f / 64.f) - mean * mean;
                const float rs   = rsqrtf(var + 1e-5f);
                const int gr = row0 + row;
#pragma unroll
                for (int j = 0; j < 4; j++) {
                    const int cl = wc * 32 + j * 8 + (lane & 3) * 2;
                    float v0 = ((acc[m][j][2 * i]     - mean) * rs * gam[cl]     + bet[cl])     * lnsc;
                    float v1 = ((acc[m][j][2 * i + 1] - mean) * rs * gam[cl + 1] + bet[cl + 1]) * lnsc;
                    *(unsigned*)&Hh[(size_t)gr * EMB + col0 + cl] = pk2h(v0, v1);
                }
            }
        return;
    }

    // ---- plain epilogue ------------------------------------------------------
#pragma unroll
    for (int m = 0; m < 2; m++) {
#pragma unroll
        for (int j = 0; j < 4; j++) {
            const int gr = row0 + wr * 32 + m * 16 + (lane >> 2);
            const int gc = col0 + wc * 32 + j * 8 + (lane & 3) * 2;
            float b0 = 0.f, b1 = 0.f;
            if (bias) { b0 = bias[gc]; b1 = bias[gc + 1]; }
            float v00 = acc[m][j][0] + b0, v01 = acc[m][j][1] + b1;
            float v10 = acc[m][j][2] + b0, v11 = acc[m][j][3] + b1;
            if (C) {
                *(float2*)&C[(size_t)gr * EMB + gc]       = make_float2(v00, v01);
                *(float2*)&C[(size_t)(gr + 8) * EMB + gc] = make_float2(v10, v11);
            }
            if (Hh) {
                *(unsigned*)&Hh[(size_t)gr * EMB + gc]       = pk2h(v00, v01);
                *(unsigned*)&Hh[(size_t)(gr + 8) * EMB + gc] = pk2h(v10, v11);
            }
        }
    }
}

__global__ __launch_bounds__(256, 2) void proj_qkv(
    const float* __restrict__ klng, const float* __restrict__ klnb,
    const float* __restrict__ qlng, const float* __restrict__ qlnb)
{
    const float SC  = 0.21022410381342865f;                 // 512^-0.25
    const float SCQ = 0.21022410381342865f * 1.4426950408889634f;  // * log2(e)
    const int z = blockIdx.z;
    const bf16* Wh = g_wh + (size_t)z * WSZ;
    const bf16* Wl = g_wl + (size_t)z * WSZ;
    if (z == 0)
        proj_body(g_xh, g_xl, Wh, Wl, nullptr, nullptr, g_kh16, klng, klnb, SC);
    else if (z == 1)
        proj_body(g_xh, g_xl, Wh, Wl, nullptr, nullptr, g_qh16, qlng, qlnb, SCQ);
    else
        proj_body(g_xh, g_xl, Wh, Wl, nullptr, nullptr, g_vh16, nullptr, nullptr, 0.f);
}

__global__ __launch_bounds__(256, 2) void proj_out(const float* __restrict__ bias,
                                                   float* __restrict__ out)
{
    proj_body(g_oh, g_ol, g_wh + 3 * (size_t)WSZ, g_wl + 3 * (size_t)WSZ,
              bias, out, nullptr, nullptr, nullptr, 0.f);
}

// ---------------------------------------------------------------------------
// Flash attention (fp16, 1-term): 128-query tiles, 256 thr. Scores arrive in
// log2 domain (Q carries log2e); mask folded as additive -100 bias; softmax
// via ex2.approx.f16x2 whose output IS the PV A-fragment. cp.async 2-stage KV.
// smem: Q 18432 + 2 stages x {K,V} 18432 + mask 512 = 55808 B.
// ---------------------------------------------------------------------------
__global__ __launch_bounds__(256, 2) void attn_mma(const float* __restrict__ mask)
{
    extern __shared__ __align__(16) char smraw[];
    const unsigned smb = sa(smraw);
    const unsigned QH = 0, KV = 18432u, MK = 55296u;

    const int b   = blockIdx.z;
    const int h   = blockIdx.y;
    const int t0  = blockIdx.x * 128;
    const int tid = threadIdx.x;
    const int lane = tid & 31;
    const int w    = tid >> 5;

    // ---- Q load (fp16 hi) ----
#pragma unroll
    for (int i = 0; i < 4; i++) {
        int idx = tid + i * 256;
        int r = idx >> 3, c = idx & 7;
        size_t gi = (size_t)(b * TT + t0 + r) * EMB + h * DD + c * 8;
        CP_ASYNC16(smb + QH + r * 144 + c * 16, g_qh16 + gi);
    }

    auto load_kv = [&](int s, int kt) {
        const unsigned base = smb + KV + (unsigned)s * 18432u;
        const int s0 = kt * 64;
#pragma unroll
        for (int i = 0; i < 2; i++) {
            int idx = tid + i * 256;
            int r = idx >> 3, c = idx & 7;
            size_t gi = (size_t)(b * TT + s0 + r) * EMB + h * DD + c * 8;
            unsigned d = base + r * 144 + c * 16;
            CP_ASYNC16(d,         g_kh16 + gi);
            CP_ASYNC16(d + 9216u, g_vh16 + gi);
        }
        if (tid < 16)
            CP_ASYNC16(smb + MK + (unsigned)s * 256u + tid * 16,
                       mask + b * TT + s0 + tid * 4);
    };

    load_kv(0, 0); CP_COMMIT();
    load_kv(1, 1); CP_COMMIT();

    const unsigned qh_a = smb + QH + (w * 16 + (lane & 15)) * 144 + (lane >> 4) * 16;
    const unsigned koff = (((lane >> 4) << 3) + (lane & 7)) * 144 + ((lane >> 3) & 1) * 16;
    const unsigned voff = ((((lane >> 3) & 1) * 8 + (lane & 7)) * 72 + ((lane >> 4) << 3)) * 2;

    // ---- wait Q (+stage0), hoist Q fragments into registers ----
    CP_WAIT(1);
    __syncthreads();
    unsigned qhf[4][4];
#pragma unroll
    for (int kc = 0; kc < 4; kc++)
        ldsm4(qhf[kc], qh_a + kc * 32);

    float oa[8][4];
#pragma unroll
    for (int j = 0; j < 8; j++)
#pragma unroll
        for (int e = 0; e < 4; e++) oa[j][e] = 0.f;
    float l0 = 0.f, l1 = 0.f;

    const float rb0 = (mask[b * TT + t0 + w * 16 + (lane >> 2)]     > 0.f) ? 0.f : -100.f;
    const float rb1 = (mask[b * TT + t0 + w * 16 + (lane >> 2) + 8] > 0.f) ? 0.f : -100.f;

    for (int kt = 0; kt < TT / 64; kt++) {
        const int s = kt & 1;
        if (kt < TT / 64 - 1) { CP_WAIT(1); } else { CP_WAIT(0); }
        __syncthreads();

        const unsigned stb  = smb + KV + (unsigned)s * 18432u;
        const unsigned kh_a = stb + koff;
        const unsigned vh_a = stb + 9216u + voff;
        const float* mkbuf = (const float*)(smraw + MK + (unsigned)s * 256u);

        // ---- S (log2 domain) = Qh * K ----
        float sc[8][4];
#pragma unroll
        for (int j = 0; j < 8; j++)
#pragma unroll
            for (int e = 0; e < 4; e++) sc[j][e] = 0.f;

#pragma unroll
        for (int kc = 0; kc < 4; kc++) {
#pragma unroll
            for (int jp = 0; jp < 4; jp++) {
                unsigned bh[4];
                ldsm4(bh, kh_a + kc * 32 + jp * 16 * 144);
                mma16816h(sc[2 * jp],     qhf[kc], bh[0], bh[1]);
                mma16816h(sc[2 * jp + 1], qhf[kc], bh[2], bh[3]);
            }
        }

        // ---- mask bias + packed ex2 -> P fragments ----
        unsigned p01[8], p23[8];
#pragma unroll
        for (int j = 0; j < 8; j++) {
            int col = j * 8 + (lane & 3) * 2;
            float cb0 = (mkbuf[col]     > 0.f) ? 0.f : -100.f;
            float cb1 = (mkbuf[col + 1] > 0.f) ? 0.f : -100.f;
            p01[j] = ex2h2(pk2h(sc[j][0] + rb0 + cb0, sc[j][1] + rb0 + cb1));
            p23[j] = ex2h2(pk2h(sc[j][2] + rb1 + cb0, sc[j][3] + rb1 + cb1));
            float2 f0 = h22f2(p01[j]);
            float2 f1 = h22f2(p23[j]);
            l0 += f0.x + f0.y;
            l1 += f1.x + f1.y;
        }

        // ---- O += P * V ----
#pragma unroll
        for (int kc = 0; kc < 4; kc++) {
            unsigned a[4];
            a[0] = p01[2 * kc];     a[1] = p23[2 * kc];
            a[2] = p01[2 * kc + 1]; a[3] = p23[2 * kc + 1];
#pragma unroll
            for (int jp = 0; jp < 4; jp++) {
                unsigned bv[4];
                ldsm4t(bv, vh_a + kc * 16 * 144 + jp * 32);
                mma16816h(oa[2 * jp],     a, bv[0], bv[1]);
                mma16816h(oa[2 * jp + 1], a, bv[2], bv[3]);
            }
        }

        __syncthreads();
        if (kt + 2 < TT / 64) { load_kv(s, kt + 2); CP_COMMIT(); }
    }

    // ---- epilogue: reduce l across quad, O / l -> bf16 split ----
    l0 += __shfl_xor_sync(0xffffffffu, l0, 1);
    l0 += __shfl_xor_sync(0xffffffffu, l0, 2);
    l1 += __shfl_xor_sync(0xffffffffu, l1, 1);
    l1 += __shfl_xor_sync(0xffffffffu, l1, 2);
    const float inv0 = 1.f / l0;
    const float inv1 = 1.f / l1;
    const int gr0 = b * TT + t0 + w * 16 + (lane >> 2);
#pragma unroll
    for (int j = 0; j < 8; j++) {
        const int col = h * DD + j * 8 + (lane & 3) * 2;
        float v00 = oa[j][0] * inv0, v01 = oa[j][1] * inv0;
        float v10 = oa[j][2] * inv1, v11 = oa[j][3] * inv1;
        unsigned h0 = pk2(v00, v01);
        unsigned h1 = pk2(v10, v11);
        *(unsigned*)&g_oh[(size_t)gr0 * EMB + col]       = h0;
        *(unsigned*)&g_oh[(size_t)(gr0 + 8) * EMB + col] = h1;
        float x, y;
        unpk2(h0, x, y);
        *(unsigned*)&g_ol[(size_t)gr0 * EMB + col] = pk2(v00 - x, v01 - y);
        unpk2(h1, x, y);
        *(unsigned*)&g_ol[(size_t)(gr0 + 8) * EMB + col] = pk2(v10 - x, v11 - y);
    }
}

// ---------------------------------------------------------------------------
extern "C" void kernel_launch(void* const* d_in, const int* in_sizes, int n_in,
                              void* d_out, int out_size)
{
    const float* x    = (const float*)d_in[0];
    const float* mask = (const float*)d_in[1];
    const float* Wk   = (const float*)d_in[2];
    const float* Wq   = (const float*)d_in[3];
    const float* Wv   = (const float*)d_in[4];
    const float* Wu   = (const float*)d_in[5];
    const float* bu   = (const float*)d_in[6];
    const float* klng = (const float*)d_in[7];
    const float* klnb = (const float*)d_in[8];
    const float* qlng = (const float*)d_in[9];
    const float* qlnb = (const float*)d_in[10];
    float* out = (float*)d_out;

    split_x<<<(ME * EMB / 4 + 255) / 256, 256>>>(x, ME * EMB);
    split_w<<<dim3((WSZ / 4 + 255) / 256, 4), 256>>>(Wk, Wq, Wv, Wu);

    const int PSMEM = 2 * 55296;  // 110592
    cudaFuncSetAttribute(proj_qkv,
                         cudaFuncAttributeMaxDynamicSharedMemorySize, PSMEM);
    cudaFuncSetAttribute(proj_out,
                         cudaFuncAttributeMaxDynamicSharedMemorySize, PSMEM);
    proj_qkv<<<dim3(ME / 128, EMB / 64, 3), 256, PSMEM>>>(klng, klnb, qlng, qlnb);

    const int ASMEM = 55296 + 512;  // 55808
    cudaFuncSetAttribute(attn_mma,
                         cudaFuncAttributeMaxDynamicSharedMemorySize, ASMEM);
    attn_mma<<<dim3(TT / 128, HH, BB), 256, ASMEM>>>(mask);

    proj_out<<<dim3(ME / 128, EMB / 64, 1), 256, PSMEM>>>(bu, out);
}

// round 10
// speedup vs baseline: 2.5937x; 1.1749x over previous
#include <cuda_runtime.h>
#include <cuda_fp16.h>
#include <cstdint>

#define ME   4096   // B*T rows
#define EMB  512
#define TT   2048
#define BB   2
#define HH   8
#define DD   64
#define WSZ  (EMB * EMB)

// ---- scratch (device globals; no cudaMalloc allowed) -----------------------
__device__ __align__(16) __half g_xh[ME * EMB];
__device__ __align__(16) __half g_xl[ME * EMB];
__device__ __align__(16) __half g_wh[4 * WSZ];      // single fp16 weights
__device__ __align__(16) __half g_qh[ME * EMB];     // carries SC*log2e
__device__ __align__(16) __half g_kh[ME * EMB];     // carries SC
__device__ __align__(16) __half g_vh[ME * EMB];
__device__ __align__(16) __half g_oh[ME * EMB];
__device__ __align__(16) __half g_ol[ME * EMB];

// ---- helpers ----------------------------------------------------------------
__device__ __forceinline__ unsigned sa(const void* p) {
    return (unsigned)__cvta_generic_to_shared(p);
}
__device__ __forceinline__ void ldsm4(unsigned r[4], unsigned addr) {
    asm volatile("ldmatrix.sync.aligned.m8n8.x4.shared.b16 {%0,%1,%2,%3}, [%4];"
                 : "=r"(r[0]), "=r"(r[1]), "=r"(r[2]), "=r"(r[3]) : "r"(addr));
}
__device__ __forceinline__ void ldsm4t(unsigned r[4], unsigned addr) {
    asm volatile("ldmatrix.sync.aligned.m8n8.x4.trans.shared.b16 {%0,%1,%2,%3}, [%4];"
                 : "=r"(r[0]), "=r"(r[1]), "=r"(r[2]), "=r"(r[3]) : "r"(addr));
}
__device__ __forceinline__ void mma16816h(float d[4], const unsigned a[4],
                                          unsigned b0, unsigned b1) {
    asm volatile(
        "mma.sync.aligned.m16n8k16.row.col.f32.f16.f16.f32 "
        "{%0,%1,%2,%3}, {%4,%5,%6,%7}, {%8,%9}, {%0,%1,%2,%3};"
        : "+f"(d[0]), "+f"(d[1]), "+f"(d[2]), "+f"(d[3])
        : "r"(a[0]), "r"(a[1]), "r"(a[2]), "r"(a[3]), "r"(b0), "r"(b1));
}
__device__ __forceinline__ unsigned pk2h(float lo, float hi) {    // f16x2
    __half2 t = __floats2half2_rn(lo, hi);
    return *reinterpret_cast<unsigned*>(&t);
}
__device__ __forceinline__ float2 h22f2(unsigned u) {
    __half2 t = *reinterpret_cast<__half2*>(&u);
    return __half22float2(t);
}
__device__ __forceinline__ unsigned ex2h2(unsigned a) {           // 2^x on f16x2
    unsigned r;
    asm("ex2.approx.f16x2 %0, %1;" : "=r"(r) : "r"(a));
    return r;
}

#define CP_ASYNC16(dst, src) \
    asm volatile("cp.async.cg.shared.global [%0], [%1], 16;" :: "r"(dst), "l"(src))
#define CP_COMMIT() asm volatile("cp.async.commit_group;" ::: "memory")
#define CP_WAIT(n)  asm volatile("cp.async.wait_group %0;" :: "n"(n) : "memory")

// ---- split fp32 -> (hi, lo) fp16 ---------------------------------------------
__global__ void split_x(const float* __restrict__ in, int n)
{
    int i = (blockIdx.x * blockDim.x + threadIdx.x) * 4;
    if (i >= n) return;
    float4 v = *(const float4*)&in[i];
    __half2 h0 = __floats2half2_rn(v.x, v.y);
    __half2 h1 = __floats2half2_rn(v.z, v.w);
    *(__half2*)&g_xh[i]     = h0;
    *(__half2*)&g_xh[i + 2] = h1;
    float2 f0 = __half22float2(h0);
    float2 f1 = __half22float2(h1);
    *(__half2*)&g_xl[i]     = __floats2half2_rn(v.x - f0.x, v.y - f0.y);
    *(__half2*)&g_xl[i + 2] = __floats2half2_rn(v.z - f1.x, v.w - f1.y);
}

// single fp16 weights
__global__ void split_w(const float* __restrict__ w0, const float* __restrict__ w1,
                        const float* __restrict__ w2, const float* __restrict__ w3)
{
    const int z = blockIdx.y;
    const float* src = (z == 0) ? w0 : (z == 1) ? w1 : (z == 2) ? w2 : w3;
    int i = (blockIdx.x * blockDim.x + threadIdx.x) * 4;
    if (i >= WSZ) return;
    float4 v = *(const float4*)&src[i];
    __half* dst = g_wh + (size_t)z * WSZ + i;
    *(__half2*)&dst[0] = __floats2half2_rn(v.x, v.y);
    *(__half2*)&dst[2] = __floats2half2_rn(v.z, v.w);
}

// ---------------------------------------------------------------------------
// fp16 2-term GEMM body: C = (Ah+Al)[M,512] @ Wh[N,512]^T (+bias).
// tile 128x64, 256 thr, 8 warps (4 Mrow x 2 Ncol), cp.async 2-stage.
// Epilogues: fp32 (+bias); or fp16 hi out (optionally +lo residual), optionally
// with fused per-(token,head) LayerNorm (tile == one head) scaled by lnsc.
// smem/stage: Ah 18432 + Al 18432 + Wh 9216 = 46080; 2 stages = 92160 B.
// ---------------------------------------------------------------------------
__device__ __forceinline__ void proj_body(
    const __half* __restrict__ Ah, const __half* __restrict__ Al,
    const __half* __restrict__ Wh,
    const float* __restrict__ bias, float* __restrict__ C,
    __half* __restrict__ Hh, __half* __restrict__ Hl,
    const float* __restrict__ gam, const float* __restrict__ bet, float lnsc)
{
    extern __shared__ __align__(16) char smp[];
    const unsigned smb = sa(smp);

    const int tid  = threadIdx.x;
    const int lane = tid & 31;
    const int w    = tid >> 5;
    const int wr   = w & 3;
    const int wc   = w >> 2;
    const int row0 = blockIdx.x * 128;
    const int col0 = blockIdx.y * 64;

    const int lr  = tid >> 3;
    const int lcb = (tid & 7) * 16;
    const int lce = (tid & 7) * 8;

    float acc[2][4][4];
#pragma unroll
    for (int m = 0; m < 2; m++)
#pragma unroll
        for (int j = 0; j < 4; j++)
#pragma unroll
            for (int e = 0; e < 4; e++) acc[m][j][e] = 0.f;

    auto load_stage = [&](int s, int kt) {
        const unsigned st = smb + (unsigned)s * 46080u;
#pragma unroll
        for (int i = 0; i < 4; i++) {
            int r = lr + i * 32;
            unsigned dst = st + r * 144 + lcb;
            CP_ASYNC16(dst, Ah + (size_t)(row0 + r) * EMB + kt * 64 + lce);
            CP_ASYNC16(dst + 18432u, Al + (size_t)(row0 + r) * EMB + kt * 64 + lce);
        }
#pragma unroll
        for (int i = 0; i < 2; i++) {
            int r = lr + i * 32;
            CP_ASYNC16(st + 36864u + r * 144 + lcb,
                       Wh + (size_t)(col0 + r) * EMB + kt * 64 + lce);
        }
    };

    const unsigned aoff = (wr * 32 + (lane & 15)) * 144 + (lane >> 4) * 16;
    const unsigned boff = 36864u +
        (wc * 32 + ((lane >> 4) << 3) + (lane & 7)) * 144 + (((lane >> 3) & 1) * 16);

    load_stage(0, 0); CP_COMMIT();
    load_stage(1, 1); CP_COMMIT();

    for (int kt = 0; kt < 8; kt++) {
        const int s = kt & 1;
        if (kt < 7) { CP_WAIT(1); } else { CP_WAIT(0); }
        __syncthreads();
        const unsigned st = smb + (unsigned)s * 46080u;
        const unsigned aAh = st + aoff;
        const unsigned aWh = st + boff;
#pragma unroll
        for (int kc = 0; kc < 4; kc++) {
            unsigned a0h[4], a1h[4], a0l[4], a1l[4];
            ldsm4(a0h, aAh + kc * 32);
            ldsm4(a1h, aAh + kc * 32 + 16 * 144);
            ldsm4(a0l, aAh + 18432u + kc * 32);
            ldsm4(a1l, aAh + 18432u + kc * 32 + 16 * 144);
#pragma unroll
            for (int jp = 0; jp < 2; jp++) {
                unsigned bh[4];
                ldsm4(bh, aWh + kc * 32 + jp * 16 * 144);
                mma16816h(acc[0][2 * jp],     a0h, bh[0], bh[1]);
                mma16816h(acc[0][2 * jp + 1], a0h, bh[2], bh[3]);
                mma16816h(acc[1][2 * jp],     a1h, bh[0], bh[1]);
                mma16816h(acc[1][2 * jp + 1], a1h, bh[2], bh[3]);
                mma16816h(acc[0][2 * jp],     a0l, bh[0], bh[1]);
                mma16816h(acc[0][2 * jp + 1], a0l, bh[2], bh[3]);
                mma16816h(acc[1][2 * jp],     a1l, bh[0], bh[1]);
                mma16816h(acc[1][2 * jp + 1], a1l, bh[2], bh[3]);
            }
        }
        __syncthreads();
        if (kt + 2 < 8) { load_stage(s, kt + 2); CP_COMMIT(); }
    }

    if (gam) {
        // ---- fused per-row LayerNorm + *lnsc -> fp16 hi ----------------------
        float* redS = (float*)smp;          // [2][128]
        float* redQ = redS + 256;           // [2][128]
        float sum[2][2], ssq[2][2];
#pragma unroll
        for (int m = 0; m < 2; m++)
#pragma unroll
            for (int i = 0; i < 2; i++) {
                float s_ = 0.f, q_ = 0.f;
#pragma unroll
                for (int j = 0; j < 4; j++) {
                    float a0 = acc[m][j][2 * i], a1 = acc[m][j][2 * i + 1];
                    s_ += a0 + a1;
                    q_ += a0 * a0 + a1 * a1;
                }
                sum[m][i] = s_; ssq[m][i] = q_;
            }
#pragma unroll
        for (int off = 1; off <= 2; off <<= 1)
#pragma unroll
            for (int m = 0; m < 2; m++)
#pragma unroll
                for (int i = 0; i < 2; i++) {
                    sum[m][i] += __shfl_xor_sync(0xffffffffu, sum[m][i], off);
                    ssq[m][i] += __shfl_xor_sync(0xffffffffu, ssq[m][i], off);
                }
        if ((lane & 3) == 0) {
#pragma unroll
            for (int m = 0; m < 2; m++)
#pragma unroll
                for (int i = 0; i < 2; i++) {
                    int row = wr * 32 + m * 16 + i * 8 + (lane >> 2);
                    redS[wc * 128 + row] = sum[m][i];
                    redQ[wc * 128 + row] = ssq[m][i];
                }
        }
        __syncthreads();
#pragma unroll
        for (int m = 0; m < 2; m++)
#pragma unroll
            for (int i = 0; i < 2; i++) {
                const int row = wr * 32 + m * 16 + i * 8 + (lane >> 2);
                const float s_ = redS[row] + redS[128 + row];
                const float q_ = redQ[row] + redQ[128 + row];
                const float mean = s_ * (1.f / 64.f);
                const float var  = q_ * (1.f / 64.f) - mean * mean;
                const float rs   = rsqrtf(var + 1e-5f);
                const int gr = row0 + row;
#pragma unroll
                for (int j = 0; j < 4; j++) {
                    const int cl = wc * 32 + j * 8 + (lane & 3) * 2;
                    float v0 = ((acc[m][j][2 * i]     - mean) * rs * gam[cl]     + bet[cl])     * lnsc;
                    float v1 = ((acc[m][j][2 * i + 1] - mean) * rs * gam[cl + 1] + bet[cl + 1]) * lnsc;
                    *(unsigned*)&Hh[(size_t)gr * EMB + col0 + cl] = pk2h(v0, v1);
                }
            }
        return;
    }

    // ---- plain epilogue ------------------------------------------------------
#pragma unroll
    for (int m = 0; m < 2; m++) {
#pragma unroll
        for (int j = 0; j < 4; j++) {
            const int gr = row0 + wr * 32 + m * 16 + (lane >> 2);
            const int gc = col0 + wc * 32 + j * 8 + (lane & 3) * 2;
            float b0 = 0.f, b1 = 0.f;
            if (bias) { b0 = bias[gc]; b1 = bias[gc + 1]; }
            float v00 = acc[m][j][0] + b0, v01 = acc[m][j][1] + b1;
            float v10 = acc[m][j][2] + b0, v11 = acc[m][j][3] + b1;
            if (C) {
                *(float2*)&C[(size_t)gr * EMB + gc]       = make_float2(v00, v01);
                *(float2*)&C[(size_t)(gr + 8) * EMB + gc] = make_float2(v10, v11);
            }
            if (Hh) {
                unsigned h0 = pk2h(v00, v01);
                unsigned h1 = pk2h(v10, v11);
                *(unsigned*)&Hh[(size_t)gr * EMB + gc]       = h0;
                *(unsigned*)&Hh[(size_t)(gr + 8) * EMB + gc] = h1;
                if (Hl) {
                    float2 f0 = h22f2(h0);
                    float2 f1 = h22f2(h1);
                    *(unsigned*)&Hl[(size_t)gr * EMB + gc] =
                        pk2h(v00 - f0.x, v01 - f0.y);
                    *(unsigned*)&Hl[(size_t)(gr + 8) * EMB + gc] =
                        pk2h(v10 - f1.x, v11 - f1.y);
                }
            }
        }
    }
}

__global__ __launch_bounds__(256, 2) void proj_qkv(
    const float* __restrict__ klng, const float* __restrict__ klnb,
    const float* __restrict__ qlng, const float* __restrict__ qlnb)
{
    const float SC  = 0.21022410381342865f;                        // 512^-0.25
    const float SCQ = 0.21022410381342865f * 1.4426950408889634f;  // * log2(e)
    const int z = blockIdx.z;
    const __half* Wh = g_wh + (size_t)z * WSZ;
    if (z == 0)
        proj_body(g_xh, g_xl, Wh, nullptr, nullptr, g_kh, nullptr, klng, klnb, SC);
    else if (z == 1)
        proj_body(g_xh, g_xl, Wh, nullptr, nullptr, g_qh, nullptr, qlng, qlnb, SCQ);
    else
        proj_body(g_xh, g_xl, Wh, nullptr, nullptr, g_vh, nullptr, nullptr, nullptr, 0.f);
}

__global__ __launch_bounds__(256, 2) void proj_out(const float* __restrict__ bias,
                                                   float* __restrict__ out)
{
    proj_body(g_oh, g_ol, g_wh + 3 * (size_t)WSZ,
              bias, out, nullptr, nullptr, nullptr, nullptr, 0.f);
}

// ---------------------------------------------------------------------------
// Flash attention (fp16, 1-term): 128-query tiles, 256 thr. Scores in log2
// domain (Q carries log2e); mask folded as additive -100 bias; softmax via
// ex2.approx.f16x2 whose output IS the PV A-fragment. cp.async 2-stage KV.
// smem: Q 18432 + 2 stages x {K,V} 18432 + mask 512 = 55808 B.
// ---------------------------------------------------------------------------
__global__ __launch_bounds__(256, 2) void attn_mma(const float* __restrict__ mask)
{
    extern __shared__ __align__(16) char smraw[];
    const unsigned smb = sa(smraw);
    const unsigned QH = 0, KV = 18432u, MK = 55296u;

    const int b   = blockIdx.z;
    const int h   = blockIdx.y;
    const int t0  = blockIdx.x * 128;
    const int tid = threadIdx.x;
    const int lane = tid & 31;
    const int w    = tid >> 5;

    // ---- Q load (fp16 hi) ----
#pragma unroll
    for (int i = 0; i < 4; i++) {
        int idx = tid + i * 256;
        int r = idx >> 3, c = idx & 7;
        size_t gi = (size_t)(b * TT + t0 + r) * EMB + h * DD + c * 8;
        CP_ASYNC16(smb + QH + r * 144 + c * 16, g_qh + gi);
    }

    auto load_kv = [&](int s, int kt) {
        const unsigned base = smb + KV + (unsigned)s * 18432u;
        const int s0 = kt * 64;
#pragma unroll
        for (int i = 0; i < 2; i++) {
            int idx = tid + i * 256;
            int r = idx >> 3, c = idx & 7;
            size_t gi = (size_t)(b * TT + s0 + r) * EMB + h * DD + c * 8;
            unsigned d = base + r * 144 + c * 16;
            CP_ASYNC16(d,         g_kh + gi);
            CP_ASYNC16(d + 9216u, g_vh + gi);
        }
        if (tid < 16)
            CP_ASYNC16(smb + MK + (unsigned)s * 256u + tid * 16,
                       mask + b * TT + s0 + tid * 4);
    };

    load_kv(0, 0); CP_COMMIT();
    load_kv(1, 1); CP_COMMIT();

    const unsigned qh_a = smb + QH + (w * 16 + (lane & 15)) * 144 + (lane >> 4) * 16;
    const unsigned koff = (((lane >> 4) << 3) + (lane & 7)) * 144 + ((lane >> 3) & 1) * 16;
    const unsigned voff = ((((lane >> 3) & 1) * 8 + (lane & 7)) * 72 + ((lane >> 4) << 3)) * 2;

    // ---- wait Q (+stage0), hoist Q fragments into registers ----
    CP_WAIT(1);
    __syncthreads();
    unsigned qhf[4][4];
#pragma unroll
    for (int kc = 0; kc < 4; kc++)
        ldsm4(qhf[kc], qh_a + kc * 32);

    float oa[8][4];
#pragma unroll
    for (int j = 0; j < 8; j++)
#pragma unroll
        for (int e = 0; e < 4; e++) oa[j][e] = 0.f;
    float l0 = 0.f, l1 = 0.f;

    const float rb0 = (mask[b * TT + t0 + w * 16 + (lane >> 2)]     > 0.f) ? 0.f : -100.f;
    const float rb1 = (mask[b * TT + t0 + w * 16 + (lane >> 2) + 8] > 0.f) ? 0.f : -100.f;

    for (int kt = 0; kt < TT / 64; kt++) {
        const int s = kt & 1;
        if (kt < TT / 64 - 1) { CP_WAIT(1); } else { CP_WAIT(0); }
        __syncthreads();

        const unsigned stb  = smb + KV + (unsigned)s * 18432u;
        const unsigned kh_a = stb + koff;
        const unsigned vh_a = stb + 9216u + voff;
        const float* mkbuf = (const float*)(smraw + MK + (unsigned)s * 256u);

        // ---- S (log2 domain) = Qh * K ----
        float sc[8][4];
#pragma unroll
        for (int j = 0; j < 8; j++)
#pragma unroll
            for (int e = 0; e < 4; e++) sc[j][e] = 0.f;

#pragma unroll
        for (int kc = 0; kc < 4; kc++) {
#pragma unroll
            for (int jp = 0; jp < 4; jp++) {
                unsigned bh[4];
                ldsm4(bh, kh_a + kc * 32 + jp * 16 * 144);
                mma16816h(sc[2 * jp],     qhf[kc], bh[0], bh[1]);
                mma16816h(sc[2 * jp + 1], qhf[kc], bh[2], bh[3]);
            }
        }

        // ---- mask bias + packed ex2 -> P fragments ----
        unsigned p01[8], p23[8];
#pragma unroll
        for (int j = 0; j < 8; j++) {
            int col = j * 8 + (lane & 3) * 2;
            float cb0 = (mkbuf[col]     > 0.f) ? 0.f : -100.f;
            float cb1 = (mkbuf[col + 1] > 0.f) ? 0.f : -100.f;
            p01[j] = ex2h2(pk2h(sc[j][0] + rb0 + cb0, sc[j][1] + rb0 + cb1));
            p23[j] = ex2h2(pk2h(sc[j][2] + rb1 + cb0, sc[j][3] + rb1 + cb1));
            float2 f0 = h22f2(p01[j]);
            float2 f1 = h22f2(p23[j]);
            l0 += f0.x + f0.y;
            l1 += f1.x + f1.y;
        }

        // ---- O += P * V ----
#pragma unroll
        for (int kc = 0; kc < 4; kc++) {
            unsigned a[4];
            a[0] = p01[2 * kc];     a[1] = p23[2 * kc];
            a[2] = p01[2 * kc + 1]; a[3] = p23[2 * kc + 1];
#pragma unroll
            for (int jp = 0; jp < 4; jp++) {
                unsigned bv[4];
                ldsm4t(bv, vh_a + kc * 16 * 144 + jp * 32);
                mma16816h(oa[2 * jp],     a, bv[0], bv[1]);
                mma16816h(oa[2 * jp + 1], a, bv[2], bv[3]);
            }
        }

        __syncthreads();
        if (kt + 2 < TT / 64) { load_kv(s, kt + 2); CP_COMMIT(); }
    }

    // ---- epilogue: reduce l across quad, O / l -> fp16 hi/lo ----
    l0 += __shfl_xor_sync(0xffffffffu, l0, 1);
    l0 += __shfl_xor_sync(0xffffffffu, l0, 2);
    l1 += __shfl_xor_sync(0xffffffffu, l1, 1);
    l1 += __shfl_xor_sync(0xffffffffu, l1, 2);
    const float inv0 = 1.f / l0;
    const float inv1 = 1.f / l1;
    const int gr0 = b * TT + t0 + w * 16 + (lane >> 2);
#pragma unroll
    for (int j = 0; j < 8; j++) {
        const int col = h * DD + j * 8 + (lane & 3) * 2;
        float v00 = oa[j][0] * inv0, v01 = oa[j][1] * inv0;
        float v10 = oa[j][2] * inv1, v11 = oa[j][3] * inv1;
        unsigned h0 = pk2h(v00, v01);
        unsigned h1 = pk2h(v10, v11);
        *(unsigned*)&g_oh[(size_t)gr0 * EMB + col]       = h0;
        *(unsigned*)&g_oh[(size_t)(gr0 + 8) * EMB + col] = h1;
        float2 f0 = h22f2(h0);
        float2 f1 = h22f2(h1);
        *(unsigned*)&g_ol[(size_t)gr0 * EMB + col]       = pk2h(v00 - f0.x, v01 - f0.y);
        *(unsigned*)&g_ol[(size_t)(gr0 + 8) * EMB + col] = pk2h(v10 - f1.x, v11 - f1.y);
    }
}

// ---------------------------------------------------------------------------
extern "C" void kernel_launch(void* const* d_in, const int* in_sizes, int n_in,
                              void* d_out, int out_size)
{
    const float* x    = (const float*)d_in[0];
    const float* mask = (const float*)d_in[1];
    const float* Wk   = (const float*)d_in[2];
    const float* Wq   = (const float*)d_in[3];
    const float* Wv   = (const float*)d_in[4];
    const float* Wu   = (const float*)d_in[5];
    const float* bu   = (const float*)d_in[6];
    const float* klng = (const float*)d_in[7];
    const float* klnb = (const float*)d_in[8];
    const float* qlng = (const float*)d_in[9];
    const float* qlnb = (const float*)d_in[10];
    float* out = (float*)d_out;

    split_x<<<(ME * EMB / 4 + 255) / 256, 256>>>(x, ME * EMB);
    split_w<<<dim3((WSZ / 4 + 255) / 256, 4), 256>>>(Wk, Wq, Wv, Wu);

    const int PSMEM = 2 * 46080;  // 92160
    cudaFuncSetAttribute(proj_qkv,
                         cudaFuncAttributeMaxDynamicSharedMemorySize, PSMEM);
    cudaFuncSetAttribute(proj_out,
                         cudaFuncAttributeMaxDynamicSharedMemorySize, PSMEM);
    proj_qkv<<<dim3(ME / 128, EMB / 64, 3), 256, PSMEM>>>(klng, klnb, qlng, qlnb);

    const int ASMEM = 55296 + 512;  // 55808
    cudaFuncSetAttribute(attn_mma,
                         cudaFuncAttributeMaxDynamicSharedMemorySize, ASMEM);
    attn_mma<<<dim3(TT / 128, HH, BB), 256, ASMEM>>>(mask);

    proj_out<<<dim3(ME / 128, EMB / 64, 1), 256, PSMEM>>>(bu, out);
}

// round 11
// speedup vs baseline: 3.0676x; 1.1827x over previous
#include <cuda_runtime.h>
#include <cuda_fp16.h>
#include <cstdint>

#define ME   4096   // B*T rows
#define EMB  512
#define TT   2048
#define BB   2
#define HH   8
#define DD   64
#define WSZ  (EMB * EMB)

// ---- scratch (device globals; no cudaMalloc allowed) -----------------------
__device__ __align__(16) __half g_xh[ME * EMB];
__device__ __align__(16) __half g_xl[ME * EMB];
__device__ __align__(16) __half g_wh[4 * WSZ];      // single fp16 weights
__device__ __align__(16) __half g_qh[ME * EMB];     // carries SC*log2e
__device__ __align__(16) __half g_kh[ME * EMB];     // carries SC
__device__ __align__(16) __half g_vh[ME * EMB];
__device__ __align__(16) __half g_oh[ME * EMB];

// ---- helpers ----------------------------------------------------------------
__device__ __forceinline__ unsigned sa(const void* p) {
    return (unsigned)__cvta_generic_to_shared(p);
}
__device__ __forceinline__ void ldsm4(unsigned r[4], unsigned addr) {
    asm volatile("ldmatrix.sync.aligned.m8n8.x4.shared.b16 {%0,%1,%2,%3}, [%4];"
                 : "=r"(r[0]), "=r"(r[1]), "=r"(r[2]), "=r"(r[3]) : "r"(addr));
}
__device__ __forceinline__ void ldsm4t(unsigned r[4], unsigned addr) {
    asm volatile("ldmatrix.sync.aligned.m8n8.x4.trans.shared.b16 {%0,%1,%2,%3}, [%4];"
                 : "=r"(r[0]), "=r"(r[1]), "=r"(r[2]), "=r"(r[3]) : "r"(addr));
}
__device__ __forceinline__ void mma16816h(float d[4], const unsigned a[4],
                                          unsigned b0, unsigned b1) {
    asm volatile(
        "mma.sync.aligned.m16n8k16.row.col.f32.f16.f16.f32 "
        "{%0,%1,%2,%3}, {%4,%5,%6,%7}, {%8,%9}, {%0,%1,%2,%3};"
        : "+f"(d[0]), "+f"(d[1]), "+f"(d[2]), "+f"(d[3])
        : "r"(a[0]), "r"(a[1]), "r"(a[2]), "r"(a[3]), "r"(b0), "r"(b1));
}
__device__ __forceinline__ unsigned pk2h(float lo, float hi) {    // f16x2
    __half2 t = __floats2half2_rn(lo, hi);
    return *reinterpret_cast<unsigned*>(&t);
}
__device__ __forceinline__ float2 h22f2(unsigned u) {
    __half2 t = *reinterpret_cast<__half2*>(&u);
    return __half22float2(t);
}
__device__ __forceinline__ unsigned ex2h2(unsigned a) {           // 2^x on f16x2
    unsigned r;
    asm("ex2.approx.f16x2 %0, %1;" : "=r"(r) : "r"(a));
    return r;
}

#define CP_ASYNC16(dst, src) \
    asm volatile("cp.async.cg.shared.global [%0], [%1], 16;" :: "r"(dst), "l"(src))
#define CP_COMMIT() asm volatile("cp.async.commit_group;" ::: "memory")
#define CP_WAIT(n)  asm volatile("cp.async.wait_group %0;" :: "n"(n) : "memory")

// ---- fused split: x -> fp16 hi/lo, weights -> single fp16 --------------------
__global__ void split_all(const float* __restrict__ x,
                          const float* __restrict__ w0, const float* __restrict__ w1,
                          const float* __restrict__ w2, const float* __restrict__ w3)
{
    int i = (blockIdx.x * blockDim.x + threadIdx.x) * 4;
    if (i < ME * EMB) {
        float4 v = *(const float4*)&x[i];
        __half2 h0 = __floats2half2_rn(v.x, v.y);
        __half2 h1 = __floats2half2_rn(v.z, v.w);
        *(__half2*)&g_xh[i]     = h0;
        *(__half2*)&g_xh[i + 2] = h1;
        float2 f0 = __half22float2(h0);
        float2 f1 = __half22float2(h1);
        *(__half2*)&g_xl[i]     = __floats2half2_rn(v.x - f0.x, v.y - f0.y);
        *(__half2*)&g_xl[i + 2] = __floats2half2_rn(v.z - f1.x, v.w - f1.y);
    } else {
        int j = i - ME * EMB;
        if (j >= 4 * WSZ) return;
        int z = j / WSZ, k = j % WSZ;
        const float* src = (z == 0) ? w0 : (z == 1) ? w1 : (z == 2) ? w2 : w3;
        float4 v = *(const float4*)&src[k];
        __half* dst = g_wh + (size_t)z * WSZ + k;
        *(__half2*)&dst[0] = __floats2half2_rn(v.x, v.y);
        *(__half2*)&dst[2] = __floats2half2_rn(v.z, v.w);
    }
}

// ---------------------------------------------------------------------------
// fp16 GEMM body: C = (Ah[+Al])[M,512] @ Wh[N,512]^T (+bias). Al==nullptr ->
// 1-term. tile 128x64, 256 thr, 8 warps (4 Mrow x 2 Ncol), cp.async 2-stage.
// Epilogues: fp32 (+bias); or fp16 hi out, optionally with fused per-(token,
// head) LayerNorm (tile == one head) scaled by lnsc.
// ---------------------------------------------------------------------------
__device__ __forceinline__ void proj_body(
    const __half* __restrict__ Ah, const __half* __restrict__ Al,
    const __half* __restrict__ Wh,
    const float* __restrict__ bias, float* __restrict__ C,
    __half* __restrict__ Hh,
    const float* __restrict__ gam, const float* __restrict__ bet, float lnsc)
{
    extern __shared__ __align__(16) char smp[];
    const unsigned smb = sa(smp);

    const int tid  = threadIdx.x;
    const int lane = tid & 31;
    const int w    = tid >> 5;
    const int wr   = w & 3;
    const int wc   = w >> 2;
    const int row0 = blockIdx.x * 128;
    const int col0 = blockIdx.y * 64;

    const int lr  = tid >> 3;
    const int lcb = (tid & 7) * 16;
    const int lce = (tid & 7) * 8;

    float acc[2][4][4];
#pragma unroll
    for (int m = 0; m < 2; m++)
#pragma unroll
        for (int j = 0; j < 4; j++)
#pragma unroll
            for (int e = 0; e < 4; e++) acc[m][j][e] = 0.f;

    auto load_stage = [&](int s, int kt) {
        const unsigned st = smb + (unsigned)s * 46080u;
#pragma unroll
        for (int i = 0; i < 4; i++) {
            int r = lr + i * 32;
            unsigned dst = st + r * 144 + lcb;
            CP_ASYNC16(dst, Ah + (size_t)(row0 + r) * EMB + kt * 64 + lce);
            if (Al)
                CP_ASYNC16(dst + 18432u, Al + (size_t)(row0 + r) * EMB + kt * 64 + lce);
        }
#pragma unroll
        for (int i = 0; i < 2; i++) {
            int r = lr + i * 32;
            CP_ASYNC16(st + 36864u + r * 144 + lcb,
                       Wh + (size_t)(col0 + r) * EMB + kt * 64 + lce);
        }
    };

    const unsigned aoff = (wr * 32 + (lane & 15)) * 144 + (lane >> 4) * 16;
    const unsigned boff = 36864u +
        (wc * 32 + ((lane >> 4) << 3) + (lane & 7)) * 144 + (((lane >> 3) & 1) * 16);

    load_stage(0, 0); CP_COMMIT();
    load_stage(1, 1); CP_COMMIT();

    for (int kt = 0; kt < 8; kt++) {
        const int s = kt & 1;
        if (kt < 7) { CP_WAIT(1); } else { CP_WAIT(0); }
        __syncthreads();
        const unsigned st = smb + (unsigned)s * 46080u;
        const unsigned aAh = st + aoff;
        const unsigned aWh = st + boff;
#pragma unroll
        for (int kc = 0; kc < 4; kc++) {
            unsigned a0h[4], a1h[4], a0l[4], a1l[4];
            ldsm4(a0h, aAh + kc * 32);
            ldsm4(a1h, aAh + kc * 32 + 16 * 144);
            if (Al) {
                ldsm4(a0l, aAh + 18432u + kc * 32);
                ldsm4(a1l, aAh + 18432u + kc * 32 + 16 * 144);
            }
#pragma unroll
            for (int jp = 0; jp < 2; jp++) {
                unsigned bh[4];
                ldsm4(bh, aWh + kc * 32 + jp * 16 * 144);
                mma16816h(acc[0][2 * jp],     a0h, bh[0], bh[1]);
                mma16816h(acc[0][2 * jp + 1], a0h, bh[2], bh[3]);
                mma16816h(acc[1][2 * jp],     a1h, bh[0], bh[1]);
                mma16816h(acc[1][2 * jp + 1], a1h, bh[2], bh[3]);
                if (Al) {
                    mma16816h(acc[0][2 * jp],     a0l, bh[0], bh[1]);
                    mma16816h(acc[0][2 * jp + 1], a0l, bh[2], bh[3]);
                    mma16816h(acc[1][2 * jp],     a1l, bh[0], bh[1]);
                    mma16816h(acc[1][2 * jp + 1], a1l, bh[2], bh[3]);
                }
            }
        }
        __syncthreads();
        if (kt + 2 < 8) { load_stage(s, kt + 2); CP_COMMIT(); }
    }

    if (gam) {
        // ---- fused per-row LayerNorm + *lnsc -> fp16 hi ----------------------
        float* redS = (float*)smp;          // [2][128]
        float* redQ = redS + 256;           // [2][128]
        float sum[2][2], ssq[2][2];
#pragma unroll
        for (int m = 0; m < 2; m++)
#pragma unroll
            for (int i = 0; i < 2; i++) {
                float s_ = 0.f, q_ = 0.f;
#pragma unroll
                for (int j = 0; j < 4; j++) {
                    float a0 = acc[m][j][2 * i], a1 = acc[m][j][2 * i + 1];
                    s_ += a0 + a1;
                    q_ += a0 * a0 + a1 * a1;
                }
                sum[m][i] = s_; ssq[m][i] = q_;
            }
#pragma unroll
        for (int off = 1; off <= 2; off <<= 1)
#pragma unroll
            for (int m = 0; m < 2; m++)
#pragma unroll
                for (int i = 0; i < 2; i++) {
                    sum[m][i] += __shfl_xor_sync(0xffffffffu, sum[m][i], off);
                    ssq[m][i] += __shfl_xor_sync(0xffffffffu, ssq[m][i], off);
                }
        if ((lane & 3) == 0) {
#pragma unroll
            for (int m = 0; m < 2; m++)
#pragma unroll
                for (int i = 0; i < 2; i++) {
                    int row = wr * 32 + m * 16 + i * 8 + (lane >> 2);
                    redS[wc * 128 + row] = sum[m][i];
                    redQ[wc * 128 + row] = ssq[m][i];
                }
        }
        __syncthreads();
#pragma unroll
        for (int m = 0; m < 2; m++)
#pragma unroll
            for (int i = 0; i < 2; i++) {
                const int row = wr * 32 + m * 16 + i * 8 + (lane >> 2);
                const float s_ = redS[row] + redS[128 + row];
                const float q_ = redQ[row] + redQ[128 + row];
                const float mean = s_ * (1.f / 64.f);
                const float var  = q_ * (1.f / 64.f) - mean * mean;
                const float rs   = rsqrtf(var + 1e-5f);
                const int gr = row0 + row;
#pragma unroll
                for (int j = 0; j < 4; j++) {
                    const int cl = wc * 32 + j * 8 + (lane & 3) * 2;
                    float v0 = ((acc[m][j][2 * i]     - mean) * rs * gam[cl]     + bet[cl])     * lnsc;
                    float v1 = ((acc[m][j][2 * i + 1] - mean) * rs * gam[cl + 1] + bet[cl + 1]) * lnsc;
                    *(unsigned*)&Hh[(size_t)gr * EMB + col0 + cl] = pk2h(v0, v1);
                }
            }
        return;
    }

    // ---- plain epilogue ------------------------------------------------------
#pragma unroll
    for (int m = 0; m < 2; m++) {
#pragma unroll
        for (int j = 0; j < 4; j++) {
            const int gr = row0 + wr * 32 + m * 16 + (lane >> 2);
            const int gc = col0 + wc * 32 + j * 8 + (lane & 3) * 2;
            float b0 = 0.f, b1 = 0.f;
            if (bias) { b0 = bias[gc]; b1 = bias[gc + 1]; }
            float v00 = acc[m][j][0] + b0, v01 = acc[m][j][1] + b1;
            float v10 = acc[m][j][2] + b0, v11 = acc[m][j][3] + b1;
            if (C) {
                *(float2*)&C[(size_t)gr * EMB + gc]       = make_float2(v00, v01);
                *(float2*)&C[(size_t)(gr + 8) * EMB + gc] = make_float2(v10, v11);
            }
            if (Hh) {
                *(unsigned*)&Hh[(size_t)gr * EMB + gc]       = pk2h(v00, v01);
                *(unsigned*)&Hh[(size_t)(gr + 8) * EMB + gc] = pk2h(v10, v11);
            }
        }
    }
}

__global__ __launch_bounds__(256, 2) void proj_qkv(
    const float* __restrict__ klng, const float* __restrict__ klnb,
    const float* __restrict__ qlng, const float* __restrict__ qlnb)
{
    const float SC  = 0.21022410381342865f;                        // 512^-0.25
    const float SCQ = 0.21022410381342865f * 1.4426950408889634f;  // * log2(e)
    const int z = blockIdx.z;
    const __half* Wh = g_wh + (size_t)z * WSZ;
    if (z == 0)        // K: 2-term, fused LN
        proj_body(g_xh, g_xl, Wh, nullptr, nullptr, g_kh, klng, klnb, SC);
    else if (z == 1)   // Q: 2-term, fused LN (log2e folded)
        proj_body(g_xh, g_xl, Wh, nullptr, nullptr, g_qh, qlng, qlnb, SCQ);
    else               // V: 1-term
        proj_body(g_xh, nullptr, Wh, nullptr, nullptr, g_vh, nullptr, nullptr, 0.f);
}

__global__ __launch_bounds__(256, 2) void proj_out(const float* __restrict__ bias,
                                                   float* __restrict__ out)
{
    // out-proj: 1-term (O_lo dropped)
    proj_body(g_oh, nullptr, g_wh + 3 * (size_t)WSZ,
              bias, out, nullptr, nullptr, nullptr, 0.f);
}

// ---------------------------------------------------------------------------
// Flash attention (fp16, 1-term): 128-query tiles, 256 thr. Scores in log2
// domain (Q carries log2e); mask folded as additive -100 bias; softmax via
// ex2.approx.f16x2 whose output IS the PV A-fragment. cp.async 2-stage KV.
// smem: Q 18432 + 2 stages x {K,V} 18432 + mask 512 = 55808 B.
// ---------------------------------------------------------------------------
__global__ __launch_bounds__(256, 2) void attn_mma(const float* __restrict__ mask)
{
    extern __shared__ __align__(16) char smraw[];
    const unsigned smb = sa(smraw);
    const unsigned QH = 0, KV = 18432u, MK = 55296u;

    const int b   = blockIdx.z;
    const int h   = blockIdx.y;
    const int t0  = blockIdx.x * 128;
    const int tid = threadIdx.x;
    const int lane = tid & 31;
    const int w    = tid >> 5;

    // ---- Q load (fp16 hi) ----
#pragma unroll
    for (int i = 0; i < 4; i++) {
        int idx = tid + i * 256;
        int r = idx >> 3, c = idx & 7;
        size_t gi = (size_t)(b * TT + t0 + r) * EMB + h * DD + c * 8;
        CP_ASYNC16(smb + QH + r * 144 + c * 16, g_qh + gi);
    }

    auto load_kv = [&](int s, int kt) {
        const unsigned base = smb + KV + (unsigned)s * 18432u;
        const int s0 = kt * 64;
#pragma unroll
        for (int i = 0; i < 2; i++) {
            int idx = tid + i * 256;
            int r = idx >> 3, c = idx & 7;
            size_t gi = (size_t)(b * TT + s0 + r) * EMB + h * DD + c * 8;
            unsigned d = base + r * 144 + c * 16;
            CP_ASYNC16(d,         g_kh + gi);
            CP_ASYNC16(d + 9216u, g_vh + gi);
        }
        if (tid < 16)
            CP_ASYNC16(smb + MK + (unsigned)s * 256u + tid * 16,
                       mask + b * TT + s0 + tid * 4);
    };

    load_kv(0, 0); CP_COMMIT();
    load_kv(1, 1); CP_COMMIT();

    const unsigned qh_a = smb + QH + (w * 16 + (lane & 15)) * 144 + (lane >> 4) * 16;
    const unsigned koff = (((lane >> 4) << 3) + (lane & 7)) * 144 + ((lane >> 3) & 1) * 16;
    const unsigned voff = ((((lane >> 3) & 1) * 8 + (lane & 7)) * 72 + ((lane >> 4) << 3)) * 2;

    // ---- wait Q (+stage0), hoist Q fragments into registers ----
    CP_WAIT(1);
    __syncthreads();
    unsigned qhf[4][4];
#pragma unroll
    for (int kc = 0; kc < 4; kc++)
        ldsm4(qhf[kc], qh_a + kc * 32);

    float oa[8][4];
#pragma unroll
    for (int j = 0; j < 8; j++)
#pragma unroll
        for (int e = 0; e < 4; e++) oa[j][e] = 0.f;
    float l0 = 0.f, l1 = 0.f;

    const float rb0 = (mask[b * TT + t0 + w * 16 + (lane >> 2)]     > 0.f) ? 0.f : -100.f;
    const float rb1 = (mask[b * TT + t0 + w * 16 + (lane >> 2) + 8] > 0.f) ? 0.f : -100.f;

    for (int kt = 0; kt < TT / 64; kt++) {
        const int s = kt & 1;
        if (kt < TT / 64 - 1) { CP_WAIT(1); } else { CP_WAIT(0); }
        __syncthreads();

        const unsigned stb  = smb + KV + (unsigned)s * 18432u;
        const unsigned kh_a = stb + koff;
        const unsigned vh_a = stb + 9216u + voff;
        const float* mkbuf = (const float*)(smraw + MK + (unsigned)s * 256u);

        // ---- S (log2 domain) = Qh * K ----
        float sc[8][4];
#pragma unroll
        for (int j = 0; j < 8; j++)
#pragma unroll
            for (int e = 0; e < 4; e++) sc[j][e] = 0.f;

#pragma unroll
        for (int kc = 0; kc < 4; kc++) {
#pragma unroll
            for (int jp = 0; jp < 4; jp++) {
                unsigned bh[4];
                ldsm4(bh, kh_a + kc * 32 + jp * 16 * 144);
                mma16816h(sc[2 * jp],     qhf[kc], bh[0], bh[1]);
                mma16816h(sc[2 * jp + 1], qhf[kc], bh[2], bh[3]);
            }
        }

        // ---- mask bias + packed ex2 -> P fragments ----
        unsigned p01[8], p23[8];
#pragma unroll
        for (int j = 0; j < 8; j++) {
            int col = j * 8 + (lane & 3) * 2;
            float cb0 = (mkbuf[col]     > 0.f) ? 0.f : -100.f;
            float cb1 = (mkbuf[col + 1] > 0.f) ? 0.f : -100.f;
            p01[j] = ex2h2(pk2h(sc[j][0] + rb0 + cb0, sc[j][1] + rb0 + cb1));
            p23[j] = ex2h2(pk2h(sc[j][2] + rb1 + cb0, sc[j][3] + rb1 + cb1));
            float2 f0 = h22f2(p01[j]);
            float2 f1 = h22f2(p23[j]);
            l0 += f0.x + f0.y;
            l1 += f1.x + f1.y;
        }

        // ---- O += P * V ----
#pragma unroll
        for (int kc = 0; kc < 4; kc++) {
            unsigned a[4];
            a[0] = p01[2 * kc];     a[1] = p23[2 * kc];
            a[2] = p01[2 * kc + 1]; a[3] = p23[2 * kc + 1];
#pragma unroll
            for (int jp = 0; jp < 4; jp++) {
                unsigned bv[4];
                ldsm4t(bv, vh_a + kc * 16 * 144 + jp * 32);
                mma16816h(oa[2 * jp],     a, bv[0], bv[1]);
                mma16816h(oa[2 * jp + 1], a, bv[2], bv[3]);
            }
        }

        __syncthreads();
        if (kt + 2 < TT / 64) { load_kv(s, kt + 2); CP_COMMIT(); }
    }

    // ---- epilogue: reduce l across quad, O / l -> fp16 hi ----
    l0 += __shfl_xor_sync(0xffffffffu, l0, 1);
    l0 += __shfl_xor_sync(0xffffffffu, l0, 2);
    l1 += __shfl_xor_sync(0xffffffffu, l1, 1);
    l1 += __shfl_xor_sync(0xffffffffu, l1, 2);
    const float inv0 = 1.f / l0;
    const float inv1 = 1.f / l1;
    const int gr0 = b * TT + t0 + w * 16 + (lane >> 2);
#pragma unroll
    for (int j = 0; j < 8; j++) {
        const int col = h * DD + j * 8 + (lane & 3) * 2;
        *(unsigned*)&g_oh[(size_t)gr0 * EMB + col] =
            pk2h(oa[j][0] * inv0, oa[j][1] * inv0);
        *(unsigned*)&g_oh[(size_t)(gr0 + 8) * EMB + col] =
            pk2h(oa[j][2] * inv1, oa[j][3] * inv1);
    }
}

// ---------------------------------------------------------------------------
extern "C" void kernel_launch(void* const* d_in, const int* in_sizes, int n_in,
                              void* d_out, int out_size)
{
    const float* x    = (const float*)d_in[0];
    const float* mask = (const float*)d_in[1];
    const float* Wk   = (const float*)d_in[2];
    const float* Wq   = (const float*)d_in[3];
    const float* Wv   = (const float*)d_in[4];
    const float* Wu   = (const float*)d_in[5];
    const float* bu   = (const float*)d_in[6];
    const float* klng = (const float*)d_in[7];
    const float* klnb = (const float*)d_in[8];
    const float* qlng = (const float*)d_in[9];
    const float* qlnb = (const float*)d_in[10];
    float* out = (float*)d_out;

    // fused splits: x (hi/lo) + 4 weights (hi) in one launch
    const int SPLIT_ITEMS = (ME * EMB + 4 * WSZ) / 4;
    split_all<<<(SPLIT_ITEMS + 255) / 256, 256>>>(x, Wk, Wq, Wv, Wu);

    const int PSMEM = 2 * 46080;  // 92160
    cudaFuncSetAttribute(proj_qkv,
                         cudaFuncAttributeMaxDynamicSharedMemorySize, PSMEM);
    cudaFuncSetAttribute(proj_out,
                         cudaFuncAttributeMaxDynamicSharedMemorySize, PSMEM);
    proj_qkv<<<dim3(ME / 128, EMB / 64, 3), 256, PSMEM>>>(klng, klnb, qlng, qlnb);

    const int ASMEM = 55296 + 512;  // 55808
    cudaFuncSetAttribute(attn_mma,
                         cudaFuncAttributeMaxDynamicSharedMemorySize, ASMEM);
    attn_mma<<<dim3(TT / 128, HH, BB), 256, ASMEM>>>(mask);

    proj_out<<<dim3(ME / 128, EMB / 64, 1), 256, PSMEM>>>(bu, out);
}

// round 12
// speedup vs baseline: 3.4118x; 1.1122x over previous
#include <cuda_runtime.h>
#include <cuda_fp16.h>
#include <cstdint>

#define ME   4096   // B*T rows
#define EMB  512
#define TT   2048
#define BB   2
#define HH   8
#define DD   64
#define WSZ  (EMB * EMB)

// ---- scratch (device globals; no cudaMalloc allowed) -----------------------
__device__ __align__(16) __half g_xh[ME * EMB];
__device__ __align__(16) __half g_wh[4 * WSZ];      // single fp16 weights
__device__ __align__(16) __half g_qh[ME * EMB];     // carries SC*log2e
__device__ __align__(16) __half g_kh[ME * EMB];     // carries SC
__device__ __align__(16) __half g_vh[ME * EMB];
__device__ __align__(16) __half g_oh[ME * EMB];

// ---- helpers ----------------------------------------------------------------
__device__ __forceinline__ unsigned sa(const void* p) {
    return (unsigned)__cvta_generic_to_shared(p);
}
__device__ __forceinline__ void ldsm4(unsigned r[4], unsigned addr) {
    asm volatile("ldmatrix.sync.aligned.m8n8.x4.shared.b16 {%0,%1,%2,%3}, [%4];"
                 : "=r"(r[0]), "=r"(r[1]), "=r"(r[2]), "=r"(r[3]) : "r"(addr));
}
__device__ __forceinline__ void ldsm4t(unsigned r[4], unsigned addr) {
    asm volatile("ldmatrix.sync.aligned.m8n8.x4.trans.shared.b16 {%0,%1,%2,%3}, [%4];"
                 : "=r"(r[0]), "=r"(r[1]), "=r"(r[2]), "=r"(r[3]) : "r"(addr));
}
__device__ __forceinline__ void mma16816h(float d[4], const unsigned a[4],
                                          unsigned b0, unsigned b1) {
    asm volatile(
        "mma.sync.aligned.m16n8k16.row.col.f32.f16.f16.f32 "
        "{%0,%1,%2,%3}, {%4,%5,%6,%7}, {%8,%9}, {%0,%1,%2,%3};"
        : "+f"(d[0]), "+f"(d[1]), "+f"(d[2]), "+f"(d[3])
        : "r"(a[0]), "r"(a[1]), "r"(a[2]), "r"(a[3]), "r"(b0), "r"(b1));
}
__device__ __forceinline__ unsigned pk2h(float lo, float hi) {    // f16x2
    __half2 t = __floats2half2_rn(lo, hi);
    return *reinterpret_cast<unsigned*>(&t);
}
__device__ __forceinline__ unsigned ex2h2(unsigned a) {           // 2^x on f16x2
    unsigned r;
    asm("ex2.approx.f16x2 %0, %1;" : "=r"(r) : "r"(a));
    return r;
}

#define CP_ASYNC16(dst, src) \
    asm volatile("cp.async.cg.shared.global [%0], [%1], 16;" :: "r"(dst), "l"(src))
#define CP_COMMIT() asm volatile("cp.async.commit_group;" ::: "memory")
#define CP_WAIT(n)  asm volatile("cp.async.wait_group %0;" :: "n"(n) : "memory")

// ---- fused convert: x and 4 weights -> fp16 ----------------------------------
__global__ void split_all(const float* __restrict__ x,
                          const float* __restrict__ w0, const float* __restrict__ w1,
                          const float* __restrict__ w2, const float* __restrict__ w3)
{
    int i = (blockIdx.x * blockDim.x + threadIdx.x) * 4;
    if (i < ME * EMB) {
        float4 v = *(const float4*)&x[i];
        *(__half2*)&g_xh[i]     = __floats2half2_rn(v.x, v.y);
        *(__half2*)&g_xh[i + 2] = __floats2half2_rn(v.z, v.w);
    } else {
        int j = i - ME * EMB;
        if (j >= 4 * WSZ) return;
        int z = j / WSZ, k = j % WSZ;
        const float* src = (z == 0) ? w0 : (z == 1) ? w1 : (z == 2) ? w2 : w3;
        float4 v = *(const float4*)&src[k];
        __half* dst = g_wh + (size_t)z * WSZ + k;
        *(__half2*)&dst[0] = __floats2half2_rn(v.x, v.y);
        *(__half2*)&dst[2] = __floats2half2_rn(v.z, v.w);
    }
}

// ---------------------------------------------------------------------------
// fp16 1-term GEMM body: C = A[M,512] @ W[N,512]^T (+bias).
// tile 128x64, 256 thr, 8 warps (4 Mrow x 2 Ncol), cp.async 2-stage.
// Epilogues: fp32 (+bias); or fp16 out, optionally with fused per-(token,head)
// LayerNorm (tile == one head) scaled by lnsc.
// smem/stage: A 18432 + W 9216 = 27648; 2 stages = 55296 B.
// ---------------------------------------------------------------------------
__device__ __forceinline__ void proj_body(
    const __half* __restrict__ Ah, const __half* __restrict__ Wh,
    const float* __restrict__ bias, float* __restrict__ C,
    __half* __restrict__ Hh,
    const float* __restrict__ gam, const float* __restrict__ bet, float lnsc)
{
    extern __shared__ __align__(16) char smp[];
    const unsigned smb = sa(smp);

    const int tid  = threadIdx.x;
    const int lane = tid & 31;
    const int w    = tid >> 5;
    const int wr   = w & 3;
    const int wc   = w >> 2;
    const int row0 = blockIdx.x * 128;
    const int col0 = blockIdx.y * 64;

    const int lr  = tid >> 3;
    const int lcb = (tid & 7) * 16;
    const int lce = (tid & 7) * 8;

    float acc[2][4][4];
#pragma unroll
    for (int m = 0; m < 2; m++)
#pragma unroll
        for (int j = 0; j < 4; j++)
#pragma unroll
            for (int e = 0; e < 4; e++) acc[m][j][e] = 0.f;

    auto load_stage = [&](int s, int kt) {
        const unsigned st = smb + (unsigned)s * 27648u;
#pragma unroll
        for (int i = 0; i < 4; i++) {
            int r = lr + i * 32;
            CP_ASYNC16(st + r * 144 + lcb,
                       Ah + (size_t)(row0 + r) * EMB + kt * 64 + lce);
        }
#pragma unroll
        for (int i = 0; i < 2; i++) {
            int r = lr + i * 32;
            CP_ASYNC16(st + 18432u + r * 144 + lcb,
                       Wh + (size_t)(col0 + r) * EMB + kt * 64 + lce);
        }
    };

    const unsigned aoff = (wr * 32 + (lane & 15)) * 144 + (lane >> 4) * 16;
    const unsigned boff = 18432u +
        (wc * 32 + ((lane >> 4) << 3) + (lane & 7)) * 144 + (((lane >> 3) & 1) * 16);

    load_stage(0, 0); CP_COMMIT();
    load_stage(1, 1); CP_COMMIT();

    for (int kt = 0; kt < 8; kt++) {
        const int s = kt & 1;
        if (kt < 7) { CP_WAIT(1); } else { CP_WAIT(0); }
        __syncthreads();
        const unsigned st = smb + (unsigned)s * 27648u;
        const unsigned aA = st + aoff;
        const unsigned aW = st + boff;
#pragma unroll
        for (int kc = 0; kc < 4; kc++) {
            unsigned a0[4], a1[4];
            ldsm4(a0, aA + kc * 32);
            ldsm4(a1, aA + kc * 32 + 16 * 144);
#pragma unroll
            for (int jp = 0; jp < 2; jp++) {
                unsigned bh[4];
                ldsm4(bh, aW + kc * 32 + jp * 16 * 144);
                mma16816h(acc[0][2 * jp],     a0, bh[0], bh[1]);
                mma16816h(acc[0][2 * jp + 1], a0, bh[2], bh[3]);
                mma16816h(acc[1][2 * jp],     a1, bh[0], bh[1]);
                mma16816h(acc[1][2 * jp + 1], a1, bh[2], bh[3]);
            }
        }
        __syncthreads();
        if (kt + 2 < 8) { load_stage(s, kt + 2); CP_COMMIT(); }
    }

    if (gam) {
        // ---- fused per-row LayerNorm + *lnsc -> fp16 -------------------------
        float* redS = (float*)smp;          // [2][128]
        float* redQ = redS + 256;           // [2][128]
        float sum[2][2], ssq[2][2];
#pragma unroll
        for (int m = 0; m < 2; m++)
#pragma unroll
            for (int i = 0; i < 2; i++) {
                float s_ = 0.f, q_ = 0.f;
#pragma unroll
                for (int j = 0; j < 4; j++) {
                    float a0 = acc[m][j][2 * i], a1 = acc[m][j][2 * i + 1];
                    s_ += a0 + a1;
                    q_ += a0 * a0 + a1 * a1;
                }
                sum[m][i] = s_; ssq[m][i] = q_;
            }
#pragma unroll
        for (int off = 1; off <= 2; off <<= 1)
#pragma unroll
            for (int m = 0; m < 2; m++)
#pragma unroll
                for (int i = 0; i < 2; i++) {
                    sum[m][i] += __shfl_xor_sync(0xffffffffu, sum[m][i], off);
                    ssq[m][i] += __shfl_xor_sync(0xffffffffu, ssq[m][i], off);
                }
        if ((lane & 3) == 0) {
#pragma unroll
            for (int m = 0; m < 2; m++)
#pragma unroll
                for (int i = 0; i < 2; i++) {
                    int row = wr * 32 + m * 16 + i * 8 + (lane >> 2);
                    redS[wc * 128 + row] = sum[m][i];
                    redQ[wc * 128 + row] = ssq[m][i];
                }
        }
        __syncthreads();
#pragma unroll
        for (int m = 0; m < 2; m++)
#pragma unroll
            for (int i = 0; i < 2; i++) {
                const int row = wr * 32 + m * 16 + i * 8 + (lane >> 2);
                const float s_ = redS[row] + redS[128 + row];
                const float q_ = redQ[row] + redQ[128 + row];
                const float mean = s_ * (1.f / 64.f);
                const float var  = q_ * (1.f / 64.f) - mean * mean;
                const float rs   = rsqrtf(var + 1e-5f);
                const int gr = row0 + row;
#pragma unroll
                for (int j = 0; j < 4; j++) {
                    const int cl = wc * 32 + j * 8 + (lane & 3) * 2;
                    float v0 = ((acc[m][j][2 * i]     - mean) * rs * gam[cl]     + bet[cl])     * lnsc;
                    float v1 = ((acc[m][j][2 * i + 1] - mean) * rs * gam[cl + 1] + bet[cl + 1]) * lnsc;
                    *(unsigned*)&Hh[(size_t)gr * EMB + col0 + cl] = pk2h(v0, v1);
                }
            }
        return;
    }

    // ---- plain epilogue ------------------------------------------------------
#pragma unroll
    for (int m = 0; m < 2; m++) {
#pragma unroll
        for (int j = 0; j < 4; j++) {
            const int gr = row0 + wr * 32 + m * 16 + (lane >> 2);
            const int gc = col0 + wc * 32 + j * 8 + (lane & 3) * 2;
            float b0 = 0.f, b1 = 0.f;
            if (bias) { b0 = bias[gc]; b1 = bias[gc + 1]; }
            float v00 = acc[m][j][0] + b0, v01 = acc[m][j][1] + b1;
            float v10 = acc[m][j][2] + b0, v11 = acc[m][j][3] + b1;
            if (C) {
                *(float2*)&C[(size_t)gr * EMB + gc]       = make_float2(v00, v01);
                *(float2*)&C[(size_t)(gr + 8) * EMB + gc] = make_float2(v10, v11);
            }
            if (Hh) {
                *(unsigned*)&Hh[(size_t)gr * EMB + gc]       = pk2h(v00, v01);
                *(unsigned*)&Hh[(size_t)(gr + 8) * EMB + gc] = pk2h(v10, v11);
            }
        }
    }
}

__global__ __launch_bounds__(256, 2) void proj_qkv(
    const float* __restrict__ klng, const float* __restrict__ klnb,
    const float* __restrict__ qlng, const float* __restrict__ qlnb)
{
    const float SC  = 0.21022410381342865f;                        // 512^-0.25
    const float SCQ = 0.21022410381342865f * 1.4426950408889634f;  // * log2(e)
    const int z = blockIdx.z;
    const __half* Wh = g_wh + (size_t)z * WSZ;
    if (z == 0)
        proj_body(g_xh, Wh, nullptr, nullptr, g_kh, klng, klnb, SC);
    else if (z == 1)
        proj_body(g_xh, Wh, nullptr, nullptr, g_qh, qlng, qlnb, SCQ);
    else
        proj_body(g_xh, Wh, nullptr, nullptr, g_vh, nullptr, nullptr, 0.f);
}

__global__ __launch_bounds__(256, 2) void proj_out(const float* __restrict__ bias,
                                                   float* __restrict__ out)
{
    proj_body(g_oh, g_wh + 3 * (size_t)WSZ, bias, out, nullptr, nullptr, nullptr, 0.f);
}

// ---------------------------------------------------------------------------
// Flash attention (fp16, 1-term): 128-query tiles, 256 thr. Scores in log2
// domain (Q carries log2e); mask folded as additive -100 bias; softmax via
// ex2.approx.f16x2 (output IS the PV A-fragment); l accumulated per-tile in
// __half2 (bounded <=136/lane/tile), folded to fp32 per tile. cp.async 2-stage.
// ---------------------------------------------------------------------------
__global__ __launch_bounds__(256, 2) void attn_mma(const float* __restrict__ mask)
{
    extern __shared__ __align__(16) char smraw[];
    const unsigned smb = sa(smraw);
    const unsigned QH = 0, KV = 18432u, MK = 55296u;

    const int b   = blockIdx.z;
    const int h   = blockIdx.y;
    const int t0  = blockIdx.x * 128;
    const int tid = threadIdx.x;
    const int lane = tid & 31;
    const int w    = tid >> 5;

    // ---- Q load (fp16) ----
#pragma unroll
    for (int i = 0; i < 4; i++) {
        int idx = tid + i * 256;
        int r = idx >> 3, c = idx & 7;
        size_t gi = (size_t)(b * TT + t0 + r) * EMB + h * DD + c * 8;
        CP_ASYNC16(smb + QH + r * 144 + c * 16, g_qh + gi);
    }

    auto load_kv = [&](int s, int kt) {
        const unsigned base = smb + KV + (unsigned)s * 18432u;
        const int s0 = kt * 64;
#pragma unroll
        for (int i = 0; i < 2; i++) {
            int idx = tid + i * 256;
            int r = idx >> 3, c = idx & 7;
            size_t gi = (size_t)(b * TT + s0 + r) * EMB + h * DD + c * 8;
            unsigned d = base + r * 144 + c * 16;
            CP_ASYNC16(d,         g_kh + gi);
            CP_ASYNC16(d + 9216u, g_vh + gi);
        }
        if (tid < 16)
            CP_ASYNC16(smb + MK + (unsigned)s * 256u + tid * 16,
                       mask + b * TT + s0 + tid * 4);
    };

    load_kv(0, 0); CP_COMMIT();
    load_kv(1, 1); CP_COMMIT();

    const unsigned qh_a = smb + QH + (w * 16 + (lane & 15)) * 144 + (lane >> 4) * 16;
    const unsigned koff = (((lane >> 4) << 3) + (lane & 7)) * 144 + ((lane >> 3) & 1) * 16;
    const unsigned voff = ((((lane >> 3) & 1) * 8 + (lane & 7)) * 72 + ((lane >> 4) << 3)) * 2;

    // ---- wait Q (+stage0), hoist Q fragments into registers ----
    CP_WAIT(1);
    __syncthreads();
    unsigned qhf[4][4];
#pragma unroll
    for (int kc = 0; kc < 4; kc++)
        ldsm4(qhf[kc], qh_a + kc * 32);

    float oa[8][4];
#pragma unroll
    for (int j = 0; j < 8; j++)
#pragma unroll
        for (int e = 0; e < 4; e++) oa[j][e] = 0.f;
    float l0 = 0.f, l1 = 0.f;

    const float rb0 = (mask[b * TT + t0 + w * 16 + (lane >> 2)]     > 0.f) ? 0.f : -100.f;
    const float rb1 = (mask[b * TT + t0 + w * 16 + (lane >> 2) + 8] > 0.f) ? 0.f : -100.f;

    for (int kt = 0; kt < TT / 64; kt++) {
        const int s = kt & 1;
        if (kt < TT / 64 - 1) { CP_WAIT(1); } else { CP_WAIT(0); }
        __syncthreads();

        const unsigned stb  = smb + KV + (unsigned)s * 18432u;
        const unsigned kh_a = stb + koff;
        const unsigned vh_a = stb + 9216u + voff;
        const float* mkbuf = (const float*)(smraw + MK + (unsigned)s * 256u);

        // ---- S (log2 domain) = Q * K ----
        float sc[8][4];
#pragma unroll
        for (int j = 0; j < 8; j++)
#pragma unroll
            for (int e = 0; e < 4; e++) sc[j][e] = 0.f;

#pragma unroll
        for (int kc = 0; kc < 4; kc++) {
#pragma unroll
            for (int jp = 0; jp < 4; jp++) {
                unsigned bh[4];
                ldsm4(bh, kh_a + kc * 32 + jp * 16 * 144);
                mma16816h(sc[2 * jp],     qhf[kc], bh[0], bh[1]);
                mma16816h(sc[2 * jp + 1], qhf[kc], bh[2], bh[3]);
            }
        }

        // ---- mask bias + packed ex2 -> P fragments; l in half2 ----
        unsigned p01[8], p23[8];
        __half2 lt0 = __floats2half2_rn(0.f, 0.f);
        __half2 lt1 = lt0;
#pragma unroll
        for (int j = 0; j < 8; j++) {
            int col = j * 8 + (lane & 3) * 2;
            float cb0 = (mkbuf[col]     > 0.f) ? 0.f : -100.f;
            float cb1 = (mkbuf[col + 1] > 0.f) ? 0.f : -100.f;
            p01[j] = ex2h2(pk2h(sc[j][0] + rb0 + cb0, sc[j][1] + rb0 + cb1));
            p23[j] = ex2h2(pk2h(sc[j][2] + rb1 + cb0, sc[j][3] + rb1 + cb1));
            lt0 = __hadd2(lt0, *reinterpret_cast<__half2*>(&p01[j]));
            lt1 = __hadd2(lt1, *reinterpret_cast<__half2*>(&p23[j]));
        }
        {
            float2 f0 = __half22float2(lt0);
            float2 f1 = __half22float2(lt1);
            l0 += f0.x + f0.y;
            l1 += f1.x + f1.y;
        }

        // ---- O += P * V ----
#pragma unroll
        for (int kc = 0; kc < 4; kc++) {
            unsigned a[4];
            a[0] = p01[2 * kc];     a[1] = p23[2 * kc];
            a[2] = p01[2 * kc + 1]; a[3] = p23[2 * kc + 1];
#pragma unroll
            for (int jp = 0; jp < 4; jp++) {
                unsigned bv[4];
                ldsm4t(bv, vh_a + kc * 16 * 144 + jp * 32);
                mma16816h(oa[2 * jp],     a, bv[0], bv[1]);
                mma16816h(oa[2 * jp + 1], a, bv[2], bv[3]);
            }
        }

        __syncthreads();
        if (kt + 2 < TT / 64) { load_kv(s, kt + 2); CP_COMMIT(); }
    }

    // ---- epilogue: reduce l across quad, O / l -> fp16 ----
    l0 += __shfl_xor_sync(0xffffffffu, l0, 1);
    l0 += __shfl_xor_sync(0xffffffffu, l0, 2);
    l1 += __shfl_xor_sync(0xffffffffu, l1, 1);
    l1 += __shfl_xor_sync(0xffffffffu, l1, 2);
    const float inv0 = 1.f / l0;
    const float inv1 = 1.f / l1;
    const int gr0 = b * TT + t0 + w * 16 + (lane >> 2);
#pragma unroll
    for (int j = 0; j < 8; j++) {
        const int col = h * DD + j * 8 + (lane & 3) * 2;
        *(unsigned*)&g_oh[(size_t)gr0 * EMB + col] =
            pk2h(oa[j][0] * inv0, oa[j][1] * inv0);
        *(unsigned*)&g_oh[(size_t)(gr0 + 8) * EMB + col] =
            pk2h(oa[j][2] * inv1, oa[j][3] * inv1);
    }
}

// ---------------------------------------------------------------------------
extern "C" void kernel_launch(void* const* d_in, const int* in_sizes, int n_in,
                              void* d_out, int out_size)
{
    const float* x    = (const float*)d_in[0];
    const float* mask = (const float*)d_in[1];
    const float* Wk   = (const float*)d_in[2];
    const float* Wq   = (const float*)d_in[3];
    const float* Wv   = (const float*)d_in[4];
    const float* Wu   = (const float*)d_in[5];
    const float* bu   = (const float*)d_in[6];
    const float* klng = (const float*)d_in[7];
    const float* klnb = (const float*)d_in[8];
    const float* qlng = (const float*)d_in[9];
    const float* qlnb = (const float*)d_in[10];
    float* out = (float*)d_out;

    const int SPLIT_ITEMS = (ME * EMB + 4 * WSZ) / 4;
    split_all<<<(SPLIT_ITEMS + 255) / 256, 256>>>(x, Wk, Wq, Wv, Wu);

    const int PSMEM = 2 * 27648;  // 55296
    cudaFuncSetAttribute(proj_qkv,
                         cudaFuncAttributeMaxDynamicSharedMemorySize, PSMEM);
    cudaFuncSetAttribute(proj_out,
                         cudaFuncAttributeMaxDynamicSharedMemorySize, PSMEM);
    proj_qkv<<<dim3(ME / 128, EMB / 64, 3), 256, PSMEM>>>(klng, klnb, qlng, qlnb);

    const int ASMEM = 55296 + 512;  // 55808
    cudaFuncSetAttribute(attn_mma,
                         cudaFuncAttributeMaxDynamicSharedMemorySize, ASMEM);
    attn_mma<<<dim3(TT / 128, HH, BB), 256, ASMEM>>>(mask);

    proj_out<<<dim3(ME / 128, EMB / 64, 1), 256, PSMEM>>>(bu, out);
}

// round 13
// speedup vs baseline: 3.5572x; 1.0426x over previous
#include <cuda_runtime.h>
#include <cuda_fp16.h>
#include <cstdint>

#define ME   4096   // B*T rows
#define EMB  512
#define TT   2048
#define BB   2
#define HH   8
#define DD   64
#define WSZ  (EMB * EMB)

// ---- scratch (device globals; no cudaMalloc allowed) -----------------------
__device__ __align__(16) __half g_xh[ME * EMB];
__device__ __align__(16) __half g_wh[4 * WSZ];      // single fp16 weights
__device__ __align__(16) __half g_qh[ME * EMB];     // carries SC*log2e
__device__ __align__(16) __half g_kh[ME * EMB];     // carries SC
__device__ __align__(16) __half g_vh[ME * EMB];
__device__ __align__(16) __half g_oh[ME * EMB];

// ---- helpers ----------------------------------------------------------------
__device__ __forceinline__ unsigned sa(const void* p) {
    return (unsigned)__cvta_generic_to_shared(p);
}
__device__ __forceinline__ void ldsm4(unsigned r[4], unsigned addr) {
    asm volatile("ldmatrix.sync.aligned.m8n8.x4.shared.b16 {%0,%1,%2,%3}, [%4];"
                 : "=r"(r[0]), "=r"(r[1]), "=r"(r[2]), "=r"(r[3]) : "r"(addr));
}
__device__ __forceinline__ void ldsm4t(unsigned r[4], unsigned addr) {
    asm volatile("ldmatrix.sync.aligned.m8n8.x4.trans.shared.b16 {%0,%1,%2,%3}, [%4];"
                 : "=r"(r[0]), "=r"(r[1]), "=r"(r[2]), "=r"(r[3]) : "r"(addr));
}
__device__ __forceinline__ void mma16816h(float d[4], const unsigned a[4],
                                          unsigned b0, unsigned b1) {
    asm volatile(
        "mma.sync.aligned.m16n8k16.row.col.f32.f16.f16.f32 "
        "{%0,%1,%2,%3}, {%4,%5,%6,%7}, {%8,%9}, {%0,%1,%2,%3};"
        : "+f"(d[0]), "+f"(d[1]), "+f"(d[2]), "+f"(d[3])
        : "r"(a[0]), "r"(a[1]), "r"(a[2]), "r"(a[3]), "r"(b0), "r"(b1));
}
__device__ __forceinline__ unsigned pk2h(float lo, float hi) {    // f16x2
    __half2 t = __floats2half2_rn(lo, hi);
    return *reinterpret_cast<unsigned*>(&t);
}
__device__ __forceinline__ unsigned ex2h2(unsigned a) {           // 2^x on f16x2
    unsigned r;
    asm("ex2.approx.f16x2 %0, %1;" : "=r"(r) : "r"(a));
    return r;
}

#define CP_ASYNC16(dst, src) \
    asm volatile("cp.async.cg.shared.global [%0], [%1], 16;" :: "r"(dst), "l"(src))
#define CP_COMMIT() asm volatile("cp.async.commit_group;" ::: "memory")
#define CP_WAIT(n)  asm volatile("cp.async.wait_group %0;" :: "n"(n) : "memory")

// ---- fused convert: x and 4 weights -> fp16 ----------------------------------
__global__ void split_all(const float* __restrict__ x,
                          const float* __restrict__ w0, const float* __restrict__ w1,
                          const float* __restrict__ w2, const float* __restrict__ w3)
{
    int i = (blockIdx.x * blockDim.x + threadIdx.x) * 4;
    if (i < ME * EMB) {
        float4 v = *(const float4*)&x[i];
        *(__half2*)&g_xh[i]     = __floats2half2_rn(v.x, v.y);
        *(__half2*)&g_xh[i + 2] = __floats2half2_rn(v.z, v.w);
    } else {
        int j = i - ME * EMB;
        if (j >= 4 * WSZ) return;
        int z = j / WSZ, k = j % WSZ;
        const float* src = (z == 0) ? w0 : (z == 1) ? w1 : (z == 2) ? w2 : w3;
        float4 v = *(const float4*)&src[k];
        __half* dst = g_wh + (size_t)z * WSZ + k;
        *(__half2*)&dst[0] = __floats2half2_rn(v.x, v.y);
        *(__half2*)&dst[2] = __floats2half2_rn(v.z, v.w);
    }
}

// ---------------------------------------------------------------------------
// fp16 1-term GEMM body: C = A[M,512] @ W[N,512]^T (+bias).
// tile 128x64, 256 thr, 8 warps (4 Mrow x 2 Ncol), cp.async 3-stage pipeline
// with load-before-compute (one __syncthreads per k-tile).
// smem/stage: A 18432 + W 9216 = 27648; 3 stages = 82944 B.
// ---------------------------------------------------------------------------
__device__ __forceinline__ void proj_body(
    const __half* __restrict__ Ah, const __half* __restrict__ Wh,
    const float* __restrict__ bias, float* __restrict__ C,
    __half* __restrict__ Hh,
    const float* __restrict__ gam, const float* __restrict__ bet, float lnsc)
{
    extern __shared__ __align__(16) char smp[];
    const unsigned smb = sa(smp);

    const int tid  = threadIdx.x;
    const int lane = tid & 31;
    const int w    = tid >> 5;
    const int wr   = w & 3;
    const int wc   = w >> 2;
    const int row0 = blockIdx.x * 128;
    const int col0 = blockIdx.y * 64;

    const int lr  = tid >> 3;
    const int lcb = (tid & 7) * 16;
    const int lce = (tid & 7) * 8;

    float acc[2][4][4];
#pragma unroll
    for (int m = 0; m < 2; m++)
#pragma unroll
        for (int j = 0; j < 4; j++)
#pragma unroll
            for (int e = 0; e < 4; e++) acc[m][j][e] = 0.f;

    auto load_stage = [&](int s, int kt) {
        const unsigned st = smb + (unsigned)s * 27648u;
#pragma unroll
        for (int i = 0; i < 4; i++) {
            int r = lr + i * 32;
            CP_ASYNC16(st + r * 144 + lcb,
                       Ah + (size_t)(row0 + r) * EMB + kt * 64 + lce);
        }
#pragma unroll
        for (int i = 0; i < 2; i++) {
            int r = lr + i * 32;
            CP_ASYNC16(st + 18432u + r * 144 + lcb,
                       Wh + (size_t)(col0 + r) * EMB + kt * 64 + lce);
        }
    };

    const unsigned aoff = (wr * 32 + (lane & 15)) * 144 + (lane >> 4) * 16;
    const unsigned boff = 18432u +
        (wc * 32 + ((lane >> 4) << 3) + (lane & 7)) * 144 + (((lane >> 3) & 1) * 16);

    load_stage(0, 0); CP_COMMIT();
    load_stage(1, 1); CP_COMMIT();

    for (int kt = 0; kt < 8; kt++) {
        if (kt < 7) { CP_WAIT(1); } else { CP_WAIT(0); }
        __syncthreads();
        if (kt + 2 < 8) { load_stage((kt + 2) % 3, kt + 2); CP_COMMIT(); }
        const unsigned st = smb + (unsigned)(kt % 3) * 27648u;
        const unsigned aA = st + aoff;
        const unsigned aW = st + boff;
#pragma unroll
        for (int kc = 0; kc < 4; kc++) {
            unsigned a0[4], a1[4];
            ldsm4(a0, aA + kc * 32);
            ldsm4(a1, aA + kc * 32 + 16 * 144);
#pragma unroll
            for (int jp = 0; jp < 2; jp++) {
                unsigned bh[4];
                ldsm4(bh, aW + kc * 32 + jp * 16 * 144);
                mma16816h(acc[0][2 * jp],     a0, bh[0], bh[1]);
                mma16816h(acc[0][2 * jp + 1], a0, bh[2], bh[3]);
                mma16816h(acc[1][2 * jp],     a1, bh[0], bh[1]);
                mma16816h(acc[1][2 * jp + 1], a1, bh[2], bh[3]);
            }
        }
    }

    if (gam) {
        // ---- fused per-row LayerNorm + *lnsc -> fp16 -------------------------
        __syncthreads();   // all warps done reading smem stages before reuse
        float* redS = (float*)smp;          // [2][128]
        float* redQ = redS + 256;           // [2][128]
        float sum[2][2], ssq[2][2];
#pragma unroll
        for (int m = 0; m < 2; m++)
#pragma unroll
            for (int i = 0; i < 2; i++) {
                float s_ = 0.f, q_ = 0.f;
#pragma unroll
                for (int j = 0; j < 4; j++) {
                    float a0 = acc[m][j][2 * i], a1 = acc[m][j][2 * i + 1];
                    s_ += a0 + a1;
                    q_ += a0 * a0 + a1 * a1;
                }
                sum[m][i] = s_; ssq[m][i] = q_;
            }
#pragma unroll
        for (int off = 1; off <= 2; off <<= 1)
#pragma unroll
            for (int m = 0; m < 2; m++)
#pragma unroll
                for (int i = 0; i < 2; i++) {
                    sum[m][i] += __shfl_xor_sync(0xffffffffu, sum[m][i], off);
                    ssq[m][i] += __shfl_xor_sync(0xffffffffu, ssq[m][i], off);
                }
        if ((lane & 3) == 0) {
#pragma unroll
            for (int m = 0; m < 2; m++)
#pragma unroll
                for (int i = 0; i < 2; i++) {
                    int row = wr * 32 + m * 16 + i * 8 + (lane >> 2);
                    redS[wc * 128 + row] = sum[m][i];
                    redQ[wc * 128 + row] = ssq[m][i];
                }
        }
        __syncthreads();
#pragma unroll
        for (int m = 0; m < 2; m++)
#pragma unroll
            for (int i = 0; i < 2; i++) {
                const int row = wr * 32 + m * 16 + i * 8 + (lane >> 2);
                const float s_ = redS[row] + redS[128 + row];
                const float q_ = redQ[row] + redQ[128 + row];
                const float mean = s_ * (1.f / 64.f);
                const float var  = q_ * (1.f / 64.f) - mean * mean;
                const float rs   = rsqrtf(var + 1e-5f);
                const int gr = row0 + row;
#pragma unroll
                for (int j = 0; j < 4; j++) {
                    const int cl = wc * 32 + j * 8 + (lane & 3) * 2;
                    float v0 = ((acc[m][j][2 * i]     - mean) * rs * gam[cl]     + bet[cl])     * lnsc;
                    float v1 = ((acc[m][j][2 * i + 1] - mean) * rs * gam[cl + 1] + bet[cl + 1]) * lnsc;
                    *(unsigned*)&Hh[(size_t)gr * EMB + col0 + cl] = pk2h(v0, v1);
                }
            }
        return;
    }

    // ---- plain epilogue ------------------------------------------------------
#pragma unroll
    for (int m = 0; m < 2; m++) {
#pragma unroll
        for (int j = 0; j < 4; j++) {
            const int gr = row0 + wr * 32 + m * 16 + (lane >> 2);
            const int gc = col0 + wc * 32 + j * 8 + (lane & 3) * 2;
            float b0 = 0.f, b1 = 0.f;
            if (bias) { b0 = bias[gc]; b1 = bias[gc + 1]; }
            float v00 = acc[m][j][0] + b0, v01 = acc[m][j][1] + b1;
            float v10 = acc[m][j][2] + b0, v11 = acc[m][j][3] + b1;
            if (C) {
                *(float2*)&C[(size_t)gr * EMB + gc]       = make_float2(v00, v01);
                *(float2*)&C[(size_t)(gr + 8) * EMB + gc] = make_float2(v10, v11);
            }
            if (Hh) {
                *(unsigned*)&Hh[(size_t)gr * EMB + gc]       = pk2h(v00, v01);
                *(unsigned*)&Hh[(size_t)(gr + 8) * EMB + gc] = pk2h(v10, v11);
            }
        }
    }
}

__global__ __launch_bounds__(256, 2) void proj_qkv(
    const float* __restrict__ klng, const float* __restrict__ klnb,
    const float* __restrict__ qlng, const float* __restrict__ qlnb)
{
    const float SC  = 0.21022410381342865f;                        // 512^-0.25
    const float SCQ = 0.21022410381342865f * 1.4426950408889634f;  // * log2(e)
    const int z = blockIdx.z;
    const __half* Wh = g_wh + (size_t)z * WSZ;
    if (z == 0)
        proj_body(g_xh, Wh, nullptr, nullptr, g_kh, klng, klnb, SC);
    else if (z == 1)
        proj_body(g_xh, Wh, nullptr, nullptr, g_qh, qlng, qlnb, SCQ);
    else
        proj_body(g_xh, Wh, nullptr, nullptr, g_vh, nullptr, nullptr, 0.f);
}

__global__ __launch_bounds__(256, 2) void proj_out(const float* __restrict__ bias,
                                                   float* __restrict__ out)
{
    proj_body(g_oh, g_wh + 3 * (size_t)WSZ, bias, out, nullptr, nullptr, nullptr, 0.f);
}

// ---------------------------------------------------------------------------
// Flash attention (fp16, 1-term): 128-query tiles, 256 thr. Scores in log2
// domain (Q carries log2e); mask folded as additive -100 bias; softmax via
// ex2.approx.f16x2 (output IS the PV A-fragment); l in half2 per tile.
// 3-stage cp.async KV pipeline, load-before-compute, one sync per tile.
// smem: Q 18432 + 3 stages x {K,V} 18432 + mask 3x256 = 74496 B.
// ---------------------------------------------------------------------------
__global__ __launch_bounds__(256, 2) void attn_mma(const float* __restrict__ mask)
{
    extern __shared__ __align__(16) char smraw[];
    const unsigned smb = sa(smraw);
    const unsigned QH = 0, KV = 18432u, MK = 73728u;

    const int b   = blockIdx.z;
    const int h   = blockIdx.y;
    const int t0  = blockIdx.x * 128;
    const int tid = threadIdx.x;
    const int lane = tid & 31;
    const int w    = tid >> 5;

    // ---- Q load (fp16), shares cp.async group 0 with KV stage 0 ----
#pragma unroll
    for (int i = 0; i < 4; i++) {
        int idx = tid + i * 256;
        int r = idx >> 3, c = idx & 7;
        size_t gi = (size_t)(b * TT + t0 + r) * EMB + h * DD + c * 8;
        CP_ASYNC16(smb + QH + r * 144 + c * 16, g_qh + gi);
    }

    auto load_kv = [&](int s, int kt) {
        const unsigned base = smb + KV + (unsigned)s * 18432u;
        const int s0 = kt * 64;
#pragma unroll
        for (int i = 0; i < 2; i++) {
            int idx = tid + i * 256;
            int r = idx >> 3, c = idx & 7;
            size_t gi = (size_t)(b * TT + s0 + r) * EMB + h * DD + c * 8;
            unsigned d = base + r * 144 + c * 16;
            CP_ASYNC16(d,         g_kh + gi);
            CP_ASYNC16(d + 9216u, g_vh + gi);
        }
        if (tid < 16)
            CP_ASYNC16(smb + MK + (unsigned)s * 256u + tid * 16,
                       mask + b * TT + s0 + tid * 4);
    };

    load_kv(0, 0); CP_COMMIT();
    load_kv(1, 1); CP_COMMIT();

    const unsigned qh_a = smb + QH + (w * 16 + (lane & 15)) * 144 + (lane >> 4) * 16;
    const unsigned koff = (((lane >> 4) << 3) + (lane & 7)) * 144 + ((lane >> 3) & 1) * 16;
    const unsigned voff = ((((lane >> 3) & 1) * 8 + (lane & 7)) * 72 + ((lane >> 4) << 3)) * 2;

    // ---- wait Q (+stage0), hoist Q fragments into registers ----
    CP_WAIT(1);
    __syncthreads();
    unsigned qhf[4][4];
#pragma unroll
    for (int kc = 0; kc < 4; kc++)
        ldsm4(qhf[kc], qh_a + kc * 32);

    float oa[8][4];
#pragma unroll
    for (int j = 0; j < 8; j++)
#pragma unroll
        for (int e = 0; e < 4; e++) oa[j][e] = 0.f;
    float l0 = 0.f, l1 = 0.f;

    const float rb0 = (mask[b * TT + t0 + w * 16 + (lane >> 2)]     > 0.f) ? 0.f : -100.f;
    const float rb1 = (mask[b * TT + t0 + w * 16 + (lane >> 2) + 8] > 0.f) ? 0.f : -100.f;

    for (int kt = 0; kt < TT / 64; kt++) {
        if (kt < TT / 64 - 1) { CP_WAIT(1); } else { CP_WAIT(0); }
        __syncthreads();
        if (kt + 2 < TT / 64) { load_kv((kt + 2) % 3, kt + 2); CP_COMMIT(); }

        const unsigned stb  = smb + KV + (unsigned)(kt % 3) * 18432u;
        const unsigned kh_a = stb + koff;
        const unsigned vh_a = stb + 9216u + voff;
        const float* mkbuf = (const float*)(smraw + MK + (unsigned)(kt % 3) * 256u);

        // ---- S (log2 domain) = Q * K ----
        float sc[8][4];
#pragma unroll
        for (int j = 0; j < 8; j++)
#pragma unroll
            for (int e = 0; e < 4; e++) sc[j][e] = 0.f;

#pragma unroll
        for (int kc = 0; kc < 4; kc++) {
#pragma unroll
            for (int jp = 0; jp < 4; jp++) {
                unsigned bh[4];
                ldsm4(bh, kh_a + kc * 32 + jp * 16 * 144);
                mma16816h(sc[2 * jp],     qhf[kc], bh[0], bh[1]);
                mma16816h(sc[2 * jp + 1], qhf[kc], bh[2], bh[3]);
            }
        }

        // ---- mask bias + packed ex2 -> P fragments; l in half2 ----
        unsigned p01[8], p23[8];
        __half2 lt0 = __floats2half2_rn(0.f, 0.f);
        __half2 lt1 = lt0;
#pragma unroll
        for (int j = 0; j < 8; j++) {
            int col = j * 8 + (lane & 3) * 2;
            float cb0 = (mkbuf[col]     > 0.f) ? 0.f : -100.f;
            float cb1 = (mkbuf[col + 1] > 0.f) ? 0.f : -100.f;
            p01[j] = ex2h2(pk2h(sc[j][0] + rb0 + cb0, sc[j][1] + rb0 + cb1));
            p23[j] = ex2h2(pk2h(sc[j][2] + rb1 + cb0, sc[j][3] + rb1 + cb1));
            lt0 = __hadd2(lt0, *reinterpret_cast<__half2*>(&p01[j]));
            lt1 = __hadd2(lt1, *reinterpret_cast<__half2*>(&p23[j]));
        }
        {
            float2 f0 = __half22float2(lt0);
            float2 f1 = __half22float2(lt1);
            l0 += f0.x + f0.y;
            l1 += f1.x + f1.y;
        }

        // ---- O += P * V ----
#pragma unroll
        for (int kc = 0; kc < 4; kc++) {
            unsigned a[4];
            a[0] = p01[2 * kc];     a[1] = p23[2 * kc];
            a[2] = p01[2 * kc + 1]; a[3] = p23[2 * kc + 1];
#pragma unroll
            for (int jp = 0; jp < 4; jp++) {
                unsigned bv[4];
                ldsm4t(bv, vh_a + kc * 16 * 144 + jp * 32);
                mma16816h(oa[2 * jp],     a, bv[0], bv[1]);
                mma16816h(oa[2 * jp + 1], a, bv[2], bv[3]);
            }
        }
    }

    // ---- epilogue: reduce l across quad, O / l -> fp16 ----
    l0 += __shfl_xor_sync(0xffffffffu, l0, 1);
    l0 += __shfl_xor_sync(0xffffffffu, l0, 2);
    l1 += __shfl_xor_sync(0xffffffffu, l1, 1);
    l1 += __shfl_xor_sync(0xffffffffu, l1, 2);
    const float inv0 = 1.f / l0;
    const float inv1 = 1.f / l1;
    const int gr0 = b * TT + t0 + w * 16 + (lane >> 2);
#pragma unroll
    for (int j = 0; j < 8; j++) {
        const int col = h * DD + j * 8 + (lane & 3) * 2;
        *(unsigned*)&g_oh[(size_t)gr0 * EMB + col] =
            pk2h(oa[j][0] * inv0, oa[j][1] * inv0);
        *(unsigned*)&g_oh[(size_t)(gr0 + 8) * EMB + col] =
            pk2h(oa[j][2] * inv1, oa[j][3] * inv1);
    }
}

// ---------------------------------------------------------------------------
extern "C" void kernel_launch(void* const* d_in, const int* in_sizes, int n_in,
                              void* d_out, int out_size)
{
    const float* x    = (const float*)d_in[0];
    const float* mask = (const float*)d_in[1];
    const float* Wk   = (const float*)d_in[2];
    const float* Wq   = (const float*)d_in[3];
    const float* Wv   = (const float*)d_in[4];
    const float* Wu   = (const float*)d_in[5];
    const float* bu   = (const float*)d_in[6];
    const float* klng = (const float*)d_in[7];
    const float* klnb = (const float*)d_in[8];
    const float* qlng = (const float*)d_in[9];
    const float* qlnb = (const float*)d_in[10];
    float* out = (float*)d_out;

    const int SPLIT_ITEMS = (ME * EMB + 4 * WSZ) / 4;
    split_all<<<(SPLIT_ITEMS + 255) / 256, 256>>>(x, Wk, Wq, Wv, Wu);

    const int PSMEM = 3 * 27648;  // 82944
    cudaFuncSetAttribute(proj_qkv,
                         cudaFuncAttributeMaxDynamicSharedMemorySize, PSMEM);
    cudaFuncSetAttribute(proj_out,
                         cudaFuncAttributeMaxDynamicSharedMemorySize, PSMEM);
    proj_qkv<<<dim3(ME / 128, EMB / 64, 3), 256, PSMEM>>>(klng, klnb, qlng, qlnb);

    const int ASMEM = 18432 + 3 * 18432 + 3 * 256;  // 74496
    cudaFuncSetAttribute(attn_mma,
                         cudaFuncAttributeMaxDynamicSharedMemorySize, ASMEM);
    attn_mma<<<dim3(TT / 128, HH, BB), 256, ASMEM>>>(mask);

    proj_out<<<dim3(ME / 128, EMB / 64, 1), 256, PSMEM>>>(bu, out);
}